// round 1
// baseline (speedup 1.0000x reference)
#include <cuda_runtime.h>
#include <cuda_bf16.h>
#include <cstdint>

// ---------------------------------------------------------------------------
// Problem constants
// ---------------------------------------------------------------------------
#define B_   2
#define S_   2048
#define DM_  768
#define NQK_ 16
#define DQK_ 16
#define NOV_ 256
#define VKV_ 16
#define SK_  (S_ + VKV_)     // 2064 keys
#define BS_  (B_ * S_)       // 4096 rows

// ---------------------------------------------------------------------------
// Device scratch (no cudaMalloc allowed)
// ---------------------------------------------------------------------------
__device__ float g_Wqkv[DM_ * DM_];                 // [d][c]  c: 0-255 Q, 256-511 K, 512-767 V
__device__ float g_qkv [BS_ * DM_];                 // projection output
__device__ float g_Q   [B_ * NQK_ * S_  * DQK_];    // per (b,h) contiguous
__device__ float g_K   [B_ * NQK_ * SK_ * DQK_];
__device__ float g_V   [B_ * NQK_ * SK_ * DQK_];    // value regrouped: head h, r=0..15
__device__ float g_Z   [BS_ * NOV_];                // attention out, (b*s, n) row-major

// ---------------------------------------------------------------------------
// 1) Pack W_Q / W_K / W_V into a single [768][768] column-blocked matrix
// ---------------------------------------------------------------------------
__global__ void pack_weights(const float* __restrict__ WQ,
                             const float* __restrict__ WK,
                             const float* __restrict__ WV)
{
    int idx = blockIdx.x * blockDim.x + threadIdx.x;   // d*768 + c
    if (idx >= DM_ * DM_) return;
    int c = idx % DM_;
    int d = idx / DM_;
    float v;
    if (c < 256) {
        int h = c >> 4, e = c & 15;
        v = WQ[(h * DM_ + d) * DQK_ + e];
    } else if (c < 512) {
        int cc = c - 256;
        int h = cc >> 4, e = cc & 15;
        v = WK[(h * DM_ + d) * DQK_ + e];
    } else {
        int n = c - 512;
        v = WV[n * DM_ + d];           // W_V is (256, 768, 1)
    }
    g_Wqkv[d * DM_ + c] = v;
}

// ---------------------------------------------------------------------------
// 2) fp32 SGEMM: C[M,N] = A[M,K] * Bm[K,N] (+ optional bias[N])
//    128x128 block tile, 256 threads, 8x8 per thread, K-tile 8.
//    Requires M%128==0, N%128==0, K%8==0, 16B-aligned pointers.
// ---------------------------------------------------------------------------
__global__ __launch_bounds__(256)
void sgemm_kernel(const float* __restrict__ A, const float* __restrict__ Bm,
                  float* __restrict__ C, int M, int N, int K,
                  const float* __restrict__ bias)
{
    const int BM = 128, BN = 128, BK = 8, TM = 8, TN = 8;
    __shared__ float As[BK][BM];
    __shared__ float Bs[BK][BN];

    int tid = threadIdx.x;
    int bm = blockIdx.y, bn = blockIdx.x;

    int tm = (tid / (BN / TN)) * TM;     // row of thread tile
    int tn = (tid % (BN / TN)) * TN;     // col of thread tile

    // global->smem load indices
    int arow = tid >> 1;                 // 0..127
    int acol = (tid & 1) * 4;            // 0 or 4
    int brow = tid >> 5;                 // 0..7
    int bcol = (tid & 31) * 4;           // 0..124

    float acc[TM][TN];
#pragma unroll
    for (int i = 0; i < TM; i++)
#pragma unroll
        for (int j = 0; j < TN; j++) acc[i][j] = 0.f;

    const float* Aptr = A + (size_t)(bm * BM + arow) * K + acol;
    const float* Bptr = Bm + (size_t)brow * N + bn * BN + bcol;

    for (int k0 = 0; k0 < K; k0 += BK) {
        float4 a = *(const float4*)(Aptr + k0);
        As[acol + 0][arow] = a.x;
        As[acol + 1][arow] = a.y;
        As[acol + 2][arow] = a.z;
        As[acol + 3][arow] = a.w;
        float4 b = *(const float4*)(Bptr + (size_t)k0 * N);
        *(float4*)&Bs[brow][bcol] = b;
        __syncthreads();

#pragma unroll
        for (int kk = 0; kk < BK; kk++) {
            float ra[TM], rb[TN];
#pragma unroll
            for (int i = 0; i < TM; i++) ra[i] = As[kk][tm + i];
#pragma unroll
            for (int j = 0; j < TN; j++) rb[j] = Bs[kk][tn + j];
#pragma unroll
            for (int i = 0; i < TM; i++)
#pragma unroll
                for (int j = 0; j < TN; j++) acc[i][j] += ra[i] * rb[j];
        }
        __syncthreads();
    }

#pragma unroll
    for (int i = 0; i < TM; i++) {
        float* crow = C + (size_t)(bm * BM + tm + i) * N + bn * BN + tn;
#pragma unroll
        for (int j = 0; j < TN; j += 4) {
            float4 v;
            v.x = acc[i][j + 0];
            v.y = acc[i][j + 1];
            v.z = acc[i][j + 2];
            v.w = acc[i][j + 3];
            if (bias) {
                v.x += bias[bn * BN + tn + j + 0];
                v.y += bias[bn * BN + tn + j + 1];
                v.z += bias[bn * BN + tn + j + 2];
                v.w += bias[bn * BN + tn + j + 3];
            }
            *(float4*)(crow + j) = v;
        }
    }
}

// ---------------------------------------------------------------------------
// 3) Rotary + bias + scatter Q,K into per-(b,h) buffers
// ---------------------------------------------------------------------------
__global__ void rot_scatter_qk(const float* __restrict__ bQ,
                               const float* __restrict__ bK)
{
    int idx = blockIdx.x * blockDim.x + threadIdx.x;   // over B*S*NQK
    if (idx >= B_ * S_ * NQK_) return;
    int h = idx & 15;
    int s = (idx >> 4) & (S_ - 1);
    int b = idx >> 15;

    const float* src = &g_qkv[(size_t)(b * S_ + s) * DM_];
    float qv[16], kv[16];
#pragma unroll
    for (int e = 0; e < 16; e++) {
        qv[e] = src[h * 16 + e]       + bQ[h * 16 + e];
        kv[e] = src[256 + h * 16 + e] + bK[h * 16 + e];
    }
    float qo[16], ko[16];
    float pos = (float)s;
#pragma unroll
    for (int i = 0; i < 8; i++) {
        float freq = powf(10000.f, (float)i / 8.f);
        float ang = pos / freq;
        float sn, cs;
        sincosf(ang, &sn, &cs);
        qo[i]     = qv[i]     * cs - qv[i + 8] * sn;
        qo[i + 8] = qv[i + 8] * cs + qv[i]     * sn;
        ko[i]     = kv[i]     * cs - kv[i + 8] * sn;
        ko[i + 8] = kv[i + 8] * cs + kv[i]     * sn;
    }
    float* qdst = &g_Q[((size_t)(b * NQK_ + h) * S_ + s) * DQK_];
    float* kdst = &g_K[((size_t)(b * NQK_ + h) * SK_ + s) * DQK_];
#pragma unroll
    for (int e = 0; e < 16; e++) { qdst[e] = qo[e]; kdst[e] = ko[e]; }
}

// ---------------------------------------------------------------------------
// 4) V scatter (regroup 256 scalar OV heads -> 16 heads x 16 r-dims)
// ---------------------------------------------------------------------------
__global__ void scatter_v(const float* __restrict__ bV)
{
    int idx = blockIdx.x * blockDim.x + threadIdx.x;   // over B*S*NOV
    if (idx >= B_ * S_ * NOV_) return;
    int n = idx & 255;
    int s = (idx >> 8) & (S_ - 1);
    int b = idx >> 19;
    int h = n >> 4, r = n & 15;
    g_V[((size_t)(b * NQK_ + h) * SK_ + s) * DQK_ + r] =
        g_qkv[(size_t)(b * S_ + s) * DM_ + 512 + n] + bV[n];
}

// ---------------------------------------------------------------------------
// 5) Virtual K/V rows (no rotary, appended after real keys)
// ---------------------------------------------------------------------------
__global__ void scatter_virtual(const float* __restrict__ vk,
                                const float* __restrict__ vv)
{
    int idx = blockIdx.x * blockDim.x + threadIdx.x;   // over B*VKV*256
    if (idx >= B_ * VKV_ * 256) return;
    int c = idx & 255;
    int m = (idx >> 8) & 15;
    int b = idx >> 12;
    int h = c >> 4, e = c & 15;
    size_t row = ((size_t)(b * NQK_ + h) * SK_ + S_ + m) * DQK_ + e;
    g_K[row] = vk[m * 256 + c];    // virtual_k (VKV, NQK, DQK)
    g_V[row] = vv[m * 256 + c];    // virtual_v (VKV, NOV, 1) -> n = h*16+e maps to r=e
}

// ---------------------------------------------------------------------------
// 6) Attention: per-thread online softmax, mask j <= q + VKV (lookahead!)
//    grid: (S/128, B*NQK), 128 threads; smem tiles of 128 keys.
// ---------------------------------------------------------------------------
__global__ __launch_bounds__(128)
void attn_kernel()
{
    int bh  = blockIdx.y;             // 0..31
    int qt  = blockIdx.x;             // 0..15
    int tid = threadIdx.x;
    int q   = qt * 128 + tid;

    const float* qrow = &g_Q[((size_t)bh * S_ + q) * DQK_];
    float qr[16];
#pragma unroll
    for (int e = 0; e < 16; e++) qr[e] = qrow[e] * 0.25f;   // fold 1/sqrt(16)

    __shared__ float Ks[128][16];
    __shared__ float Vs[128][16];

    float m = -1e30f, l = 0.f;
    float acc[16];
#pragma unroll
    for (int r = 0; r < 16; r++) acc[r] = 0.f;

    int jmax = q + VKV_;                 // inclusive
    int ntiles = qt + 2;                 // tiles 0..qt+1 cover all valid keys

    for (int jt = 0; jt < ntiles; jt++) {
        int jbase = jt * 128;
        int j = jbase + tid;
        if (j < SK_) {
            const float4* sk = (const float4*)&g_K[((size_t)bh * SK_ + j) * DQK_];
            float4* dk = (float4*)&Ks[tid][0];
            dk[0] = sk[0]; dk[1] = sk[1]; dk[2] = sk[2]; dk[3] = sk[3];
            const float4* sv = (const float4*)&g_V[((size_t)bh * SK_ + j) * DQK_];
            float4* dv = (float4*)&Vs[tid][0];
            dv[0] = sv[0]; dv[1] = sv[1]; dv[2] = sv[2]; dv[3] = sv[3];
        }
        __syncthreads();

        int jend = min(jmax, SK_ - 1) - jbase;    // inclusive, may be <0
        if (jend > 127) jend = 127;
        for (int jj = 0; jj <= jend; jj++) {
            float4 k0 = *(const float4*)&Ks[jj][0];
            float4 k1 = *(const float4*)&Ks[jj][4];
            float4 k2 = *(const float4*)&Ks[jj][8];
            float4 k3 = *(const float4*)&Ks[jj][12];
            float s;
            s  = qr[0]  * k0.x + qr[1]  * k0.y + qr[2]  * k0.z + qr[3]  * k0.w;
            s += qr[4]  * k1.x + qr[5]  * k1.y + qr[6]  * k1.z + qr[7]  * k1.w;
            s += qr[8]  * k2.x + qr[9]  * k2.y + qr[10] * k2.z + qr[11] * k2.w;
            s += qr[12] * k3.x + qr[13] * k3.y + qr[14] * k3.z + qr[15] * k3.w;

            float mnew = fmaxf(m, s);
            float corr = __expf(m - mnew);
            float p    = __expf(s - mnew);
            l = l * corr + p;
            m = mnew;

            float4 v0 = *(const float4*)&Vs[jj][0];
            float4 v1 = *(const float4*)&Vs[jj][4];
            float4 v2 = *(const float4*)&Vs[jj][8];
            float4 v3 = *(const float4*)&Vs[jj][12];
            acc[0]  = acc[0]  * corr + p * v0.x;
            acc[1]  = acc[1]  * corr + p * v0.y;
            acc[2]  = acc[2]  * corr + p * v0.z;
            acc[3]  = acc[3]  * corr + p * v0.w;
            acc[4]  = acc[4]  * corr + p * v1.x;
            acc[5]  = acc[5]  * corr + p * v1.y;
            acc[6]  = acc[6]  * corr + p * v1.z;
            acc[7]  = acc[7]  * corr + p * v1.w;
            acc[8]  = acc[8]  * corr + p * v2.x;
            acc[9]  = acc[9]  * corr + p * v2.y;
            acc[10] = acc[10] * corr + p * v2.z;
            acc[11] = acc[11] * corr + p * v2.w;
            acc[12] = acc[12] * corr + p * v3.x;
            acc[13] = acc[13] * corr + p * v3.y;
            acc[14] = acc[14] * corr + p * v3.z;
            acc[15] = acc[15] * corr + p * v3.w;
        }
        __syncthreads();
    }

    float inv_l = 1.f / l;
    int b = bh >> 4, h = bh & 15;
    float* zdst = &g_Z[((size_t)(b * S_ + q)) * NOV_ + h * 16];
#pragma unroll
    for (int r = 0; r < 16; r++) zdst[r] = acc[r] * inv_l;
}

// ---------------------------------------------------------------------------
// Launch
// ---------------------------------------------------------------------------
extern "C" void kernel_launch(void* const* d_in, const int* in_sizes, int n_in,
                              void* d_out, int out_size)
{
    const float* resid = (const float*)d_in[0];
    const float* W_Q   = (const float*)d_in[1];
    const float* W_K   = (const float*)d_in[2];
    const float* W_V   = (const float*)d_in[3];
    const float* W_O   = (const float*)d_in[4];
    const float* b_Q   = (const float*)d_in[5];
    const float* b_K   = (const float*)d_in[6];
    const float* b_V   = (const float*)d_in[7];
    const float* b_O   = (const float*)d_in[8];
    const float* v_k   = (const float*)d_in[9];
    const float* v_v   = (const float*)d_in[10];
    float* out = (float*)d_out;

    float *Wqkv, *qkv, *Z;
    cudaGetSymbolAddress((void**)&Wqkv, g_Wqkv);
    cudaGetSymbolAddress((void**)&qkv,  g_qkv);
    cudaGetSymbolAddress((void**)&Z,    g_Z);

    // 1) pack weights
    pack_weights<<<(DM_ * DM_ + 255) / 256, 256>>>(W_Q, W_K, W_V);

    // 2) QKV projection: (4096 x 768) x (768 x 768)
    {
        dim3 grid(DM_ / 128, BS_ / 128);
        sgemm_kernel<<<grid, 256>>>(resid, Wqkv, qkv, BS_, DM_, DM_, nullptr);
    }

    // 3) rotary + scatter Q,K
    rot_scatter_qk<<<(B_ * S_ * NQK_ + 255) / 256, 256>>>(b_Q, b_K);

    // 4) scatter V
    scatter_v<<<(B_ * S_ * NOV_ + 255) / 256, 256>>>(b_V);

    // 5) virtual kv
    scatter_virtual<<<(B_ * VKV_ * 256 + 255) / 256, 256>>>(v_k, v_v);

    // 6) attention
    {
        dim3 grid(S_ / 128, B_ * NQK_);
        attn_kernel<<<grid, 128>>>();
    }

    // 7) output projection: (4096 x 256) x (256 x 768) + b_O
    {
        dim3 grid(DM_ / 128, BS_ / 128);
        sgemm_kernel<<<grid, 256>>>(Z, W_O, out, BS_, DM_, NOV_, b_O);
    }
}

// round 2
// speedup vs baseline: 1.7542x; 1.7542x over previous
#include <cuda_runtime.h>
#include <cuda_fp16.h>
#include <cstdint>

// ---------------------------------------------------------------------------
// Problem constants
// ---------------------------------------------------------------------------
#define B_   2
#define S_   2048
#define DM_  768
#define NQK_ 16
#define DQK_ 16
#define NOV_ 256
#define VKV_ 16
#define SK_  (S_ + VKV_)     // 2064 keys
#define BS_  (B_ * S_)       // 4096 rows

// ---------------------------------------------------------------------------
// Device scratch
// ---------------------------------------------------------------------------
__device__ __half g_Ah  [BS_ * DM_];                // resid in half
__device__ __half g_Wh1 [DM_ * DM_];                // [c][d] packed QKV weights, half
__device__ __half g_Wh2 [DM_ * NOV_];               // [m][n_ov] packed W_O, half
__device__ float  g_qkv [BS_ * DM_];                // GEMM1 out (fp32)
__device__ float  g_Q   [B_ * NQK_ * S_  * DQK_];
__device__ float  g_K   [B_ * NQK_ * SK_ * DQK_];
__device__ float  g_V   [B_ * NQK_ * SK_ * DQK_];
__device__ __half g_Zh  [BS_ * NOV_];               // attention out (half)

// ---------------------------------------------------------------------------
// helpers
// ---------------------------------------------------------------------------
__device__ __forceinline__ uint32_t smem_u32(const void* p) {
    return (uint32_t)__cvta_generic_to_shared(p);
}
__device__ __forceinline__ void cp16(uint32_t s, const void* g) {
    asm volatile("cp.async.cg.shared.global [%0], [%1], 16;" :: "r"(s), "l"(g));
}
__device__ __forceinline__ float ex2f(float x) {
    float y; asm("ex2.approx.ftz.f32 %0, %1;" : "=f"(y) : "f"(x)); return y;
}
__device__ __forceinline__ void ldm4(uint32_t& r0, uint32_t& r1, uint32_t& r2, uint32_t& r3, uint32_t addr) {
    asm volatile("ldmatrix.sync.aligned.m8n8.x4.shared.b16 {%0,%1,%2,%3}, [%4];"
                 : "=r"(r0), "=r"(r1), "=r"(r2), "=r"(r3) : "r"(addr));
}
__device__ __forceinline__ void mma16816(float* d, const uint32_t* a, const uint32_t* b) {
    asm volatile("mma.sync.aligned.m16n8k16.row.col.f32.f16.f16.f32 "
                 "{%0,%1,%2,%3},{%4,%5,%6,%7},{%8,%9},{%0,%1,%2,%3};"
                 : "+f"(d[0]), "+f"(d[1]), "+f"(d[2]), "+f"(d[3])
                 : "r"(a[0]), "r"(a[1]), "r"(a[2]), "r"(a[3]), "r"(b[0]), "r"(b[1]));
}

// ---------------------------------------------------------------------------
// 1) Pack weights to half:  Wh1[c][d], Wh2[m][n_ov]
// ---------------------------------------------------------------------------
__global__ void pack_w1(const float* __restrict__ WQ,
                        const float* __restrict__ WK,
                        const float* __restrict__ WV)
{
    int idx = blockIdx.x * blockDim.x + threadIdx.x;
    if (idx >= DM_ * DM_) return;
    int c = idx / DM_;
    int d = idx % DM_;
    float v;
    if (c < 256) {
        int h = c >> 4, e = c & 15;
        v = WQ[(h * DM_ + d) * DQK_ + e];
    } else if (c < 512) {
        int cc = c - 256;
        int h = cc >> 4, e = cc & 15;
        v = WK[(h * DM_ + d) * DQK_ + e];
    } else {
        v = WV[(c - 512) * DM_ + d];
    }
    g_Wh1[idx] = __float2half(v);
}

__global__ void pack_w2(const float* __restrict__ WO)
{
    int idx = blockIdx.x * blockDim.x + threadIdx.x;
    if (idx >= DM_ * NOV_) return;
    int m  = idx >> 8;        // 0..767
    int nv = idx & 255;
    g_Wh2[idx] = __float2half(WO[nv * DM_ + m]);
}

__global__ void cvt_resid(const float* __restrict__ in)
{
    int i = (blockIdx.x * blockDim.x + threadIdx.x) * 4;
    if (i >= BS_ * DM_) return;
    float4 v = *(const float4*)(in + i);
    __half2 h0 = __floats2half2_rn(v.x, v.y);
    __half2 h1 = __floats2half2_rn(v.z, v.w);
    *(__half2*)&g_Ah[i]     = h0;
    *(__half2*)&g_Ah[i + 2] = h1;
}

// ---------------------------------------------------------------------------
// 2) fp16 tensor-core GEMM: C[M,N](fp32) = A[M,K](h) * B[N,K](h)^T (+bias)
//    Block 128x128, K-tile 32, 8 warps (4x2), warp tile 32x64.
//    A smem [128][40] halves, B smem [128][40] halves (padded stride).
// ---------------------------------------------------------------------------
#define BKH 32
#define LDT 40     // padded stride in halves (80B)

__global__ __launch_bounds__(256)
void hgemm(const __half* __restrict__ A, const __half* __restrict__ Bm,
           float* __restrict__ C, int M, int N, int K,
           const float* __restrict__ bias)
{
    __shared__ __half As[2][128 * LDT];
    __shared__ __half Bs[2][128 * LDT];

    const int tid  = threadIdx.x;
    const int warp = tid >> 5, lane = tid & 31;
    const int wm = warp >> 1, wn = warp & 1;
    const int bm = blockIdx.y * 128, bn = blockIdx.x * 128;

    // cp.async staging: thread -> row tid/2, 2 chunks of 16B at koff
    const int row  = tid >> 1;
    const int koff = (tid & 1) * 16;
    const __half* Ag = A + (size_t)(bm + row) * K + koff;
    const __half* Bg = Bm + (size_t)(bn + row) * K + koff;
    const uint32_t AsB = smem_u32(&As[0][0]);
    const uint32_t BsB = smem_u32(&Bs[0][0]);
    const uint32_t stAoff = (uint32_t)(row * LDT + koff) * 2;
    const uint32_t BUFB = 128 * LDT * 2;

    // ldmatrix lane offsets
    const int mat = lane >> 3, r = lane & 7;
    const uint32_t a_off = (uint32_t)((wm * 32 + (mat & 1) * 8 + r) * LDT + (mat >> 1) * 8) * 2;
    const uint32_t b_off = (uint32_t)((wn * 64 + (mat >> 1) * 8 + r) * LDT + (mat & 1) * 8) * 2;

    float acc[2][8][4];
#pragma unroll
    for (int i = 0; i < 2; i++)
#pragma unroll
        for (int j = 0; j < 8; j++)
#pragma unroll
            for (int t = 0; t < 4; t++) acc[i][j][t] = 0.f;

    const int KT = K / BKH;

    // preload ktile 0
    cp16(AsB + stAoff,      Ag);
    cp16(AsB + stAoff + 16, Ag + 8);
    cp16(BsB + stAoff,      Bg);
    cp16(BsB + stAoff + 16, Bg + 8);
    asm volatile("cp.async.commit_group;");

    for (int kt = 0; kt < KT; kt++) {
        const int buf = kt & 1;
        if (kt + 1 < KT) {
            const uint32_t bo = (uint32_t)(buf ^ 1) * BUFB;
            const __half* ag = Ag + (kt + 1) * BKH;
            const __half* bg = Bg + (kt + 1) * BKH;
            cp16(AsB + bo + stAoff,      ag);
            cp16(AsB + bo + stAoff + 16, ag + 8);
            cp16(BsB + bo + stAoff,      bg);
            cp16(BsB + bo + stAoff + 16, bg + 8);
            asm volatile("cp.async.commit_group;");
            asm volatile("cp.async.wait_group 1;" ::: "memory");
        } else {
            asm volatile("cp.async.wait_group 0;" ::: "memory");
        }
        __syncthreads();

        const uint32_t Abuf = AsB + buf * BUFB;
        const uint32_t Bbuf = BsB + buf * BUFB;
#pragma unroll
        for (int ks = 0; ks < 2; ks++) {
            uint32_t a[2][4];
#pragma unroll
            for (int mt = 0; mt < 2; mt++)
                ldm4(a[mt][0], a[mt][1], a[mt][2], a[mt][3],
                     Abuf + a_off + (uint32_t)(mt * 16 * LDT + ks * 16) * 2);
            uint32_t bf[8][2];
#pragma unroll
            for (int p = 0; p < 4; p++) {
                uint32_t r0, r1, r2, r3;
                ldm4(r0, r1, r2, r3,
                     Bbuf + b_off + (uint32_t)(p * 16 * LDT + ks * 16) * 2);
                bf[2 * p][0] = r0; bf[2 * p][1] = r1;
                bf[2 * p + 1][0] = r2; bf[2 * p + 1][1] = r3;
            }
#pragma unroll
            for (int mt = 0; mt < 2; mt++)
#pragma unroll
                for (int nt = 0; nt < 8; nt++)
                    mma16816(acc[mt][nt], a[mt], bf[nt]);
        }
        __syncthreads();
    }

    // epilogue
#pragma unroll
    for (int mt = 0; mt < 2; mt++) {
        const int r0 = bm + wm * 32 + mt * 16 + (lane >> 2);
#pragma unroll
        for (int nt = 0; nt < 8; nt++) {
            const int c0 = bn + wn * 64 + nt * 8 + (lane & 3) * 2;
            float b0 = 0.f, b1 = 0.f;
            if (bias) { b0 = bias[c0]; b1 = bias[c0 + 1]; }
            float2 v01 = { acc[mt][nt][0] + b0, acc[mt][nt][1] + b1 };
            float2 v23 = { acc[mt][nt][2] + b0, acc[mt][nt][3] + b1 };
            *(float2*)(C + (size_t)r0 * N + c0)        = v01;
            *(float2*)(C + (size_t)(r0 + 8) * N + c0)  = v23;
        }
    }
}

// ---------------------------------------------------------------------------
// 3) Rotary + bias + scatter Q,K
// ---------------------------------------------------------------------------
__global__ void rot_scatter_qk(const float* __restrict__ bQ,
                               const float* __restrict__ bK)
{
    int idx = blockIdx.x * blockDim.x + threadIdx.x;
    if (idx >= B_ * S_ * NQK_) return;
    int h = idx & 15;
    int s = (idx >> 4) & (S_ - 1);
    int b = idx >> 15;

    const float* src = &g_qkv[(size_t)(b * S_ + s) * DM_];
    float qv[16], kv[16];
#pragma unroll
    for (int e = 0; e < 16; e++) {
        qv[e] = src[h * 16 + e]       + bQ[h * 16 + e];
        kv[e] = src[256 + h * 16 + e] + bK[h * 16 + e];
    }
    float qo[16], ko[16];
    float pos = (float)s;
#pragma unroll
    for (int i = 0; i < 8; i++) {
        float freq = powf(10000.f, (float)i / 8.f);
        float ang = pos / freq;
        float sn, cs;
        sincosf(ang, &sn, &cs);
        qo[i]     = qv[i]     * cs - qv[i + 8] * sn;
        qo[i + 8] = qv[i + 8] * cs + qv[i]     * sn;
        ko[i]     = kv[i]     * cs - kv[i + 8] * sn;
        ko[i + 8] = kv[i + 8] * cs + kv[i]     * sn;
    }
    float* qdst = &g_Q[((size_t)(b * NQK_ + h) * S_ + s) * DQK_];
    float* kdst = &g_K[((size_t)(b * NQK_ + h) * SK_ + s) * DQK_];
#pragma unroll
    for (int e = 0; e < 16; e++) { qdst[e] = qo[e]; kdst[e] = ko[e]; }
}

// ---------------------------------------------------------------------------
// 4) V scatter
// ---------------------------------------------------------------------------
__global__ void scatter_v(const float* __restrict__ bV)
{
    int idx = blockIdx.x * blockDim.x + threadIdx.x;
    if (idx >= B_ * S_ * NOV_) return;
    int n = idx & 255;
    int s = (idx >> 8) & (S_ - 1);
    int b = idx >> 19;
    int h = n >> 4, r = n & 15;
    g_V[((size_t)(b * NQK_ + h) * SK_ + s) * DQK_ + r] =
        g_qkv[(size_t)(b * S_ + s) * DM_ + 512 + n] + bV[n];
}

// ---------------------------------------------------------------------------
// 5) Virtual K/V rows
// ---------------------------------------------------------------------------
__global__ void scatter_virtual(const float* __restrict__ vk,
                                const float* __restrict__ vv)
{
    int idx = blockIdx.x * blockDim.x + threadIdx.x;
    if (idx >= B_ * VKV_ * 256) return;
    int c = idx & 255;
    int m = (idx >> 8) & 15;
    int b = idx >> 12;
    int h = c >> 4, e = c & 15;
    size_t row = ((size_t)(b * NQK_ + h) * SK_ + S_ + m) * DQK_ + e;
    g_K[row] = vk[m * 256 + c];
    g_V[row] = vv[m * 256 + c];
}

// ---------------------------------------------------------------------------
// 6) Attention: chunked online softmax (log2 domain), half output
// ---------------------------------------------------------------------------
__global__ __launch_bounds__(128)
void attn_kernel()
{
    const int bh  = blockIdx.y;
    const int qt  = blockIdx.x;
    const int tid = threadIdx.x;
    const int q   = qt * 128 + tid;
    const float QSCALE = 0.25f * 1.4426950408889634f;   // 1/sqrt(16) * log2(e)

    const float* qrow = &g_Q[((size_t)bh * S_ + q) * DQK_];
    float qr[16];
#pragma unroll
    for (int e = 0; e < 16; e++) qr[e] = qrow[e] * QSCALE;

    __shared__ float Ks[128][16];
    __shared__ float Vs[128][16];

    float m = -1e30f, l = 0.f;
    float acc[16];
#pragma unroll
    for (int r = 0; r < 16; r++) acc[r] = 0.f;

    const int jmax = q + VKV_;
    const int ntiles = qt + 2;

    for (int jt = 0; jt < ntiles; jt++) {
        const int jbase = jt * 128;
        const int j = jbase + tid;
        if (j < SK_) {
            const float4* sk = (const float4*)&g_K[((size_t)bh * SK_ + j) * DQK_];
            float4* dk = (float4*)&Ks[tid][0];
            dk[0] = sk[0]; dk[1] = sk[1]; dk[2] = sk[2]; dk[3] = sk[3];
            const float4* sv = (const float4*)&g_V[((size_t)bh * SK_ + j) * DQK_];
            float4* dv = (float4*)&Vs[tid][0];
            dv[0] = sv[0]; dv[1] = sv[1]; dv[2] = sv[2]; dv[3] = sv[3];
        }
        __syncthreads();

        int jend = min(jmax, SK_ - 1) - jbase;
        if (jend > 127) jend = 127;

        for (int c0 = 0; c0 <= jend; c0 += 16) {
            const int cnt = jend - c0 + 1;   // may exceed 16; clamp via compare
            float sc[16];
#pragma unroll
            for (int u = 0; u < 16; u++) {
                const int jj = c0 + u;
                float4 k0 = *(const float4*)&Ks[jj][0];
                float4 k1 = *(const float4*)&Ks[jj][4];
                float4 k2 = *(const float4*)&Ks[jj][8];
                float4 k3 = *(const float4*)&Ks[jj][12];
                float s;
                s  = qr[0]  * k0.x + qr[1]  * k0.y + qr[2]  * k0.z + qr[3]  * k0.w;
                s += qr[4]  * k1.x + qr[5]  * k1.y + qr[6]  * k1.z + qr[7]  * k1.w;
                s += qr[8]  * k2.x + qr[9]  * k2.y + qr[10] * k2.z + qr[11] * k2.w;
                s += qr[12] * k3.x + qr[13] * k3.y + qr[14] * k3.z + qr[15] * k3.w;
                sc[u] = (u < cnt) ? s : -1e30f;
            }
            float cm = sc[0];
#pragma unroll
            for (int u = 1; u < 16; u++) cm = fmaxf(cm, sc[u]);
            const float mnew = fmaxf(m, cm);
            const float corr = ex2f(m - mnew);
            m = mnew;
            l *= corr;
#pragma unroll
            for (int r = 0; r < 16; r++) acc[r] *= corr;
#pragma unroll
            for (int u = 0; u < 16; u++) {
                const int jj = c0 + u;
                const float p = ex2f(sc[u] - mnew);
                l += p;
                float4 v0 = *(const float4*)&Vs[jj][0];
                float4 v1 = *(const float4*)&Vs[jj][4];
                float4 v2 = *(const float4*)&Vs[jj][8];
                float4 v3 = *(const float4*)&Vs[jj][12];
                acc[0]  += p * v0.x;  acc[1]  += p * v0.y;
                acc[2]  += p * v0.z;  acc[3]  += p * v0.w;
                acc[4]  += p * v1.x;  acc[5]  += p * v1.y;
                acc[6]  += p * v1.z;  acc[7]  += p * v1.w;
                acc[8]  += p * v2.x;  acc[9]  += p * v2.y;
                acc[10] += p * v2.z;  acc[11] += p * v2.w;
                acc[12] += p * v3.x;  acc[13] += p * v3.y;
                acc[14] += p * v3.z;  acc[15] += p * v3.w;
            }
        }
        __syncthreads();
    }

    const float inv_l = 1.f / l;
    const int b = bh >> 4, h = bh & 15;
    __half2* zd = (__half2*)&g_Zh[((size_t)(b * S_ + q)) * NOV_ + h * 16];
#pragma unroll
    for (int r2 = 0; r2 < 8; r2++)
        zd[r2] = __floats2half2_rn(acc[2 * r2] * inv_l, acc[2 * r2 + 1] * inv_l);
}

// ---------------------------------------------------------------------------
// Launch
// ---------------------------------------------------------------------------
extern "C" void kernel_launch(void* const* d_in, const int* in_sizes, int n_in,
                              void* d_out, int out_size)
{
    const float* resid = (const float*)d_in[0];
    const float* W_Q   = (const float*)d_in[1];
    const float* W_K   = (const float*)d_in[2];
    const float* W_V   = (const float*)d_in[3];
    const float* W_O   = (const float*)d_in[4];
    const float* b_Q   = (const float*)d_in[5];
    const float* b_K   = (const float*)d_in[6];
    const float* b_V   = (const float*)d_in[7];
    const float* b_O   = (const float*)d_in[8];
    const float* v_k   = (const float*)d_in[9];
    const float* v_v   = (const float*)d_in[10];
    float* out = (float*)d_out;

    __half *Ah, *Wh1, *Wh2, *Zh;
    float *qkv;
    cudaGetSymbolAddress((void**)&Ah,  g_Ah);
    cudaGetSymbolAddress((void**)&Wh1, g_Wh1);
    cudaGetSymbolAddress((void**)&Wh2, g_Wh2);
    cudaGetSymbolAddress((void**)&Zh,  g_Zh);
    cudaGetSymbolAddress((void**)&qkv, g_qkv);

    pack_w1<<<(DM_ * DM_ + 255) / 256, 256>>>(W_Q, W_K, W_V);
    pack_w2<<<(DM_ * NOV_ + 255) / 256, 256>>>(W_O);
    cvt_resid<<<(BS_ * DM_ / 4 + 255) / 256, 256>>>(resid);

    // GEMM1: (4096 x 768) = Ah (4096x768) * Wh1^T   -> g_qkv fp32
    {
        dim3 grid(DM_ / 128, BS_ / 128);
        hgemm<<<grid, 256>>>(Ah, Wh1, qkv, BS_, DM_, DM_, nullptr);
    }

    rot_scatter_qk<<<(B_ * S_ * NQK_ + 255) / 256, 256>>>(b_Q, b_K);
    scatter_v<<<(B_ * S_ * NOV_ + 255) / 256, 256>>>(b_V);
    scatter_virtual<<<(B_ * VKV_ * 256 + 255) / 256, 256>>>(v_k, v_v);

    {
        dim3 grid(S_ / 128, B_ * NQK_);
        attn_kernel<<<grid, 128>>>();
    }

    // GEMM2: (4096 x 768) = Zh (4096x256) * Wh2^T + b_O -> out fp32
    {
        dim3 grid(DM_ / 128, BS_ / 128);
        hgemm<<<grid, 256>>>(Zh, Wh2, out, BS_, DM_, NOV_, b_O);
    }
}

// round 3
// speedup vs baseline: 4.3288x; 2.4677x over previous
#include <cuda_runtime.h>
#include <cuda_fp16.h>
#include <cstdint>

// ---------------------------------------------------------------------------
// Problem constants
// ---------------------------------------------------------------------------
#define B_   2
#define S_   2048
#define DM_  768
#define NQK_ 16
#define DQK_ 16
#define NOV_ 256
#define VKV_ 16
#define SK_  (S_ + VKV_)     // 2064 keys
#define BS_  (B_ * S_)       // 4096 rows

// ---------------------------------------------------------------------------
// Device scratch
// ---------------------------------------------------------------------------
__device__ __half g_Ah  [BS_ * DM_];                // resid in half
__device__ __half g_Wh1 [DM_ * DM_];                // [c][d] packed QKV weights
__device__ __half g_Wh2 [DM_ * NOV_];               // [m][n_ov] packed W_O
__device__ float  g_qkv [BS_ * DM_];                // GEMM1 out (fp32)
__device__ __half g_Qh  [B_ * NQK_ * S_  * DQK_];   // log2-scaled Q, per (b,h)
__device__ __half g_Kh  [B_ * NQK_ * SK_ * DQK_];
__device__ __half g_Vh  [B_ * NQK_ * SK_ * DQK_];
__device__ __half g_Zh  [BS_ * NOV_];               // attention out (half)

// ---------------------------------------------------------------------------
// helpers
// ---------------------------------------------------------------------------
__device__ __forceinline__ uint32_t smem_u32(const void* p) {
    return (uint32_t)__cvta_generic_to_shared(p);
}
__device__ __forceinline__ void cp16(uint32_t s, const void* g) {
    asm volatile("cp.async.cg.shared.global [%0], [%1], 16;" :: "r"(s), "l"(g));
}
__device__ __forceinline__ float ex2f(float x) {
    float y; asm("ex2.approx.ftz.f32 %0, %1;" : "=f"(y) : "f"(x)); return y;
}
__device__ __forceinline__ void ldm4(uint32_t& r0, uint32_t& r1, uint32_t& r2, uint32_t& r3, uint32_t addr) {
    asm volatile("ldmatrix.sync.aligned.m8n8.x4.shared.b16 {%0,%1,%2,%3}, [%4];"
                 : "=r"(r0), "=r"(r1), "=r"(r2), "=r"(r3) : "r"(addr));
}
__device__ __forceinline__ void ldm4t(uint32_t& r0, uint32_t& r1, uint32_t& r2, uint32_t& r3, uint32_t addr) {
    asm volatile("ldmatrix.sync.aligned.m8n8.x4.trans.shared.b16 {%0,%1,%2,%3}, [%4];"
                 : "=r"(r0), "=r"(r1), "=r"(r2), "=r"(r3) : "r"(addr));
}
__device__ __forceinline__ void mma16816(float* d, const uint32_t* a, const uint32_t* b) {
    asm volatile("mma.sync.aligned.m16n8k16.row.col.f32.f16.f16.f32 "
                 "{%0,%1,%2,%3},{%4,%5,%6,%7},{%8,%9},{%0,%1,%2,%3};"
                 : "+f"(d[0]), "+f"(d[1]), "+f"(d[2]), "+f"(d[3])
                 : "r"(a[0]), "r"(a[1]), "r"(a[2]), "r"(a[3]), "r"(b[0]), "r"(b[1]));
}
__device__ __forceinline__ uint32_t packh2(float x, float y) {
    __half2 h = __floats2half2_rn(x, y);
    return *(uint32_t*)&h;
}

// ---------------------------------------------------------------------------
// 1) Pack weights / convert resid
// ---------------------------------------------------------------------------
__global__ void pack_w1(const float* __restrict__ WQ,
                        const float* __restrict__ WK,
                        const float* __restrict__ WV)
{
    int idx = blockIdx.x * blockDim.x + threadIdx.x;
    if (idx >= DM_ * DM_) return;
    int c = idx / DM_;
    int d = idx % DM_;
    float v;
    if (c < 256) {
        int h = c >> 4, e = c & 15;
        v = WQ[(h * DM_ + d) * DQK_ + e];
    } else if (c < 512) {
        int cc = c - 256;
        int h = cc >> 4, e = cc & 15;
        v = WK[(h * DM_ + d) * DQK_ + e];
    } else {
        v = WV[(c - 512) * DM_ + d];
    }
    g_Wh1[idx] = __float2half(v);
}

__global__ void pack_w2(const float* __restrict__ WO)
{
    int idx = blockIdx.x * blockDim.x + threadIdx.x;
    if (idx >= DM_ * NOV_) return;
    int m  = idx >> 8;
    int nv = idx & 255;
    g_Wh2[idx] = __float2half(WO[nv * DM_ + m]);
}

__global__ void cvt_resid(const float* __restrict__ in)
{
    int i = (blockIdx.x * blockDim.x + threadIdx.x) * 4;
    if (i >= BS_ * DM_) return;
    float4 v = *(const float4*)(in + i);
    *(__half2*)&g_Ah[i]     = __floats2half2_rn(v.x, v.y);
    *(__half2*)&g_Ah[i + 2] = __floats2half2_rn(v.z, v.w);
}

// ---------------------------------------------------------------------------
// 2) fp16 tensor-core GEMM (unchanged from validated R2 version)
// ---------------------------------------------------------------------------
#define BKH 32
#define LDT 40

__global__ __launch_bounds__(256)
void hgemm(const __half* __restrict__ A, const __half* __restrict__ Bm,
           float* __restrict__ C, int M, int N, int K,
           const float* __restrict__ bias)
{
    __shared__ __half As[2][128 * LDT];
    __shared__ __half Bs[2][128 * LDT];

    const int tid  = threadIdx.x;
    const int warp = tid >> 5, lane = tid & 31;
    const int wm = warp >> 1, wn = warp & 1;
    const int bm = blockIdx.y * 128, bn = blockIdx.x * 128;

    const int row  = tid >> 1;
    const int koff = (tid & 1) * 16;
    const __half* Ag = A + (size_t)(bm + row) * K + koff;
    const __half* Bg = Bm + (size_t)(bn + row) * K + koff;
    const uint32_t AsB = smem_u32(&As[0][0]);
    const uint32_t BsB = smem_u32(&Bs[0][0]);
    const uint32_t stAoff = (uint32_t)(row * LDT + koff) * 2;
    const uint32_t BUFB = 128 * LDT * 2;

    const int mat = lane >> 3, r = lane & 7;
    const uint32_t a_off = (uint32_t)((wm * 32 + (mat & 1) * 8 + r) * LDT + (mat >> 1) * 8) * 2;
    const uint32_t b_off = (uint32_t)((wn * 64 + (mat >> 1) * 8 + r) * LDT + (mat & 1) * 8) * 2;

    float acc[2][8][4];
#pragma unroll
    for (int i = 0; i < 2; i++)
#pragma unroll
        for (int j = 0; j < 8; j++)
#pragma unroll
            for (int t = 0; t < 4; t++) acc[i][j][t] = 0.f;

    const int KT = K / BKH;

    cp16(AsB + stAoff,      Ag);
    cp16(AsB + stAoff + 16, Ag + 8);
    cp16(BsB + stAoff,      Bg);
    cp16(BsB + stAoff + 16, Bg + 8);
    asm volatile("cp.async.commit_group;");

    for (int kt = 0; kt < KT; kt++) {
        const int buf = kt & 1;
        if (kt + 1 < KT) {
            const uint32_t bo = (uint32_t)(buf ^ 1) * BUFB;
            const __half* ag = Ag + (kt + 1) * BKH;
            const __half* bg = Bg + (kt + 1) * BKH;
            cp16(AsB + bo + stAoff,      ag);
            cp16(AsB + bo + stAoff + 16, ag + 8);
            cp16(BsB + bo + stAoff,      bg);
            cp16(BsB + bo + stAoff + 16, bg + 8);
            asm volatile("cp.async.commit_group;");
            asm volatile("cp.async.wait_group 1;" ::: "memory");
        } else {
            asm volatile("cp.async.wait_group 0;" ::: "memory");
        }
        __syncthreads();

        const uint32_t Abuf = AsB + buf * BUFB;
        const uint32_t Bbuf = BsB + buf * BUFB;
#pragma unroll
        for (int ks = 0; ks < 2; ks++) {
            uint32_t a[2][4];
#pragma unroll
            for (int mt = 0; mt < 2; mt++)
                ldm4(a[mt][0], a[mt][1], a[mt][2], a[mt][3],
                     Abuf + a_off + (uint32_t)(mt * 16 * LDT + ks * 16) * 2);
            uint32_t bf[8][2];
#pragma unroll
            for (int p = 0; p < 4; p++) {
                uint32_t r0, r1, r2, r3;
                ldm4(r0, r1, r2, r3,
                     Bbuf + b_off + (uint32_t)(p * 16 * LDT + ks * 16) * 2);
                bf[2 * p][0] = r0; bf[2 * p][1] = r1;
                bf[2 * p + 1][0] = r2; bf[2 * p + 1][1] = r3;
            }
#pragma unroll
            for (int mt = 0; mt < 2; mt++)
#pragma unroll
                for (int nt = 0; nt < 8; nt++)
                    mma16816(acc[mt][nt], a[mt], bf[nt]);
        }
        __syncthreads();
    }

#pragma unroll
    for (int mt = 0; mt < 2; mt++) {
        const int r0 = bm + wm * 32 + mt * 16 + (lane >> 2);
#pragma unroll
        for (int nt = 0; nt < 8; nt++) {
            const int c0 = bn + wn * 64 + nt * 8 + (lane & 3) * 2;
            float b0 = 0.f, b1 = 0.f;
            if (bias) { b0 = bias[c0]; b1 = bias[c0 + 1]; }
            float2 v01 = { acc[mt][nt][0] + b0, acc[mt][nt][1] + b1 };
            float2 v23 = { acc[mt][nt][2] + b0, acc[mt][nt][3] + b1 };
            *(float2*)(C + (size_t)r0 * N + c0)        = v01;
            *(float2*)(C + (size_t)(r0 + 8) * N + c0)  = v23;
        }
    }
}

// ---------------------------------------------------------------------------
// 3) Rotary + bias + scatter Q,K  (half output; Q gets scale*log2e folded)
// ---------------------------------------------------------------------------
#define QSCALE 0.36067376022224085f   // 0.25 * log2(e)

__global__ void rot_scatter_qk(const float* __restrict__ bQ,
                               const float* __restrict__ bK)
{
    int idx = blockIdx.x * blockDim.x + threadIdx.x;
    if (idx >= B_ * S_ * NQK_) return;
    int h = idx & 15;
    int s = (idx >> 4) & (S_ - 1);
    int b = idx >> 15;

    const float* src = &g_qkv[(size_t)(b * S_ + s) * DM_];
    float qv[16], kv[16];
#pragma unroll
    for (int e = 0; e < 16; e++) {
        qv[e] = src[h * 16 + e]       + bQ[h * 16 + e];
        kv[e] = src[256 + h * 16 + e] + bK[h * 16 + e];
    }
    float pos = (float)s;
    __half qo[16], ko[16];
#pragma unroll
    for (int i = 0; i < 8; i++) {
        float freq = powf(10000.f, (float)i / 8.f);
        float ang = pos / freq;
        float sn, cs;
        sincosf(ang, &sn, &cs);
        qo[i]     = __float2half((qv[i]     * cs - qv[i + 8] * sn) * QSCALE);
        qo[i + 8] = __float2half((qv[i + 8] * cs + qv[i]     * sn) * QSCALE);
        ko[i]     = __float2half(kv[i]     * cs - kv[i + 8] * sn);
        ko[i + 8] = __float2half(kv[i + 8] * cs + kv[i]     * sn);
    }
    __half* qdst = &g_Qh[((size_t)(b * NQK_ + h) * S_ + s) * DQK_];
    __half* kdst = &g_Kh[((size_t)(b * NQK_ + h) * SK_ + s) * DQK_];
#pragma unroll
    for (int e = 0; e < 16; e++) { qdst[e] = qo[e]; kdst[e] = ko[e]; }
}

// ---------------------------------------------------------------------------
// 4) V scatter (half)
// ---------------------------------------------------------------------------
__global__ void scatter_v(const float* __restrict__ bV)
{
    int idx = blockIdx.x * blockDim.x + threadIdx.x;
    if (idx >= B_ * S_ * NOV_) return;
    int n = idx & 255;
    int s = (idx >> 8) & (S_ - 1);
    int b = idx >> 19;
    int h = n >> 4, r = n & 15;
    g_Vh[((size_t)(b * NQK_ + h) * SK_ + s) * DQK_ + r] =
        __float2half(g_qkv[(size_t)(b * S_ + s) * DM_ + 512 + n] + bV[n]);
}

// ---------------------------------------------------------------------------
// 5) Virtual K/V rows (half)
// ---------------------------------------------------------------------------
__global__ void scatter_virtual(const float* __restrict__ vk,
                                const float* __restrict__ vv)
{
    int idx = blockIdx.x * blockDim.x + threadIdx.x;
    if (idx >= B_ * VKV_ * 256) return;
    int c = idx & 255;
    int m = (idx >> 8) & 15;
    int b = idx >> 12;
    int h = c >> 4, e = c & 15;
    size_t row = ((size_t)(b * NQK_ + h) * SK_ + S_ + m) * DQK_ + e;
    g_Kh[row] = __float2half(vk[m * 256 + c]);
    g_Vh[row] = __float2half(vv[m * 256 + c]);
}

// ---------------------------------------------------------------------------
// 6) Tensor-core flash attention.
//    Block = 128 queries of one (b,h); 8 warps x 16 query rows.
//    Key tiles of 128, cp.async double-buffered.
// ---------------------------------------------------------------------------
__global__ __launch_bounds__(256)
void attn_mma()
{
    const int bh   = blockIdx.y;
    const int qt   = (int)(gridDim.x - 1) - (int)blockIdx.x;   // big tiles first
    const int tid  = threadIdx.x;
    const int warp = tid >> 5, lane = tid & 31;

    __shared__ __half Qs[128 * 16];
    __shared__ __half Ks[2][128 * 16];
    __shared__ __half Vs[2][128 * 16];

    const __half* Qg = g_Qh + ((size_t)bh * S_ + qt * 128) * DQK_;
    const __half* Kg = g_Kh + (size_t)bh * SK_ * DQK_;
    const __half* Vg = g_Vh + (size_t)bh * SK_ * DQK_;

    const int ld_row = tid >> 1;
    const int ld_off = (tid & 1) * 8;

    // Q tile -> smem
    *(float4*)&Qs[ld_row * 16 + ld_off] =
        *(const float4*)&Qg[(size_t)ld_row * 16 + ld_off];

    // preload K/V tile 0
    {
        int j = ld_row; if (j > SK_ - 1) j = SK_ - 1;
        cp16(smem_u32(&Ks[0][ld_row * 16 + ld_off]), Kg + (size_t)j * 16 + ld_off);
        cp16(smem_u32(&Vs[0][ld_row * 16 + ld_off]), Vg + (size_t)j * 16 + ld_off);
        asm volatile("cp.async.commit_group;");
    }
    __syncthreads();

    // Q fragment (m16k16 row-major)
    uint32_t qa[4];
    {
        int g = lane >> 3, r = lane & 7;
        int row = warp * 16 + (g & 1) * 8 + r;
        int col = (g >> 1) * 8;
        ldm4(qa[0], qa[1], qa[2], qa[3], smem_u32(&Qs[row * 16 + col]));
    }

    float m0 = -1e30f, m1 = -1e30f, l0 = 0.f, l1 = 0.f;
    float o[2][4] = {{0.f,0.f,0.f,0.f},{0.f,0.f,0.f,0.f}};

    const int ntiles = qt + 2;
    const int qrow0  = qt * 128 + warp * 16 + (lane >> 2);   // this thread's row r

    for (int jt = 0; jt < ntiles; jt++) {
        const int buf = jt & 1;
        if (jt + 1 < ntiles) {
            int j = (jt + 1) * 128 + ld_row; if (j > SK_ - 1) j = SK_ - 1;
            cp16(smem_u32(&Ks[buf ^ 1][ld_row * 16 + ld_off]), Kg + (size_t)j * 16 + ld_off);
            cp16(smem_u32(&Vs[buf ^ 1][ld_row * 16 + ld_off]), Vg + (size_t)j * 16 + ld_off);
            asm volatile("cp.async.commit_group;");
            asm volatile("cp.async.wait_group 1;" ::: "memory");
        } else {
            asm volatile("cp.async.wait_group 0;" ::: "memory");
        }
        __syncthreads();

        // ---- QK^T : 16 n-tiles of 8 keys ----
        float sc[16][4];
#pragma unroll
        for (int nt = 0; nt < 16; nt++)
#pragma unroll
            for (int t = 0; t < 4; t++) sc[nt][t] = 0.f;

        {
            const int g = lane >> 3, r = lane & 7;
            const int krow = (g >> 1) * 8 + r;
            const int kcol = (g & 1) * 8;
#pragma unroll
            for (int i = 0; i < 8; i++) {
                uint32_t b0, b1, b2, b3;
                ldm4(b0, b1, b2, b3,
                     smem_u32(&Ks[buf][(16 * i + krow) * 16 + kcol]));
                uint32_t bl[2] = { b0, b1 };
                uint32_t bh2[2] = { b2, b3 };
                mma16816(sc[2 * i],     qa, bl);
                mma16816(sc[2 * i + 1], qa, bh2);
            }
        }

        // ---- mask (only diagonal/lookahead tiles) ----
        if (jt >= qt) {
            const int jb = jt * 128 + (lane & 3) * 2;
            const int t0 = qrow0 + 16;       // row r limit (inclusive)
            const int t1 = qrow0 + 24;       // row r+8 limit
#pragma unroll
            for (int nt = 0; nt < 16; nt++) {
                int j0 = jb + nt * 8;
                if (j0     > t0) sc[nt][0] = -1e30f;
                if (j0 + 1 > t0) sc[nt][1] = -1e30f;
                if (j0     > t1) sc[nt][2] = -1e30f;
                if (j0 + 1 > t1) sc[nt][3] = -1e30f;
            }
        }

        // ---- online softmax (log2 domain) ----
        float rm0 = sc[0][0], rm1 = sc[0][2];
#pragma unroll
        for (int nt = 0; nt < 16; nt++) {
            rm0 = fmaxf(rm0, fmaxf(sc[nt][0], sc[nt][1]));
            rm1 = fmaxf(rm1, fmaxf(sc[nt][2], sc[nt][3]));
        }
        rm0 = fmaxf(rm0, __shfl_xor_sync(0xffffffff, rm0, 1));
        rm0 = fmaxf(rm0, __shfl_xor_sync(0xffffffff, rm0, 2));
        rm1 = fmaxf(rm1, __shfl_xor_sync(0xffffffff, rm1, 1));
        rm1 = fmaxf(rm1, __shfl_xor_sync(0xffffffff, rm1, 2));

        const float mn0 = fmaxf(m0, rm0);
        const float mn1 = fmaxf(m1, rm1);
        const float c0 = ex2f(m0 - mn0);
        const float c1 = ex2f(m1 - mn1);
        m0 = mn0; m1 = mn1;
        l0 *= c0; l1 *= c1;
        o[0][0] *= c0; o[0][1] *= c0; o[0][2] *= c1; o[0][3] *= c1;
        o[1][0] *= c0; o[1][1] *= c0; o[1][2] *= c1; o[1][3] *= c1;

#pragma unroll
        for (int nt = 0; nt < 16; nt++) {
            sc[nt][0] = ex2f(sc[nt][0] - mn0);
            sc[nt][1] = ex2f(sc[nt][1] - mn0);
            sc[nt][2] = ex2f(sc[nt][2] - mn1);
            sc[nt][3] = ex2f(sc[nt][3] - mn1);
            l0 += sc[nt][0] + sc[nt][1];
            l1 += sc[nt][2] + sc[nt][3];
        }

        // ---- P @ V : 8 k-steps of 16 keys ----
        {
            const int g = lane >> 3, r = lane & 7;
            const int vrow = (g & 1) * 8 + r;
            const int vcol = (g >> 1) * 8;
#pragma unroll
            for (int kt = 0; kt < 8; kt++) {
                uint32_t pa[4];
                pa[0] = packh2(sc[2 * kt][0],     sc[2 * kt][1]);
                pa[1] = packh2(sc[2 * kt][2],     sc[2 * kt][3]);
                pa[2] = packh2(sc[2 * kt + 1][0], sc[2 * kt + 1][1]);
                pa[3] = packh2(sc[2 * kt + 1][2], sc[2 * kt + 1][3]);
                uint32_t v0, v1, v2, v3;
                ldm4t(v0, v1, v2, v3,
                      smem_u32(&Vs[buf][(16 * kt + vrow) * 16 + vcol]));
                uint32_t bl[2] = { v0, v1 };
                uint32_t bh2[2] = { v2, v3 };
                mma16816(o[0], pa, bl);
                mma16816(o[1], pa, bh2);
            }
        }
        __syncthreads();
    }

    // ---- epilogue ----
    l0 += __shfl_xor_sync(0xffffffff, l0, 1);
    l0 += __shfl_xor_sync(0xffffffff, l0, 2);
    l1 += __shfl_xor_sync(0xffffffff, l1, 1);
    l1 += __shfl_xor_sync(0xffffffff, l1, 2);
    const float inv0 = 1.f / l0;
    const float inv1 = 1.f / l1;

    const int b = bh >> 4, h = bh & 15;
    const int col = (lane & 3) * 2;
#pragma unroll
    for (int vt = 0; vt < 2; vt++) {
        uint32_t lo = packh2(o[vt][0] * inv0, o[vt][1] * inv0);
        uint32_t hi = packh2(o[vt][2] * inv1, o[vt][3] * inv1);
        size_t base0 = ((size_t)(b * S_ + qrow0)     ) * NOV_ + h * 16 + vt * 8 + col;
        size_t base1 = ((size_t)(b * S_ + qrow0 + 8) ) * NOV_ + h * 16 + vt * 8 + col;
        *(uint32_t*)&g_Zh[base0] = lo;
        *(uint32_t*)&g_Zh[base1] = hi;
    }
}

// ---------------------------------------------------------------------------
// Launch
// ---------------------------------------------------------------------------
extern "C" void kernel_launch(void* const* d_in, const int* in_sizes, int n_in,
                              void* d_out, int out_size)
{
    const float* resid = (const float*)d_in[0];
    const float* W_Q   = (const float*)d_in[1];
    const float* W_K   = (const float*)d_in[2];
    const float* W_V   = (const float*)d_in[3];
    const float* W_O   = (const float*)d_in[4];
    const float* b_Q   = (const float*)d_in[5];
    const float* b_K   = (const float*)d_in[6];
    const float* b_V   = (const float*)d_in[7];
    const float* b_O   = (const float*)d_in[8];
    const float* v_k   = (const float*)d_in[9];
    const float* v_v   = (const float*)d_in[10];
    float* out = (float*)d_out;

    __half *Ah, *Wh1, *Wh2, *Zh;
    float *qkv;
    cudaGetSymbolAddress((void**)&Ah,  g_Ah);
    cudaGetSymbolAddress((void**)&Wh1, g_Wh1);
    cudaGetSymbolAddress((void**)&Wh2, g_Wh2);
    cudaGetSymbolAddress((void**)&Zh,  g_Zh);
    cudaGetSymbolAddress((void**)&qkv, g_qkv);

    pack_w1<<<(DM_ * DM_ + 255) / 256, 256>>>(W_Q, W_K, W_V);
    pack_w2<<<(DM_ * NOV_ + 255) / 256, 256>>>(W_O);
    cvt_resid<<<(BS_ * DM_ / 4 + 255) / 256, 256>>>(resid);

    // GEMM1: (4096 x 768) = Ah * Wh1^T -> g_qkv fp32
    {
        dim3 grid(DM_ / 128, BS_ / 128);
        hgemm<<<grid, 256>>>(Ah, Wh1, qkv, BS_, DM_, DM_, nullptr);
    }

    rot_scatter_qk<<<(B_ * S_ * NQK_ + 255) / 256, 256>>>(b_Q, b_K);
    scatter_v<<<(B_ * S_ * NOV_ + 255) / 256, 256>>>(b_V);
    scatter_virtual<<<(B_ * VKV_ * 256 + 255) / 256, 256>>>(v_k, v_v);

    // tensor-core flash attention
    {
        dim3 grid(S_ / 128, B_ * NQK_);
        attn_mma<<<grid, 256>>>();
    }

    // GEMM2: (4096 x 768) = Zh * Wh2^T + b_O -> out fp32
    {
        dim3 grid(DM_ / 128, BS_ / 128);
        hgemm<<<grid, 256>>>(Zh, Wh2, out, BS_, DM_, NOV_, b_O);
    }
}

// round 4
// speedup vs baseline: 4.4507x; 1.0282x over previous
#include <cuda_runtime.h>
#include <cuda_fp16.h>
#include <cstdint>

// ---------------------------------------------------------------------------
// Problem constants
// ---------------------------------------------------------------------------
#define B_   2
#define S_   2048
#define DM_  768
#define NQK_ 16
#define DQK_ 16
#define NOV_ 256
#define VKV_ 16
#define SK_  (S_ + VKV_)     // 2064 keys
#define BS_  (B_ * S_)       // 4096 rows

// ---------------------------------------------------------------------------
// Device scratch
// ---------------------------------------------------------------------------
__device__ __half g_Ah  [BS_ * DM_];
__device__ __half g_Wh1 [DM_ * DM_];
__device__ __half g_Wh2 [DM_ * NOV_];
__device__ float  g_qkv [BS_ * DM_];
__device__ __half g_Qh  [B_ * NQK_ * S_  * DQK_];
__device__ __half g_Kh  [B_ * NQK_ * SK_ * DQK_];
__device__ __half g_Vh  [B_ * NQK_ * SK_ * DQK_];
__device__ __half g_Zh  [BS_ * NOV_];

// ---------------------------------------------------------------------------
// helpers
// ---------------------------------------------------------------------------
__device__ __forceinline__ uint32_t smem_u32(const void* p) {
    return (uint32_t)__cvta_generic_to_shared(p);
}
__device__ __forceinline__ void cp16(uint32_t s, const void* g) {
    asm volatile("cp.async.cg.shared.global [%0], [%1], 16;" :: "r"(s), "l"(g));
}
__device__ __forceinline__ float ex2f(float x) {
    float y; asm("ex2.approx.ftz.f32 %0, %1;" : "=f"(y) : "f"(x)); return y;
}
// pack {lo,hi} floats -> half2 and take 2^x elementwise (packed MUFU)
__device__ __forceinline__ uint32_t ex2h2(float lo, float hi) {
    uint32_t h, r;
    asm("cvt.rn.f16x2.f32 %0, %1, %2;" : "=r"(h) : "f"(hi), "f"(lo));
    asm("ex2.approx.f16x2 %0, %1;" : "=r"(r) : "r"(h));
    return r;
}
__device__ __forceinline__ void ldm4(uint32_t& r0, uint32_t& r1, uint32_t& r2, uint32_t& r3, uint32_t addr) {
    asm volatile("ldmatrix.sync.aligned.m8n8.x4.shared.b16 {%0,%1,%2,%3}, [%4];"
                 : "=r"(r0), "=r"(r1), "=r"(r2), "=r"(r3) : "r"(addr));
}
__device__ __forceinline__ void ldm4t(uint32_t& r0, uint32_t& r1, uint32_t& r2, uint32_t& r3, uint32_t addr) {
    asm volatile("ldmatrix.sync.aligned.m8n8.x4.trans.shared.b16 {%0,%1,%2,%3}, [%4];"
                 : "=r"(r0), "=r"(r1), "=r"(r2), "=r"(r3) : "r"(addr));
}
__device__ __forceinline__ void mma16816(float* d, const uint32_t* a, const uint32_t* b) {
    asm volatile("mma.sync.aligned.m16n8k16.row.col.f32.f16.f16.f32 "
                 "{%0,%1,%2,%3},{%4,%5,%6,%7},{%8,%9},{%0,%1,%2,%3};"
                 : "+f"(d[0]), "+f"(d[1]), "+f"(d[2]), "+f"(d[3])
                 : "r"(a[0]), "r"(a[1]), "r"(a[2]), "r"(a[3]), "r"(b[0]), "r"(b[1]));
}
__device__ __forceinline__ uint32_t packh2(float x, float y) {
    __half2 h = __floats2half2_rn(x, y);
    return *(uint32_t*)&h;
}

// ---------------------------------------------------------------------------
// 1) Pack weights / convert resid
// ---------------------------------------------------------------------------
__global__ void pack_w1(const float* __restrict__ WQ,
                        const float* __restrict__ WK,
                        const float* __restrict__ WV)
{
    int idx = blockIdx.x * blockDim.x + threadIdx.x;
    if (idx >= DM_ * DM_) return;
    int c = idx / DM_;
    int d = idx % DM_;
    float v;
    if (c < 256) {
        int h = c >> 4, e = c & 15;
        v = WQ[(h * DM_ + d) * DQK_ + e];
    } else if (c < 512) {
        int cc = c - 256;
        int h = cc >> 4, e = cc & 15;
        v = WK[(h * DM_ + d) * DQK_ + e];
    } else {
        v = WV[(c - 512) * DM_ + d];
    }
    g_Wh1[idx] = __float2half(v);
}

__global__ void pack_w2(const float* __restrict__ WO)
{
    int idx = blockIdx.x * blockDim.x + threadIdx.x;
    if (idx >= DM_ * NOV_) return;
    int m  = idx >> 8;
    int nv = idx & 255;
    g_Wh2[idx] = __float2half(WO[nv * DM_ + m]);
}

__global__ void cvt_resid(const float* __restrict__ in)
{
    int i = (blockIdx.x * blockDim.x + threadIdx.x) * 4;
    if (i >= BS_ * DM_) return;
    float4 v = *(const float4*)(in + i);
    *(__half2*)&g_Ah[i]     = __floats2half2_rn(v.x, v.y);
    *(__half2*)&g_Ah[i + 2] = __floats2half2_rn(v.z, v.w);
}

// ---------------------------------------------------------------------------
// 2) fp16 tensor-core GEMM, 3-stage cp.async pipeline (dynamic smem)
// ---------------------------------------------------------------------------
#define BKH 32
#define LDT 40
#define HG_STAGES 3
#define HG_STAGE_HALVES (128 * LDT)
#define HG_SMEM_BYTES (HG_STAGES * HG_STAGE_HALVES * 2 * 2)   // A+B, 61440 B

__global__ __launch_bounds__(256)
void hgemm(const __half* __restrict__ A, const __half* __restrict__ Bm,
           float* __restrict__ C, int M, int N, int K,
           const float* __restrict__ bias)
{
    extern __shared__ __half sm[];
    __half* Asm = sm;
    __half* Bsm = sm + HG_STAGES * HG_STAGE_HALVES;

    const int tid  = threadIdx.x;
    const int warp = tid >> 5, lane = tid & 31;
    const int wm = warp >> 1, wn = warp & 1;
    const int bm = blockIdx.y * 128, bn = blockIdx.x * 128;

    const int row  = tid >> 1;
    const int koff = (tid & 1) * 16;
    const __half* Ag = A + (size_t)(bm + row) * K + koff;
    const __half* Bg = Bm + (size_t)(bn + row) * K + koff;
    const uint32_t AsB = smem_u32(Asm);
    const uint32_t BsB = smem_u32(Bsm);
    const uint32_t stAoff = (uint32_t)(row * LDT + koff) * 2;
    const uint32_t SBYTES = HG_STAGE_HALVES * 2;

    const int mat = lane >> 3, r = lane & 7;
    const uint32_t a_off = (uint32_t)((wm * 32 + (mat & 1) * 8 + r) * LDT + (mat >> 1) * 8) * 2;
    const uint32_t b_off = (uint32_t)((wn * 64 + (mat >> 1) * 8 + r) * LDT + (mat & 1) * 8) * 2;

    float acc[2][8][4];
#pragma unroll
    for (int i = 0; i < 2; i++)
#pragma unroll
        for (int j = 0; j < 8; j++)
#pragma unroll
            for (int t = 0; t < 4; t++) acc[i][j][t] = 0.f;

    const int KT = K / BKH;

    // prologue: stages 0, 1
#pragma unroll
    for (int s = 0; s < 2; s++) {
        const __half* ag = Ag + s * BKH;
        const __half* bg = Bg + s * BKH;
        cp16(AsB + s * SBYTES + stAoff,      ag);
        cp16(AsB + s * SBYTES + stAoff + 16, ag + 8);
        cp16(BsB + s * SBYTES + stAoff,      bg);
        cp16(BsB + s * SBYTES + stAoff + 16, bg + 8);
        asm volatile("cp.async.commit_group;");
    }
    asm volatile("cp.async.wait_group 1;" ::: "memory");
    __syncthreads();

    int stage = 0;
    for (int kt = 0; kt < KT; kt++) {
        const uint32_t Abuf = AsB + (uint32_t)stage * SBYTES;
        const uint32_t Bbuf = BsB + (uint32_t)stage * SBYTES;
#pragma unroll
        for (int ks = 0; ks < 2; ks++) {
            uint32_t a[2][4];
#pragma unroll
            for (int mt = 0; mt < 2; mt++)
                ldm4(a[mt][0], a[mt][1], a[mt][2], a[mt][3],
                     Abuf + a_off + (uint32_t)(mt * 16 * LDT + ks * 16) * 2);
            uint32_t bf[8][2];
#pragma unroll
            for (int p = 0; p < 4; p++) {
                uint32_t r0, r1, r2, r3;
                ldm4(r0, r1, r2, r3,
                     Bbuf + b_off + (uint32_t)(p * 16 * LDT + ks * 16) * 2);
                bf[2 * p][0] = r0; bf[2 * p][1] = r1;
                bf[2 * p + 1][0] = r2; bf[2 * p + 1][1] = r3;
            }
#pragma unroll
            for (int mt = 0; mt < 2; mt++)
#pragma unroll
                for (int nt = 0; nt < 8; nt++)
                    mma16816(acc[mt][nt], a[mt], bf[nt]);
        }

        if (kt + 2 < KT) {
            const int ns = (stage + 2 >= HG_STAGES) ? stage + 2 - HG_STAGES : stage + 2;
            const __half* ag = Ag + (kt + 2) * BKH;
            const __half* bg = Bg + (kt + 2) * BKH;
            cp16(AsB + (uint32_t)ns * SBYTES + stAoff,      ag);
            cp16(AsB + (uint32_t)ns * SBYTES + stAoff + 16, ag + 8);
            cp16(BsB + (uint32_t)ns * SBYTES + stAoff,      bg);
            cp16(BsB + (uint32_t)ns * SBYTES + stAoff + 16, bg + 8);
            asm volatile("cp.async.commit_group;");
            asm volatile("cp.async.wait_group 1;" ::: "memory");
        } else {
            asm volatile("cp.async.wait_group 0;" ::: "memory");
        }
        __syncthreads();
        stage = (stage + 1 >= HG_STAGES) ? 0 : stage + 1;
    }

#pragma unroll
    for (int mt = 0; mt < 2; mt++) {
        const int r0 = bm + wm * 32 + mt * 16 + (lane >> 2);
#pragma unroll
        for (int nt = 0; nt < 8; nt++) {
            const int c0 = bn + wn * 64 + nt * 8 + (lane & 3) * 2;
            float b0 = 0.f, b1 = 0.f;
            if (bias) { b0 = bias[c0]; b1 = bias[c0 + 1]; }
            float2 v01 = { acc[mt][nt][0] + b0, acc[mt][nt][1] + b1 };
            float2 v23 = { acc[mt][nt][2] + b0, acc[mt][nt][3] + b1 };
            *(float2*)(C + (size_t)r0 * N + c0)        = v01;
            *(float2*)(C + (size_t)(r0 + 8) * N + c0)  = v23;
        }
    }
}

// ---------------------------------------------------------------------------
// 3) Rotary + bias + scatter Q,K (Q gets scale*log2e folded)
// ---------------------------------------------------------------------------
#define QSCALE 0.36067376022224085f   // 0.25 * log2(e)

__global__ void rot_scatter_qk(const float* __restrict__ bQ,
                               const float* __restrict__ bK)
{
    int idx = blockIdx.x * blockDim.x + threadIdx.x;
    if (idx >= B_ * S_ * NQK_) return;
    int h = idx & 15;
    int s = (idx >> 4) & (S_ - 1);
    int b = idx >> 15;

    const float* src = &g_qkv[(size_t)(b * S_ + s) * DM_];
    float qv[16], kv[16];
#pragma unroll
    for (int e = 0; e < 16; e++) {
        qv[e] = src[h * 16 + e]       + bQ[h * 16 + e];
        kv[e] = src[256 + h * 16 + e] + bK[h * 16 + e];
    }
    float pos = (float)s;
    __half qo[16], ko[16];
#pragma unroll
    for (int i = 0; i < 8; i++) {
        float freq = powf(10000.f, (float)i / 8.f);
        float ang = pos / freq;
        float sn, cs;
        sincosf(ang, &sn, &cs);
        qo[i]     = __float2half((qv[i]     * cs - qv[i + 8] * sn) * QSCALE);
        qo[i + 8] = __float2half((qv[i + 8] * cs + qv[i]     * sn) * QSCALE);
        ko[i]     = __float2half(kv[i]     * cs - kv[i + 8] * sn);
        ko[i + 8] = __float2half(kv[i + 8] * cs + kv[i]     * sn);
    }
    __half* qdst = &g_Qh[((size_t)(b * NQK_ + h) * S_ + s) * DQK_];
    __half* kdst = &g_Kh[((size_t)(b * NQK_ + h) * SK_ + s) * DQK_];
#pragma unroll
    for (int e = 0; e < 16; e++) { qdst[e] = qo[e]; kdst[e] = ko[e]; }
}

// ---------------------------------------------------------------------------
// 4) V scatter (half)
// ---------------------------------------------------------------------------
__global__ void scatter_v(const float* __restrict__ bV)
{
    int idx = blockIdx.x * blockDim.x + threadIdx.x;
    if (idx >= B_ * S_ * NOV_) return;
    int n = idx & 255;
    int s = (idx >> 8) & (S_ - 1);
    int b = idx >> 19;
    int h = n >> 4, r = n & 15;
    g_Vh[((size_t)(b * NQK_ + h) * SK_ + s) * DQK_ + r] =
        __float2half(g_qkv[(size_t)(b * S_ + s) * DM_ + 512 + n] + bV[n]);
}

// ---------------------------------------------------------------------------
// 5) Virtual K/V rows (half)
// ---------------------------------------------------------------------------
__global__ void scatter_virtual(const float* __restrict__ vk,
                                const float* __restrict__ vv)
{
    int idx = blockIdx.x * blockDim.x + threadIdx.x;
    if (idx >= B_ * VKV_ * 256) return;
    int c = idx & 255;
    int m = (idx >> 8) & 15;
    int b = idx >> 12;
    int h = c >> 4, e = c & 15;
    size_t row = ((size_t)(b * NQK_ + h) * SK_ + S_ + m) * DQK_ + e;
    g_Kh[row] = __float2half(vk[m * 256 + c]);
    g_Vh[row] = __float2half(vv[m * 256 + c]);
}

// ---------------------------------------------------------------------------
// 6) Tensor-core flash attention (f16x2 exp, ones-MMA row sums)
// ---------------------------------------------------------------------------
__global__ __launch_bounds__(256)
void attn_mma()
{
    const int bh   = blockIdx.y;
    const int qt   = (int)(gridDim.x - 1) - (int)blockIdx.x;   // big tiles first
    const int tid  = threadIdx.x;
    const int warp = tid >> 5, lane = tid & 31;

    __shared__ __half Qs[128 * 16];
    __shared__ __half Ks[2][128 * 16];
    __shared__ __half Vs[2][128 * 16];

    const __half* Qg = g_Qh + ((size_t)bh * S_ + qt * 128) * DQK_;
    const __half* Kg = g_Kh + (size_t)bh * SK_ * DQK_;
    const __half* Vg = g_Vh + (size_t)bh * SK_ * DQK_;

    const int ld_row = tid >> 1;
    const int ld_off = (tid & 1) * 8;

    *(float4*)&Qs[ld_row * 16 + ld_off] =
        *(const float4*)&Qg[(size_t)ld_row * 16 + ld_off];

    {
        int j = ld_row; if (j > SK_ - 1) j = SK_ - 1;
        cp16(smem_u32(&Ks[0][ld_row * 16 + ld_off]), Kg + (size_t)j * 16 + ld_off);
        cp16(smem_u32(&Vs[0][ld_row * 16 + ld_off]), Vg + (size_t)j * 16 + ld_off);
        asm volatile("cp.async.commit_group;");
    }
    __syncthreads();

    uint32_t qa[4];
    {
        int g = lane >> 3, r = lane & 7;
        int row = warp * 16 + (g & 1) * 8 + r;
        int col = (g >> 1) * 8;
        ldm4(qa[0], qa[1], qa[2], qa[3], smem_u32(&Qs[row * 16 + col]));
    }

    float m0 = -1e30f, m1 = -1e30f;
    float o[2][4] = {{0.f,0.f,0.f,0.f},{0.f,0.f,0.f,0.f}};
    float oL[4]   = {0.f,0.f,0.f,0.f};                 // row sums via ones-MMA
    const uint32_t onesb[2] = { 0x3C003C00u, 0x3C003C00u };

    const int ntiles = qt + 2;
    const int qrow0  = qt * 128 + warp * 16 + (lane >> 2);

    for (int jt = 0; jt < ntiles; jt++) {
        const int buf = jt & 1;
        if (jt + 1 < ntiles) {
            int j = (jt + 1) * 128 + ld_row; if (j > SK_ - 1) j = SK_ - 1;
            cp16(smem_u32(&Ks[buf ^ 1][ld_row * 16 + ld_off]), Kg + (size_t)j * 16 + ld_off);
            cp16(smem_u32(&Vs[buf ^ 1][ld_row * 16 + ld_off]), Vg + (size_t)j * 16 + ld_off);
            asm volatile("cp.async.commit_group;");
            asm volatile("cp.async.wait_group 1;" ::: "memory");
        } else {
            asm volatile("cp.async.wait_group 0;" ::: "memory");
        }
        __syncthreads();

        // ---- QK^T ----
        float sc[16][4];
#pragma unroll
        for (int nt = 0; nt < 16; nt++)
#pragma unroll
            for (int t = 0; t < 4; t++) sc[nt][t] = 0.f;

        {
            const int g = lane >> 3, r = lane & 7;
            const int krow = (g >> 1) * 8 + r;
            const int kcol = (g & 1) * 8;
#pragma unroll
            for (int i = 0; i < 8; i++) {
                uint32_t b0, b1, b2, b3;
                ldm4(b0, b1, b2, b3,
                     smem_u32(&Ks[buf][(16 * i + krow) * 16 + kcol]));
                uint32_t bl[2] = { b0, b1 };
                uint32_t bh2[2] = { b2, b3 };
                mma16816(sc[2 * i],     qa, bl);
                mma16816(sc[2 * i + 1], qa, bh2);
            }
        }

        // ---- mask (diagonal tiles only) ----
        if (jt >= qt) {
            const int jb = jt * 128 + (lane & 3) * 2;
            const int t0 = qrow0 + 16;
            const int t1 = qrow0 + 24;
#pragma unroll
            for (int nt = 0; nt < 16; nt++) {
                int j0 = jb + nt * 8;
                if (j0     > t0) sc[nt][0] = -1e30f;
                if (j0 + 1 > t0) sc[nt][1] = -1e30f;
                if (j0     > t1) sc[nt][2] = -1e30f;
                if (j0 + 1 > t1) sc[nt][3] = -1e30f;
            }
        }

        // ---- online softmax (log2 domain, packed half2 exp) ----
        float rm0 = sc[0][0], rm1 = sc[0][2];
#pragma unroll
        for (int nt = 0; nt < 16; nt++) {
            rm0 = fmaxf(rm0, fmaxf(sc[nt][0], sc[nt][1]));
            rm1 = fmaxf(rm1, fmaxf(sc[nt][2], sc[nt][3]));
        }
        rm0 = fmaxf(rm0, __shfl_xor_sync(0xffffffff, rm0, 1));
        rm0 = fmaxf(rm0, __shfl_xor_sync(0xffffffff, rm0, 2));
        rm1 = fmaxf(rm1, __shfl_xor_sync(0xffffffff, rm1, 1));
        rm1 = fmaxf(rm1, __shfl_xor_sync(0xffffffff, rm1, 2));

        const float mn0 = fmaxf(m0, rm0);
        const float mn1 = fmaxf(m1, rm1);
        const float c0 = ex2f(m0 - mn0);
        const float c1 = ex2f(m1 - mn1);
        m0 = mn0; m1 = mn1;
        o[0][0] *= c0; o[0][1] *= c0; o[0][2] *= c1; o[0][3] *= c1;
        o[1][0] *= c0; o[1][1] *= c0; o[1][2] *= c1; o[1][3] *= c1;
        oL[0]   *= c0; oL[1]   *= c0; oL[2]   *= c1; oL[3]   *= c1;

        uint32_t p[16][2];
#pragma unroll
        for (int nt = 0; nt < 16; nt++) {
            p[nt][0] = ex2h2(sc[nt][0] - mn0, sc[nt][1] - mn0);
            p[nt][1] = ex2h2(sc[nt][2] - mn1, sc[nt][3] - mn1);
        }

        // ---- P @ V (+ ones column for row sums) ----
        {
            const int g = lane >> 3, r = lane & 7;
            const int vrow = (g & 1) * 8 + r;
            const int vcol = (g >> 1) * 8;
#pragma unroll
            for (int kt = 0; kt < 8; kt++) {
                uint32_t pa[4];
                pa[0] = p[2 * kt][0];
                pa[1] = p[2 * kt][1];
                pa[2] = p[2 * kt + 1][0];
                pa[3] = p[2 * kt + 1][1];
                uint32_t v0, v1, v2, v3;
                ldm4t(v0, v1, v2, v3,
                      smem_u32(&Vs[buf][(16 * kt + vrow) * 16 + vcol]));
                uint32_t bl[2] = { v0, v1 };
                uint32_t bh2[2] = { v2, v3 };
                mma16816(o[0], pa, bl);
                mma16816(o[1], pa, bh2);
                mma16816(oL,   pa, onesb);
            }
        }
        __syncthreads();
    }

    // ---- epilogue (row sums already in oL; identical across quad lanes) ----
    const float inv0 = 1.f / oL[0];
    const float inv1 = 1.f / oL[2];

    const int b = bh >> 4, h = bh & 15;
    const int col = (lane & 3) * 2;
#pragma unroll
    for (int vt = 0; vt < 2; vt++) {
        uint32_t lo = packh2(o[vt][0] * inv0, o[vt][1] * inv0);
        uint32_t hi = packh2(o[vt][2] * inv1, o[vt][3] * inv1);
        size_t base0 = ((size_t)(b * S_ + qrow0)     ) * NOV_ + h * 16 + vt * 8 + col;
        size_t base1 = ((size_t)(b * S_ + qrow0 + 8) ) * NOV_ + h * 16 + vt * 8 + col;
        *(uint32_t*)&g_Zh[base0] = lo;
        *(uint32_t*)&g_Zh[base1] = hi;
    }
}

// ---------------------------------------------------------------------------
// Launch
// ---------------------------------------------------------------------------
extern "C" void kernel_launch(void* const* d_in, const int* in_sizes, int n_in,
                              void* d_out, int out_size)
{
    const float* resid = (const float*)d_in[0];
    const float* W_Q   = (const float*)d_in[1];
    const float* W_K   = (const float*)d_in[2];
    const float* W_V   = (const float*)d_in[3];
    const float* W_O   = (const float*)d_in[4];
    const float* b_Q   = (const float*)d_in[5];
    const float* b_K   = (const float*)d_in[6];
    const float* b_V   = (const float*)d_in[7];
    const float* b_O   = (const float*)d_in[8];
    const float* v_k   = (const float*)d_in[9];
    const float* v_v   = (const float*)d_in[10];
    float* out = (float*)d_out;

    __half *Ah, *Wh1, *Wh2, *Zh;
    float *qkv;
    cudaGetSymbolAddress((void**)&Ah,  g_Ah);
    cudaGetSymbolAddress((void**)&Wh1, g_Wh1);
    cudaGetSymbolAddress((void**)&Wh2, g_Wh2);
    cudaGetSymbolAddress((void**)&Zh,  g_Zh);
    cudaGetSymbolAddress((void**)&qkv, g_qkv);

    cudaFuncSetAttribute(hgemm, cudaFuncAttributeMaxDynamicSharedMemorySize,
                         HG_SMEM_BYTES);

    pack_w1<<<(DM_ * DM_ + 255) / 256, 256>>>(W_Q, W_K, W_V);
    pack_w2<<<(DM_ * NOV_ + 255) / 256, 256>>>(W_O);
    cvt_resid<<<(BS_ * DM_ / 4 + 255) / 256, 256>>>(resid);

    // GEMM1: (4096 x 768) = Ah * Wh1^T -> g_qkv fp32
    {
        dim3 grid(DM_ / 128, BS_ / 128);
        hgemm<<<grid, 256, HG_SMEM_BYTES>>>(Ah, Wh1, qkv, BS_, DM_, DM_, nullptr);
    }

    rot_scatter_qk<<<(B_ * S_ * NQK_ + 255) / 256, 256>>>(b_Q, b_K);
    scatter_v<<<(B_ * S_ * NOV_ + 255) / 256, 256>>>(b_V);
    scatter_virtual<<<(B_ * VKV_ * 256 + 255) / 256, 256>>>(v_k, v_v);

    // tensor-core flash attention
    {
        dim3 grid(S_ / 128, B_ * NQK_);
        attn_mma<<<grid, 256>>>();
    }

    // GEMM2: (4096 x 768) = Zh * Wh2^T + b_O -> out fp32
    {
        dim3 grid(DM_ / 128, BS_ / 128);
        hgemm<<<grid, 256, HG_SMEM_BYTES>>>(Zh, Wh2, out, BS_, DM_, NOV_, b_O);
    }
}

// round 5
// speedup vs baseline: 4.5776x; 1.0285x over previous
#include <cuda_runtime.h>
#include <cuda_fp16.h>
#include <cstdint>

// ---------------------------------------------------------------------------
// Problem constants
// ---------------------------------------------------------------------------
#define B_   2
#define S_   2048
#define DM_  768
#define NQK_ 16
#define DQK_ 16
#define NOV_ 256
#define VKV_ 16
#define SK_  (S_ + VKV_)     // 2064 keys
#define BS_  (B_ * S_)       // 4096 rows

// ---------------------------------------------------------------------------
// Device scratch
// ---------------------------------------------------------------------------
__device__ __half g_Ah  [BS_ * DM_];
__device__ __half g_Wh1 [DM_ * DM_];
__device__ __half g_Wh2 [DM_ * NOV_];
__device__ float  g_qkv [BS_ * DM_];
__device__ float  g_rot [S_ * 16];                  // [s][0..7]=sin, [8..15]=cos
__device__ __half g_Qh  [B_ * NQK_ * S_  * DQK_];
__device__ __half g_Kh  [B_ * NQK_ * SK_ * DQK_];
__device__ __half g_Vh  [B_ * NQK_ * SK_ * DQK_];
__device__ __half g_Zh  [BS_ * NOV_];

// ---------------------------------------------------------------------------
// helpers
// ---------------------------------------------------------------------------
__device__ __forceinline__ uint32_t smem_u32(const void* p) {
    return (uint32_t)__cvta_generic_to_shared(p);
}
__device__ __forceinline__ void cp16(uint32_t s, const void* g) {
    asm volatile("cp.async.cg.shared.global [%0], [%1], 16;" :: "r"(s), "l"(g));
}
__device__ __forceinline__ float ex2f(float x) {
    float y; asm("ex2.approx.ftz.f32 %0, %1;" : "=f"(y) : "f"(x)); return y;
}
__device__ __forceinline__ uint32_t ex2h2(float lo, float hi) {
    uint32_t h, r;
    asm("cvt.rn.f16x2.f32 %0, %1, %2;" : "=r"(h) : "f"(hi), "f"(lo));
    asm("ex2.approx.f16x2 %0, %1;" : "=r"(r) : "r"(h));
    return r;
}
__device__ __forceinline__ void ldm4(uint32_t& r0, uint32_t& r1, uint32_t& r2, uint32_t& r3, uint32_t addr) {
    asm volatile("ldmatrix.sync.aligned.m8n8.x4.shared.b16 {%0,%1,%2,%3}, [%4];"
                 : "=r"(r0), "=r"(r1), "=r"(r2), "=r"(r3) : "r"(addr));
}
__device__ __forceinline__ void ldm4t(uint32_t& r0, uint32_t& r1, uint32_t& r2, uint32_t& r3, uint32_t addr) {
    asm volatile("ldmatrix.sync.aligned.m8n8.x4.trans.shared.b16 {%0,%1,%2,%3}, [%4];"
                 : "=r"(r0), "=r"(r1), "=r"(r2), "=r"(r3) : "r"(addr));
}
__device__ __forceinline__ void mma16816(float* d, const uint32_t* a, const uint32_t* b) {
    asm volatile("mma.sync.aligned.m16n8k16.row.col.f32.f16.f16.f32 "
                 "{%0,%1,%2,%3},{%4,%5,%6,%7},{%8,%9},{%0,%1,%2,%3};"
                 : "+f"(d[0]), "+f"(d[1]), "+f"(d[2]), "+f"(d[3])
                 : "r"(a[0]), "r"(a[1]), "r"(a[2]), "r"(a[3]), "r"(b[0]), "r"(b[1]));
}
__device__ __forceinline__ uint32_t packh2(float x, float y) {
    __half2 h = __floats2half2_rn(x, y);
    return *(uint32_t*)&h;
}

// ---------------------------------------------------------------------------
// 1) Fused prep: pack W1, pack W2, convert resid, rotary table
//    block ranges: [0,2304) w1 | [2304,3072) w2 | [3072,6144) resid | [6144,6208) rot
// ---------------------------------------------------------------------------
#define PREP_W1_BLKS 2304
#define PREP_W2_BLKS 768
#define PREP_CV_BLKS 3072
#define PREP_RT_BLKS 64
#define PREP_BLKS (PREP_W1_BLKS + PREP_W2_BLKS + PREP_CV_BLKS + PREP_RT_BLKS)

__global__ void prep_kernel(const float* __restrict__ WQ,
                            const float* __restrict__ WK,
                            const float* __restrict__ WV,
                            const float* __restrict__ WO,
                            const float* __restrict__ resid)
{
    const int blk = blockIdx.x;
    if (blk < PREP_W1_BLKS) {
        int idx = blk * 256 + threadIdx.x;             // < 589824
        int c = idx / DM_;
        int d = idx % DM_;
        float v;
        if (c < 256) {
            int h = c >> 4, e = c & 15;
            v = WQ[(h * DM_ + d) * DQK_ + e];
        } else if (c < 512) {
            int cc = c - 256;
            int h = cc >> 4, e = cc & 15;
            v = WK[(h * DM_ + d) * DQK_ + e];
        } else {
            v = WV[(c - 512) * DM_ + d];
        }
        g_Wh1[idx] = __float2half(v);
    } else if (blk < PREP_W1_BLKS + PREP_W2_BLKS) {
        int idx = (blk - PREP_W1_BLKS) * 256 + threadIdx.x;   // < 196608
        int m  = idx >> 8;
        int nv = idx & 255;
        g_Wh2[idx] = __float2half(WO[nv * DM_ + m]);
    } else if (blk < PREP_W1_BLKS + PREP_W2_BLKS + PREP_CV_BLKS) {
        int i = ((blk - PREP_W1_BLKS - PREP_W2_BLKS) * 256 + threadIdx.x) * 4;
        float4 v = *(const float4*)(resid + i);
        *(__half2*)&g_Ah[i]     = __floats2half2_rn(v.x, v.y);
        *(__half2*)&g_Ah[i + 2] = __floats2half2_rn(v.z, v.w);
    } else {
        int idx = (blk - PREP_W1_BLKS - PREP_W2_BLKS - PREP_CV_BLKS) * 256 + threadIdx.x;
        int s = idx >> 3, i = idx & 7;                 // 2048 x 8
        float freq = powf(10000.f, (float)i / 8.f);
        float sn, cs;
        sincosf((float)s / freq, &sn, &cs);
        g_rot[s * 16 + i]     = sn;
        g_rot[s * 16 + 8 + i] = cs;
    }
}

// ---------------------------------------------------------------------------
// 2) fp16 tensor-core GEMM: 64x128 tile, 3-stage cp.async, 8 warps (2x4)
// ---------------------------------------------------------------------------
#define BKH 32
#define LDT 40
#define HG_STAGES 3
#define HG_A_HALVES (64  * LDT)
#define HG_B_HALVES (128 * LDT)
#define HG_SMEM_BYTES (HG_STAGES * (HG_A_HALVES + HG_B_HALVES) * 2)   // 46080

__global__ __launch_bounds__(256)
void hgemm(const __half* __restrict__ A, const __half* __restrict__ Bm,
           float* __restrict__ C, int M, int N, int K,
           const float* __restrict__ bias)
{
    extern __shared__ __half sm[];
    __half* Asm = sm;
    __half* Bsm = sm + HG_STAGES * HG_A_HALVES;

    const int tid  = threadIdx.x;
    const int warp = tid >> 5, lane = tid & 31;
    const int wm = warp >> 2, wn = warp & 3;           // 2 x 4 warps
    const int bm = blockIdx.y * 64, bn = blockIdx.x * 128;

    // A staging: 64 rows x 32 halves = 256 chunks of 16B -> 1 per thread
    const int arow = tid >> 2;
    const int aoff = (tid & 3) * 8;
    // B staging: 128 rows x 32 halves -> 2 chunks per thread
    const int brow = tid >> 1;
    const int boff = (tid & 1) * 16;

    const __half* Ag = A + (size_t)(bm + arow) * K + aoff;
    const __half* Bg = Bm + (size_t)(bn + brow) * K + boff;
    const uint32_t AsB = smem_u32(Asm);
    const uint32_t BsB = smem_u32(Bsm);
    const uint32_t stA = (uint32_t)(arow * LDT + aoff) * 2;
    const uint32_t stB = (uint32_t)(brow * LDT + boff) * 2;
    const uint32_t SA = HG_A_HALVES * 2;               // 5120 B per stage
    const uint32_t SB = HG_B_HALVES * 2;               // 10240 B per stage

    const int mat = lane >> 3, r = lane & 7;
    const uint32_t a_off = (uint32_t)((wm * 32 + (mat & 1) * 8 + r) * LDT + (mat >> 1) * 8) * 2;
    const uint32_t b_off = (uint32_t)((wn * 32 + (mat >> 1) * 8 + r) * LDT + (mat & 1) * 8) * 2;

    float acc[2][4][4];
#pragma unroll
    for (int i = 0; i < 2; i++)
#pragma unroll
        for (int j = 0; j < 4; j++)
#pragma unroll
            for (int t = 0; t < 4; t++) acc[i][j][t] = 0.f;

    const int KT = K / BKH;

#pragma unroll
    for (int s = 0; s < 2; s++) {
        cp16(AsB + s * SA + stA,      Ag + s * BKH);
        cp16(BsB + s * SB + stB,      Bg + s * BKH);
        cp16(BsB + s * SB + stB + 16, Bg + s * BKH + 8);
        asm volatile("cp.async.commit_group;");
    }
    asm volatile("cp.async.wait_group 1;" ::: "memory");
    __syncthreads();

    int stage = 0;
    for (int kt = 0; kt < KT; kt++) {
        const uint32_t Abuf = AsB + (uint32_t)stage * SA;
        const uint32_t Bbuf = BsB + (uint32_t)stage * SB;
#pragma unroll
        for (int ks = 0; ks < 2; ks++) {
            uint32_t a[2][4];
#pragma unroll
            for (int mt = 0; mt < 2; mt++)
                ldm4(a[mt][0], a[mt][1], a[mt][2], a[mt][3],
                     Abuf + a_off + (uint32_t)(mt * 16 * LDT + ks * 16) * 2);
            uint32_t bf[4][2];
#pragma unroll
            for (int p = 0; p < 2; p++) {
                uint32_t r0, r1, r2, r3;
                ldm4(r0, r1, r2, r3,
                     Bbuf + b_off + (uint32_t)(p * 16 * LDT + ks * 16) * 2);
                bf[2 * p][0] = r0; bf[2 * p][1] = r1;
                bf[2 * p + 1][0] = r2; bf[2 * p + 1][1] = r3;
            }
#pragma unroll
            for (int mt = 0; mt < 2; mt++)
#pragma unroll
                for (int nt = 0; nt < 4; nt++)
                    mma16816(acc[mt][nt], a[mt], bf[nt]);
        }

        if (kt + 2 < KT) {
            const int ns = (stage + 2 >= HG_STAGES) ? stage + 2 - HG_STAGES : stage + 2;
            const __half* ag = Ag + (kt + 2) * BKH;
            const __half* bg = Bg + (kt + 2) * BKH;
            cp16(AsB + (uint32_t)ns * SA + stA,      ag);
            cp16(BsB + (uint32_t)ns * SB + stB,      bg);
            cp16(BsB + (uint32_t)ns * SB + stB + 16, bg + 8);
            asm volatile("cp.async.commit_group;");
            asm volatile("cp.async.wait_group 1;" ::: "memory");
        } else {
            asm volatile("cp.async.wait_group 0;" ::: "memory");
        }
        __syncthreads();
        stage = (stage + 1 >= HG_STAGES) ? 0 : stage + 1;
    }

#pragma unroll
    for (int mt = 0; mt < 2; mt++) {
        const int r0 = bm + wm * 32 + mt * 16 + (lane >> 2);
#pragma unroll
        for (int nt = 0; nt < 4; nt++) {
            const int c0 = bn + wn * 32 + nt * 8 + (lane & 3) * 2;
            float b0 = 0.f, b1 = 0.f;
            if (bias) { b0 = bias[c0]; b1 = bias[c0 + 1]; }
            float2 v01 = { acc[mt][nt][0] + b0, acc[mt][nt][1] + b1 };
            float2 v23 = { acc[mt][nt][2] + b0, acc[mt][nt][3] + b1 };
            *(float2*)(C + (size_t)r0 * N + c0)       = v01;
            *(float2*)(C + (size_t)(r0 + 8) * N + c0) = v23;
        }
    }
}

// ---------------------------------------------------------------------------
// 3) Fused rotary-scatter Q,K + scatter V + virtual K/V
//    blocks [0,256): (b,s,h) rot + v  |  [256,288): virtual rows
// ---------------------------------------------------------------------------
#define QSCALE 0.36067376022224085f   // 0.25 * log2(e)
#define RV_MAIN_BLKS 256
#define RV_BLKS (RV_MAIN_BLKS + 32)

__global__ void rotv_kernel(const float* __restrict__ bQ,
                            const float* __restrict__ bK,
                            const float* __restrict__ bV,
                            const float* __restrict__ vk,
                            const float* __restrict__ vv)
{
    const int blk = blockIdx.x;
    if (blk < RV_MAIN_BLKS) {
        int idx = blk * 256 + threadIdx.x;     // over B*S*NQK = 65536
        int h = idx & 15;
        int s = (idx >> 4) & (S_ - 1);
        int b = idx >> 15;

        const float* src = &g_qkv[(size_t)(b * S_ + s) * DM_];
        const float* rt  = &g_rot[s * 16];

        float qv[16], kv[16];
#pragma unroll
        for (int e = 0; e < 16; e++) {
            qv[e] = src[h * 16 + e]       + bQ[h * 16 + e];
            kv[e] = src[256 + h * 16 + e] + bK[h * 16 + e];
        }
        __half qo[16], ko[16];
#pragma unroll
        for (int i = 0; i < 8; i++) {
            float sn = rt[i], cs = rt[8 + i];
            qo[i]     = __float2half((qv[i]     * cs - qv[i + 8] * sn) * QSCALE);
            qo[i + 8] = __float2half((qv[i + 8] * cs + qv[i]     * sn) * QSCALE);
            ko[i]     = __float2half(kv[i]     * cs - kv[i + 8] * sn);
            ko[i + 8] = __float2half(kv[i + 8] * cs + kv[i]     * sn);
        }
        __half* qdst = &g_Qh[((size_t)(b * NQK_ + h) * S_ + s) * DQK_];
        __half* kdst = &g_Kh[((size_t)(b * NQK_ + h) * SK_ + s) * DQK_];
#pragma unroll
        for (int e = 0; e < 16; e++) { qdst[e] = qo[e]; kdst[e] = ko[e]; }

        // V: heads h*16..h*16+15 -> (head h, r=e)
        __half* vdst = &g_Vh[((size_t)(b * NQK_ + h) * SK_ + s) * DQK_];
#pragma unroll
        for (int e = 0; e < 16; e++) {
            int n = h * 16 + e;
            vdst[e] = __float2half(src[512 + n] + bV[n]);
        }
    } else {
        int idx = (blk - RV_MAIN_BLKS) * 256 + threadIdx.x;   // over B*VKV*256 = 8192
        int c = idx & 255;
        int m = (idx >> 8) & 15;
        int b = idx >> 12;
        int h = c >> 4, e = c & 15;
        size_t row = ((size_t)(b * NQK_ + h) * SK_ + S_ + m) * DQK_ + e;
        g_Kh[row] = __float2half(vk[m * 256 + c]);
        g_Vh[row] = __float2half(vv[m * 256 + c]);
    }
}

// ---------------------------------------------------------------------------
// 4) Tensor-core flash attention (unchanged from R4)
// ---------------------------------------------------------------------------
__global__ __launch_bounds__(256)
void attn_mma()
{
    const int bh   = blockIdx.y;
    const int qt   = (int)(gridDim.x - 1) - (int)blockIdx.x;
    const int tid  = threadIdx.x;
    const int warp = tid >> 5, lane = tid & 31;

    __shared__ __half Qs[128 * 16];
    __shared__ __half Ks[2][128 * 16];
    __shared__ __half Vs[2][128 * 16];

    const __half* Qg = g_Qh + ((size_t)bh * S_ + qt * 128) * DQK_;
    const __half* Kg = g_Kh + (size_t)bh * SK_ * DQK_;
    const __half* Vg = g_Vh + (size_t)bh * SK_ * DQK_;

    const int ld_row = tid >> 1;
    const int ld_off = (tid & 1) * 8;

    *(float4*)&Qs[ld_row * 16 + ld_off] =
        *(const float4*)&Qg[(size_t)ld_row * 16 + ld_off];

    {
        int j = ld_row; if (j > SK_ - 1) j = SK_ - 1;
        cp16(smem_u32(&Ks[0][ld_row * 16 + ld_off]), Kg + (size_t)j * 16 + ld_off);
        cp16(smem_u32(&Vs[0][ld_row * 16 + ld_off]), Vg + (size_t)j * 16 + ld_off);
        asm volatile("cp.async.commit_group;");
    }
    __syncthreads();

    uint32_t qa[4];
    {
        int g = lane >> 3, r = lane & 7;
        int row = warp * 16 + (g & 1) * 8 + r;
        int col = (g >> 1) * 8;
        ldm4(qa[0], qa[1], qa[2], qa[3], smem_u32(&Qs[row * 16 + col]));
    }

    float m0 = -1e30f, m1 = -1e30f;
    float o[2][4] = {{0.f,0.f,0.f,0.f},{0.f,0.f,0.f,0.f}};
    float oL[4]   = {0.f,0.f,0.f,0.f};
    const uint32_t onesb[2] = { 0x3C003C00u, 0x3C003C00u };

    const int ntiles = qt + 2;
    const int qrow0  = qt * 128 + warp * 16 + (lane >> 2);

    for (int jt = 0; jt < ntiles; jt++) {
        const int buf = jt & 1;
        if (jt + 1 < ntiles) {
            int j = (jt + 1) * 128 + ld_row; if (j > SK_ - 1) j = SK_ - 1;
            cp16(smem_u32(&Ks[buf ^ 1][ld_row * 16 + ld_off]), Kg + (size_t)j * 16 + ld_off);
            cp16(smem_u32(&Vs[buf ^ 1][ld_row * 16 + ld_off]), Vg + (size_t)j * 16 + ld_off);
            asm volatile("cp.async.commit_group;");
            asm volatile("cp.async.wait_group 1;" ::: "memory");
        } else {
            asm volatile("cp.async.wait_group 0;" ::: "memory");
        }
        __syncthreads();

        float sc[16][4];
#pragma unroll
        for (int nt = 0; nt < 16; nt++)
#pragma unroll
            for (int t = 0; t < 4; t++) sc[nt][t] = 0.f;

        {
            const int g = lane >> 3, r = lane & 7;
            const int krow = (g >> 1) * 8 + r;
            const int kcol = (g & 1) * 8;
#pragma unroll
            for (int i = 0; i < 8; i++) {
                uint32_t b0, b1, b2, b3;
                ldm4(b0, b1, b2, b3,
                     smem_u32(&Ks[buf][(16 * i + krow) * 16 + kcol]));
                uint32_t bl[2] = { b0, b1 };
                uint32_t bh2[2] = { b2, b3 };
                mma16816(sc[2 * i],     qa, bl);
                mma16816(sc[2 * i + 1], qa, bh2);
            }
        }

        if (jt >= qt) {
            const int jb = jt * 128 + (lane & 3) * 2;
            const int t0 = qrow0 + 16;
            const int t1 = qrow0 + 24;
#pragma unroll
            for (int nt = 0; nt < 16; nt++) {
                int j0 = jb + nt * 8;
                if (j0     > t0) sc[nt][0] = -1e30f;
                if (j0 + 1 > t0) sc[nt][1] = -1e30f;
                if (j0     > t1) sc[nt][2] = -1e30f;
                if (j0 + 1 > t1) sc[nt][3] = -1e30f;
            }
        }

        float rm0 = sc[0][0], rm1 = sc[0][2];
#pragma unroll
        for (int nt = 0; nt < 16; nt++) {
            rm0 = fmaxf(rm0, fmaxf(sc[nt][0], sc[nt][1]));
            rm1 = fmaxf(rm1, fmaxf(sc[nt][2], sc[nt][3]));
        }
        rm0 = fmaxf(rm0, __shfl_xor_sync(0xffffffff, rm0, 1));
        rm0 = fmaxf(rm0, __shfl_xor_sync(0xffffffff, rm0, 2));
        rm1 = fmaxf(rm1, __shfl_xor_sync(0xffffffff, rm1, 1));
        rm1 = fmaxf(rm1, __shfl_xor_sync(0xffffffff, rm1, 2));

        const float mn0 = fmaxf(m0, rm0);
        const float mn1 = fmaxf(m1, rm1);
        const float c0 = ex2f(m0 - mn0);
        const float c1 = ex2f(m1 - mn1);
        m0 = mn0; m1 = mn1;
        o[0][0] *= c0; o[0][1] *= c0; o[0][2] *= c1; o[0][3] *= c1;
        o[1][0] *= c0; o[1][1] *= c0; o[1][2] *= c1; o[1][3] *= c1;
        oL[0]   *= c0; oL[1]   *= c0; oL[2]   *= c1; oL[3]   *= c1;

        uint32_t p[16][2];
#pragma unroll
        for (int nt = 0; nt < 16; nt++) {
            p[nt][0] = ex2h2(sc[nt][0] - mn0, sc[nt][1] - mn0);
            p[nt][1] = ex2h2(sc[nt][2] - mn1, sc[nt][3] - mn1);
        }

        {
            const int g = lane >> 3, r = lane & 7;
            const int vrow = (g & 1) * 8 + r;
            const int vcol = (g >> 1) * 8;
#pragma unroll
            for (int kt = 0; kt < 8; kt++) {
                uint32_t pa[4];
                pa[0] = p[2 * kt][0];
                pa[1] = p[2 * kt][1];
                pa[2] = p[2 * kt + 1][0];
                pa[3] = p[2 * kt + 1][1];
                uint32_t v0, v1, v2, v3;
                ldm4t(v0, v1, v2, v3,
                      smem_u32(&Vs[buf][(16 * kt + vrow) * 16 + vcol]));
                uint32_t bl[2] = { v0, v1 };
                uint32_t bh2[2] = { v2, v3 };
                mma16816(o[0], pa, bl);
                mma16816(o[1], pa, bh2);
                mma16816(oL,   pa, onesb);
            }
        }
        __syncthreads();
    }

    const float inv0 = 1.f / oL[0];
    const float inv1 = 1.f / oL[2];

    const int b = bh >> 4, h = bh & 15;
    const int col = (lane & 3) * 2;
#pragma unroll
    for (int vt = 0; vt < 2; vt++) {
        uint32_t lo = packh2(o[vt][0] * inv0, o[vt][1] * inv0);
        uint32_t hi = packh2(o[vt][2] * inv1, o[vt][3] * inv1);
        size_t base0 = ((size_t)(b * S_ + qrow0)     ) * NOV_ + h * 16 + vt * 8 + col;
        size_t base1 = ((size_t)(b * S_ + qrow0 + 8) ) * NOV_ + h * 16 + vt * 8 + col;
        *(uint32_t*)&g_Zh[base0] = lo;
        *(uint32_t*)&g_Zh[base1] = hi;
    }
}

// ---------------------------------------------------------------------------
// Launch
// ---------------------------------------------------------------------------
extern "C" void kernel_launch(void* const* d_in, const int* in_sizes, int n_in,
                              void* d_out, int out_size)
{
    const float* resid = (const float*)d_in[0];
    const float* W_Q   = (const float*)d_in[1];
    const float* W_K   = (const float*)d_in[2];
    const float* W_V   = (const float*)d_in[3];
    const float* W_O   = (const float*)d_in[4];
    const float* b_Q   = (const float*)d_in[5];
    const float* b_K   = (const float*)d_in[6];
    const float* b_V   = (const float*)d_in[7];
    const float* b_O   = (const float*)d_in[8];
    const float* v_k   = (const float*)d_in[9];
    const float* v_v   = (const float*)d_in[10];
    float* out = (float*)d_out;

    __half *Ah, *Wh1, *Wh2, *Zh;
    float *qkv;
    cudaGetSymbolAddress((void**)&Ah,  g_Ah);
    cudaGetSymbolAddress((void**)&Wh1, g_Wh1);
    cudaGetSymbolAddress((void**)&Wh2, g_Wh2);
    cudaGetSymbolAddress((void**)&Zh,  g_Zh);
    cudaGetSymbolAddress((void**)&qkv, g_qkv);

    // 1) fused prep
    prep_kernel<<<PREP_BLKS, 256>>>(W_Q, W_K, W_V, W_O, resid);

    // 2) GEMM1: (4096 x 768) = Ah * Wh1^T -> g_qkv fp32
    {
        dim3 grid(DM_ / 128, BS_ / 64);
        hgemm<<<grid, 256, HG_SMEM_BYTES>>>(Ah, Wh1, qkv, BS_, DM_, DM_, nullptr);
    }

    // 3) fused rotary/V/virtual scatter
    rotv_kernel<<<RV_BLKS, 256>>>(b_Q, b_K, b_V, v_k, v_v);

    // 4) tensor-core flash attention
    {
        dim3 grid(S_ / 128, B_ * NQK_);
        attn_mma<<<grid, 256>>>();
    }

    // 5) GEMM2: (4096 x 768) = Zh * Wh2^T + b_O -> out fp32
    {
        dim3 grid(DM_ / 128, BS_ / 64);
        hgemm<<<grid, 256, HG_SMEM_BYTES>>>(Zh, Wh2, out, BS_, DM_, NOV_, b_O);
    }
}

// round 6
// speedup vs baseline: 5.0159x; 1.0957x over previous
#include <cuda_runtime.h>
#include <cuda_fp16.h>
#include <cstdint>

// ---------------------------------------------------------------------------
// Problem constants
// ---------------------------------------------------------------------------
#define B_   2
#define S_   2048
#define DM_  768
#define NQK_ 16
#define DQK_ 16
#define NOV_ 256
#define VKV_ 16
#define SK_  (S_ + VKV_)     // 2064 keys = 16 + 16*128 (exact!)
#define BS_  (B_ * S_)       // 4096 rows

// ---------------------------------------------------------------------------
// Device scratch
// ---------------------------------------------------------------------------
__device__ __half g_Ah  [BS_ * DM_];
__device__ __half g_Wh1 [DM_ * DM_];
__device__ __half g_Wh2 [DM_ * NOV_];
__device__ float  g_qkv [BS_ * DM_];
__device__ float  g_rot [S_ * 16];                  // [s][0..7]=sin, [8..15]=cos
__device__ __half g_Qh  [B_ * NQK_ * S_  * DQK_];
__device__ __half g_Kh  [B_ * NQK_ * SK_ * DQK_];
__device__ __half g_Vh  [B_ * NQK_ * SK_ * DQK_];
__device__ __half g_Zh  [BS_ * NOV_];

// ---------------------------------------------------------------------------
// helpers
// ---------------------------------------------------------------------------
__device__ __forceinline__ uint32_t smem_u32(const void* p) {
    return (uint32_t)__cvta_generic_to_shared(p);
}
__device__ __forceinline__ void cp16(uint32_t s, const void* g) {
    asm volatile("cp.async.cg.shared.global [%0], [%1], 16;" :: "r"(s), "l"(g));
}
__device__ __forceinline__ float ex2f(float x) {
    float y; asm("ex2.approx.ftz.f32 %0, %1;" : "=f"(y) : "f"(x)); return y;
}
__device__ __forceinline__ uint32_t ex2h2(float lo, float hi) {
    uint32_t h, r;
    asm("cvt.rn.f16x2.f32 %0, %1, %2;" : "=r"(h) : "f"(hi), "f"(lo));
    asm("ex2.approx.f16x2 %0, %1;" : "=r"(r) : "r"(h));
    return r;
}
__device__ __forceinline__ void ldm4(uint32_t& r0, uint32_t& r1, uint32_t& r2, uint32_t& r3, uint32_t addr) {
    asm volatile("ldmatrix.sync.aligned.m8n8.x4.shared.b16 {%0,%1,%2,%3}, [%4];"
                 : "=r"(r0), "=r"(r1), "=r"(r2), "=r"(r3) : "r"(addr));
}
__device__ __forceinline__ void ldm4t(uint32_t& r0, uint32_t& r1, uint32_t& r2, uint32_t& r3, uint32_t addr) {
    asm volatile("ldmatrix.sync.aligned.m8n8.x4.trans.shared.b16 {%0,%1,%2,%3}, [%4];"
                 : "=r"(r0), "=r"(r1), "=r"(r2), "=r"(r3) : "r"(addr));
}
__device__ __forceinline__ void mma16816(float* d, const uint32_t* a, const uint32_t* b) {
    asm volatile("mma.sync.aligned.m16n8k16.row.col.f32.f16.f16.f32 "
                 "{%0,%1,%2,%3},{%4,%5,%6,%7},{%8,%9},{%0,%1,%2,%3};"
                 : "+f"(d[0]), "+f"(d[1]), "+f"(d[2]), "+f"(d[3])
                 : "r"(a[0]), "r"(a[1]), "r"(a[2]), "r"(a[3]), "r"(b[0]), "r"(b[1]));
}
__device__ __forceinline__ uint32_t packh2(float x, float y) {
    __half2 h = __floats2half2_rn(x, y);
    return *(uint32_t*)&h;
}

// ---------------------------------------------------------------------------
// 1) Fused prep: pack W1, pack W2, convert resid, rotary table
// ---------------------------------------------------------------------------
#define PREP_W1_BLKS 2304
#define PREP_W2_BLKS 768
#define PREP_CV_BLKS 3072
#define PREP_RT_BLKS 64
#define PREP_BLKS (PREP_W1_BLKS + PREP_W2_BLKS + PREP_CV_BLKS + PREP_RT_BLKS)

__global__ void prep_kernel(const float* __restrict__ WQ,
                            const float* __restrict__ WK,
                            const float* __restrict__ WV,
                            const float* __restrict__ WO,
                            const float* __restrict__ resid)
{
    const int blk = blockIdx.x;
    if (blk < PREP_W1_BLKS) {
        int idx = blk * 256 + threadIdx.x;
        int c = idx / DM_;
        int d = idx % DM_;
        float v;
        if (c < 256) {
            int h = c >> 4, e = c & 15;
            v = WQ[(h * DM_ + d) * DQK_ + e];
        } else if (c < 512) {
            int cc = c - 256;
            int h = cc >> 4, e = cc & 15;
            v = WK[(h * DM_ + d) * DQK_ + e];
        } else {
            v = WV[(c - 512) * DM_ + d];
        }
        g_Wh1[idx] = __float2half(v);
    } else if (blk < PREP_W1_BLKS + PREP_W2_BLKS) {
        int idx = (blk - PREP_W1_BLKS) * 256 + threadIdx.x;
        int m  = idx >> 8;
        int nv = idx & 255;
        g_Wh2[idx] = __float2half(WO[nv * DM_ + m]);
    } else if (blk < PREP_W1_BLKS + PREP_W2_BLKS + PREP_CV_BLKS) {
        int i = ((blk - PREP_W1_BLKS - PREP_W2_BLKS) * 256 + threadIdx.x) * 4;
        float4 v = *(const float4*)(resid + i);
        *(__half2*)&g_Ah[i]     = __floats2half2_rn(v.x, v.y);
        *(__half2*)&g_Ah[i + 2] = __floats2half2_rn(v.z, v.w);
    } else {
        int idx = (blk - PREP_W1_BLKS - PREP_W2_BLKS - PREP_CV_BLKS) * 256 + threadIdx.x;
        int s = idx >> 3, i = idx & 7;
        float freq = powf(10000.f, (float)i / 8.f);
        float sn, cs;
        sincosf((float)s / freq, &sn, &cs);
        g_rot[s * 16 + i]     = sn;
        g_rot[s * 16 + 8 + i] = cs;
    }
}

// ---------------------------------------------------------------------------
// 2) fp16 tensor-core GEMM: 64x128 tile, 3-stage cp.async (unchanged R5)
// ---------------------------------------------------------------------------
#define BKH 32
#define LDT 40
#define HG_STAGES 3
#define HG_A_HALVES (64  * LDT)
#define HG_B_HALVES (128 * LDT)
#define HG_SMEM_BYTES (HG_STAGES * (HG_A_HALVES + HG_B_HALVES) * 2)

__global__ __launch_bounds__(256)
void hgemm(const __half* __restrict__ A, const __half* __restrict__ Bm,
           float* __restrict__ C, int M, int N, int K,
           const float* __restrict__ bias)
{
    extern __shared__ __half sm[];
    __half* Asm = sm;
    __half* Bsm = sm + HG_STAGES * HG_A_HALVES;

    const int tid  = threadIdx.x;
    const int warp = tid >> 5, lane = tid & 31;
    const int wm = warp >> 2, wn = warp & 3;
    const int bm = blockIdx.y * 64, bn = blockIdx.x * 128;

    const int arow = tid >> 2;
    const int aoff = (tid & 3) * 8;
    const int brow = tid >> 1;
    const int boff = (tid & 1) * 16;

    const __half* Ag = A + (size_t)(bm + arow) * K + aoff;
    const __half* Bg = Bm + (size_t)(bn + brow) * K + boff;
    const uint32_t AsB = smem_u32(Asm);
    const uint32_t BsB = smem_u32(Bsm);
    const uint32_t stA = (uint32_t)(arow * LDT + aoff) * 2;
    const uint32_t stB = (uint32_t)(brow * LDT + boff) * 2;
    const uint32_t SA = HG_A_HALVES * 2;
    const uint32_t SB = HG_B_HALVES * 2;

    const int mat = lane >> 3, r = lane & 7;
    const uint32_t a_off = (uint32_t)((wm * 32 + (mat & 1) * 8 + r) * LDT + (mat >> 1) * 8) * 2;
    const uint32_t b_off = (uint32_t)((wn * 32 + (mat >> 1) * 8 + r) * LDT + (mat & 1) * 8) * 2;

    float acc[2][4][4];
#pragma unroll
    for (int i = 0; i < 2; i++)
#pragma unroll
        for (int j = 0; j < 4; j++)
#pragma unroll
            for (int t = 0; t < 4; t++) acc[i][j][t] = 0.f;

    const int KT = K / BKH;

#pragma unroll
    for (int s = 0; s < 2; s++) {
        cp16(AsB + s * SA + stA,      Ag + s * BKH);
        cp16(BsB + s * SB + stB,      Bg + s * BKH);
        cp16(BsB + s * SB + stB + 16, Bg + s * BKH + 8);
        asm volatile("cp.async.commit_group;");
    }
    asm volatile("cp.async.wait_group 1;" ::: "memory");
    __syncthreads();

    int stage = 0;
    for (int kt = 0; kt < KT; kt++) {
        const uint32_t Abuf = AsB + (uint32_t)stage * SA;
        const uint32_t Bbuf = BsB + (uint32_t)stage * SB;
#pragma unroll
        for (int ks = 0; ks < 2; ks++) {
            uint32_t a[2][4];
#pragma unroll
            for (int mt = 0; mt < 2; mt++)
                ldm4(a[mt][0], a[mt][1], a[mt][2], a[mt][3],
                     Abuf + a_off + (uint32_t)(mt * 16 * LDT + ks * 16) * 2);
            uint32_t bf[4][2];
#pragma unroll
            for (int p = 0; p < 2; p++) {
                uint32_t r0, r1, r2, r3;
                ldm4(r0, r1, r2, r3,
                     Bbuf + b_off + (uint32_t)(p * 16 * LDT + ks * 16) * 2);
                bf[2 * p][0] = r0; bf[2 * p][1] = r1;
                bf[2 * p + 1][0] = r2; bf[2 * p + 1][1] = r3;
            }
#pragma unroll
            for (int mt = 0; mt < 2; mt++)
#pragma unroll
                for (int nt = 0; nt < 4; nt++)
                    mma16816(acc[mt][nt], a[mt], bf[nt]);
        }

        if (kt + 2 < KT) {
            const int ns = (stage + 2 >= HG_STAGES) ? stage + 2 - HG_STAGES : stage + 2;
            const __half* ag = Ag + (kt + 2) * BKH;
            const __half* bg = Bg + (kt + 2) * BKH;
            cp16(AsB + (uint32_t)ns * SA + stA,      ag);
            cp16(BsB + (uint32_t)ns * SB + stB,      bg);
            cp16(BsB + (uint32_t)ns * SB + stB + 16, bg + 8);
            asm volatile("cp.async.commit_group;");
            asm volatile("cp.async.wait_group 1;" ::: "memory");
        } else {
            asm volatile("cp.async.wait_group 0;" ::: "memory");
        }
        __syncthreads();
        stage = (stage + 1 >= HG_STAGES) ? 0 : stage + 1;
    }

#pragma unroll
    for (int mt = 0; mt < 2; mt++) {
        const int r0 = bm + wm * 32 + mt * 16 + (lane >> 2);
#pragma unroll
        for (int nt = 0; nt < 4; nt++) {
            const int c0 = bn + wn * 32 + nt * 8 + (lane & 3) * 2;
            float b0 = 0.f, b1 = 0.f;
            if (bias) { b0 = bias[c0]; b1 = bias[c0 + 1]; }
            float2 v01 = { acc[mt][nt][0] + b0, acc[mt][nt][1] + b1 };
            float2 v23 = { acc[mt][nt][2] + b0, acc[mt][nt][3] + b1 };
            *(float2*)(C + (size_t)r0 * N + c0)       = v01;
            *(float2*)(C + (size_t)(r0 + 8) * N + c0) = v23;
        }
    }
}

// ---------------------------------------------------------------------------
// 3) Fused rotary-scatter Q,K + scatter V + virtual K/V (unchanged R5)
// ---------------------------------------------------------------------------
#define QSCALE 0.36067376022224085f   // 0.25 * log2(e)
#define RV_MAIN_BLKS 256
#define RV_BLKS (RV_MAIN_BLKS + 32)

__global__ void rotv_kernel(const float* __restrict__ bQ,
                            const float* __restrict__ bK,
                            const float* __restrict__ bV,
                            const float* __restrict__ vk,
                            const float* __restrict__ vv)
{
    const int blk = blockIdx.x;
    if (blk < RV_MAIN_BLKS) {
        int idx = blk * 256 + threadIdx.x;
        int h = idx & 15;
        int s = (idx >> 4) & (S_ - 1);
        int b = idx >> 15;

        const float* src = &g_qkv[(size_t)(b * S_ + s) * DM_];
        const float* rt  = &g_rot[s * 16];

        float qv[16], kv[16];
#pragma unroll
        for (int e = 0; e < 16; e++) {
            qv[e] = src[h * 16 + e]       + bQ[h * 16 + e];
            kv[e] = src[256 + h * 16 + e] + bK[h * 16 + e];
        }
        __half qo[16], ko[16];
#pragma unroll
        for (int i = 0; i < 8; i++) {
            float sn = rt[i], cs = rt[8 + i];
            qo[i]     = __float2half((qv[i]     * cs - qv[i + 8] * sn) * QSCALE);
            qo[i + 8] = __float2half((qv[i + 8] * cs + qv[i]     * sn) * QSCALE);
            ko[i]     = __float2half(kv[i]     * cs - kv[i + 8] * sn);
            ko[i + 8] = __float2half(kv[i + 8] * cs + kv[i]     * sn);
        }
        __half* qdst = &g_Qh[((size_t)(b * NQK_ + h) * S_ + s) * DQK_];
        __half* kdst = &g_Kh[((size_t)(b * NQK_ + h) * SK_ + s) * DQK_];
#pragma unroll
        for (int e = 0; e < 16; e++) { qdst[e] = qo[e]; kdst[e] = ko[e]; }

        __half* vdst = &g_Vh[((size_t)(b * NQK_ + h) * SK_ + s) * DQK_];
#pragma unroll
        for (int e = 0; e < 16; e++) {
            int n = h * 16 + e;
            vdst[e] = __float2half(src[512 + n] + bV[n]);
        }
    } else {
        int idx = (blk - RV_MAIN_BLKS) * 256 + threadIdx.x;
        int c = idx & 255;
        int m = (idx >> 8) & 15;
        int b = idx >> 12;
        int h = c >> 4, e = c & 15;
        size_t row = ((size_t)(b * NQK_ + h) * SK_ + S_ + m) * DQK_ + e;
        g_Kh[row] = __float2half(vk[m * 256 + c]);
        g_Vh[row] = __float2half(vv[m * 256 + c]);
    }
}

// ---------------------------------------------------------------------------
// 4) Tensor-core flash attention, shifted tiling:
//    prologue chunk = keys [0,16) unmasked; tile jt covers keys
//    [16+jt*128, 16+(jt+1)*128), jt=0..qt; diag tile (jt==qt) has clean
//    causal mask (local l <= r). 64-key softmax chunks; warp-uniform skip
//    of fully-masked subtiles in the diag tile.
// ---------------------------------------------------------------------------
__global__ __launch_bounds__(256, 3)
void attn_mma()
{
    const int bh   = blockIdx.y;
    const int qt   = (int)(gridDim.x - 1) - (int)blockIdx.x;   // big tiles first
    const int tid  = threadIdx.x;
    const int warp = tid >> 5, lane = tid & 31;

    __shared__ __half Qs[128 * 16];
    __shared__ __half K0s[16 * 16];
    __shared__ __half V0s[16 * 16];
    __shared__ __half Ks[2][128 * 16];
    __shared__ __half Vs[2][128 * 16];

    const __half* Qg = g_Qh + ((size_t)bh * S_ + qt * 128) * DQK_;
    const __half* Kg = g_Kh + (size_t)bh * SK_ * DQK_;
    const __half* Vg = g_Vh + (size_t)bh * SK_ * DQK_;

    const int ld_row = tid >> 1;
    const int ld_off = (tid & 1) * 8;

    // Q tile -> smem (plain vector store)
    *(float4*)&Qs[ld_row * 16 + ld_off] =
        *(const float4*)&Qg[(size_t)ld_row * 16 + ld_off];

    // group0: prologue K0/V0 (keys 0..15)
    if (tid < 32) {
        int pr = tid >> 1, po = (tid & 1) * 8;
        cp16(smem_u32(&K0s[pr * 16 + po]), Kg + (size_t)pr * 16 + po);
        cp16(smem_u32(&V0s[pr * 16 + po]), Vg + (size_t)pr * 16 + po);
    }
    asm volatile("cp.async.commit_group;");
    // group1: tile 0 (keys 16..143)
    cp16(smem_u32(&Ks[0][ld_row * 16 + ld_off]), Kg + (size_t)(16 + ld_row) * 16 + ld_off);
    cp16(smem_u32(&Vs[0][ld_row * 16 + ld_off]), Vg + (size_t)(16 + ld_row) * 16 + ld_off);
    asm volatile("cp.async.commit_group;");

    asm volatile("cp.async.wait_group 1;" ::: "memory");   // group0 done
    __syncthreads();

    // Q fragment (m16k16 row-major)
    uint32_t qa[4];
    const int g = lane >> 3, r = lane & 7;
    {
        int row = warp * 16 + (g & 1) * 8 + r;
        int col = (g >> 1) * 8;
        ldm4(qa[0], qa[1], qa[2], qa[3], smem_u32(&Qs[row * 16 + col]));
    }
    const int krow = (g >> 1) * 8 + r;   // K ldmatrix row pattern
    const int kcol = (g & 1) * 8;
    const int vrow = (g & 1) * 8 + r;    // V ldmatrix (trans) row pattern
    const int vcol = (g >> 1) * 8;

    float m0, m1;
    float o[2][4] = {{0.f,0.f,0.f,0.f},{0.f,0.f,0.f,0.f}};
    float oL[4]   = {0.f,0.f,0.f,0.f};
    const uint32_t onesb[2] = { 0x3C003C00u, 0x3C003C00u };

    // ---- prologue: 16 keys, unmasked, initializes m/o/oL ----
    {
        float sc[2][4] = {{0.f,0.f,0.f,0.f},{0.f,0.f,0.f,0.f}};
        uint32_t b0, b1, b2, b3;
        ldm4(b0, b1, b2, b3, smem_u32(&K0s[krow * 16 + kcol]));
        {
            uint32_t bl[2] = { b0, b1 }, bh2[2] = { b2, b3 };
            mma16816(sc[0], qa, bl);
            mma16816(sc[1], qa, bh2);
        }
        float rm0 = fmaxf(fmaxf(sc[0][0], sc[0][1]), fmaxf(sc[1][0], sc[1][1]));
        float rm1 = fmaxf(fmaxf(sc[0][2], sc[0][3]), fmaxf(sc[1][2], sc[1][3]));
        rm0 = fmaxf(rm0, __shfl_xor_sync(0xffffffff, rm0, 1));
        rm0 = fmaxf(rm0, __shfl_xor_sync(0xffffffff, rm0, 2));
        rm1 = fmaxf(rm1, __shfl_xor_sync(0xffffffff, rm1, 1));
        rm1 = fmaxf(rm1, __shfl_xor_sync(0xffffffff, rm1, 2));
        m0 = rm0; m1 = rm1;

        uint32_t pa[4];
        pa[0] = ex2h2(sc[0][0] - m0, sc[0][1] - m0);
        pa[1] = ex2h2(sc[0][2] - m1, sc[0][3] - m1);
        pa[2] = ex2h2(sc[1][0] - m0, sc[1][1] - m0);
        pa[3] = ex2h2(sc[1][2] - m1, sc[1][3] - m1);

        uint32_t v0, v1, v2, v3;
        ldm4t(v0, v1, v2, v3, smem_u32(&V0s[vrow * 16 + vcol]));
        uint32_t bl[2] = { v0, v1 }, bh2[2] = { v2, v3 };
        mma16816(o[0], pa, bl);
        mma16816(o[1], pa, bh2);
        mma16816(oL,   pa, onesb);
    }

    const int wmax = warp * 16 + 15;     // max local row this warp owns

    // ---- main loop over full tiles jt = 0..qt ----
    for (int jt = 0; jt <= qt; jt++) {
        const int buf = jt & 1;
        if (jt < qt) {
            cp16(smem_u32(&Ks[buf ^ 1][ld_row * 16 + ld_off]),
                 Kg + (size_t)(16 + (jt + 1) * 128 + ld_row) * 16 + ld_off);
            cp16(smem_u32(&Vs[buf ^ 1][ld_row * 16 + ld_off]),
                 Vg + (size_t)(16 + (jt + 1) * 128 + ld_row) * 16 + ld_off);
            asm volatile("cp.async.commit_group;");
            asm volatile("cp.async.wait_group 1;" ::: "memory");
        } else {
            asm volatile("cp.async.wait_group 0;" ::: "memory");
        }
        __syncthreads();

        const bool diag = (jt == qt);

#pragma unroll
        for (int c = 0; c < 2; c++) {
            if (!diag || c * 64 <= wmax) {
                // ---- QK^T for 64 keys ----
                float sc[8][4];
#pragma unroll
                for (int nt = 0; nt < 8; nt++)
#pragma unroll
                    for (int t = 0; t < 4; t++) sc[nt][t] = 0.f;

#pragma unroll
                for (int i = 0; i < 4; i++) {
                    if (!diag || (c * 64 + i * 16) <= wmax) {
                        uint32_t b0, b1, b2, b3;
                        ldm4(b0, b1, b2, b3,
                             smem_u32(&Ks[buf][(16 * (c * 4 + i) + krow) * 16 + kcol]));
                        uint32_t bl[2] = { b0, b1 }, bh2[2] = { b2, b3 };
                        mma16816(sc[2 * i],     qa, bl);
                        mma16816(sc[2 * i + 1], qa, bh2);
                    }
                }

                // ---- causal mask on diag tile: local l <= r ----
                if (diag) {
                    const int jb = c * 64 + (lane & 3) * 2;
                    const int t0 = warp * 16 + (lane >> 2);
                    const int t1 = t0 + 8;
#pragma unroll
                    for (int nt = 0; nt < 8; nt++) {
                        int j0 = jb + nt * 8;
                        if (j0     > t0) sc[nt][0] = -1e30f;
                        if (j0 + 1 > t0) sc[nt][1] = -1e30f;
                        if (j0     > t1) sc[nt][2] = -1e30f;
                        if (j0 + 1 > t1) sc[nt][3] = -1e30f;
                    }
                }

                // ---- online softmax update ----
                float rm0 = sc[0][0], rm1 = sc[0][2];
#pragma unroll
                for (int nt = 0; nt < 8; nt++) {
                    rm0 = fmaxf(rm0, fmaxf(sc[nt][0], sc[nt][1]));
                    rm1 = fmaxf(rm1, fmaxf(sc[nt][2], sc[nt][3]));
                }
                rm0 = fmaxf(rm0, __shfl_xor_sync(0xffffffff, rm0, 1));
                rm0 = fmaxf(rm0, __shfl_xor_sync(0xffffffff, rm0, 2));
                rm1 = fmaxf(rm1, __shfl_xor_sync(0xffffffff, rm1, 1));
                rm1 = fmaxf(rm1, __shfl_xor_sync(0xffffffff, rm1, 2));

                const float mn0 = fmaxf(m0, rm0);
                const float mn1 = fmaxf(m1, rm1);
                const float c0 = ex2f(m0 - mn0);
                const float c1 = ex2f(m1 - mn1);
                m0 = mn0; m1 = mn1;
                o[0][0] *= c0; o[0][1] *= c0; o[0][2] *= c1; o[0][3] *= c1;
                o[1][0] *= c0; o[1][1] *= c0; o[1][2] *= c1; o[1][3] *= c1;
                oL[0]   *= c0; oL[1]   *= c0; oL[2]   *= c1; oL[3]   *= c1;

                uint32_t p[8][2];
#pragma unroll
                for (int nt = 0; nt < 8; nt++) {
                    p[nt][0] = ex2h2(sc[nt][0] - mn0, sc[nt][1] - mn0);
                    p[nt][1] = ex2h2(sc[nt][2] - mn1, sc[nt][3] - mn1);
                }

                // ---- P @ V ----
#pragma unroll
                for (int kt = 0; kt < 4; kt++) {
                    if (!diag || (c * 64 + kt * 16) <= wmax) {
                        uint32_t pa[4];
                        pa[0] = p[2 * kt][0];
                        pa[1] = p[2 * kt][1];
                        pa[2] = p[2 * kt + 1][0];
                        pa[3] = p[2 * kt + 1][1];
                        uint32_t v0, v1, v2, v3;
                        ldm4t(v0, v1, v2, v3,
                              smem_u32(&Vs[buf][(16 * (c * 4 + kt) + vrow) * 16 + vcol]));
                        uint32_t bl[2] = { v0, v1 }, bh2[2] = { v2, v3 };
                        mma16816(o[0], pa, bl);
                        mma16816(o[1], pa, bh2);
                        mma16816(oL,   pa, onesb);
                    }
                }
            }
        }
        __syncthreads();
    }

    // ---- epilogue (row sums in oL, identical across quad lanes) ----
    const float inv0 = 1.f / oL[0];
    const float inv1 = 1.f / oL[2];

    const int qrow0 = qt * 128 + warp * 16 + (lane >> 2);
    const int b = bh >> 4, h = bh & 15;
    const int col = (lane & 3) * 2;
#pragma unroll
    for (int vt = 0; vt < 2; vt++) {
        uint32_t lo = packh2(o[vt][0] * inv0, o[vt][1] * inv0);
        uint32_t hi = packh2(o[vt][2] * inv1, o[vt][3] * inv1);
        size_t base0 = ((size_t)(b * S_ + qrow0)     ) * NOV_ + h * 16 + vt * 8 + col;
        size_t base1 = ((size_t)(b * S_ + qrow0 + 8) ) * NOV_ + h * 16 + vt * 8 + col;
        *(uint32_t*)&g_Zh[base0] = lo;
        *(uint32_t*)&g_Zh[base1] = hi;
    }
}

// ---------------------------------------------------------------------------
// Launch
// ---------------------------------------------------------------------------
extern "C" void kernel_launch(void* const* d_in, const int* in_sizes, int n_in,
                              void* d_out, int out_size)
{
    const float* resid = (const float*)d_in[0];
    const float* W_Q   = (const float*)d_in[1];
    const float* W_K   = (const float*)d_in[2];
    const float* W_V   = (const float*)d_in[3];
    const float* W_O   = (const float*)d_in[4];
    const float* b_Q   = (const float*)d_in[5];
    const float* b_K   = (const float*)d_in[6];
    const float* b_V   = (const float*)d_in[7];
    const float* b_O   = (const float*)d_in[8];
    const float* v_k   = (const float*)d_in[9];
    const float* v_v   = (const float*)d_in[10];
    float* out = (float*)d_out;

    __half *Ah, *Wh1, *Wh2, *Zh;
    float *qkv;
    cudaGetSymbolAddress((void**)&Ah,  g_Ah);
    cudaGetSymbolAddress((void**)&Wh1, g_Wh1);
    cudaGetSymbolAddress((void**)&Wh2, g_Wh2);
    cudaGetSymbolAddress((void**)&Zh,  g_Zh);
    cudaGetSymbolAddress((void**)&qkv, g_qkv);

    // 1) fused prep
    prep_kernel<<<PREP_BLKS, 256>>>(W_Q, W_K, W_V, W_O, resid);

    // 2) GEMM1: (4096 x 768) = Ah * Wh1^T -> g_qkv fp32
    {
        dim3 grid(DM_ / 128, BS_ / 64);
        hgemm<<<grid, 256, HG_SMEM_BYTES>>>(Ah, Wh1, qkv, BS_, DM_, DM_, nullptr);
    }

    // 3) fused rotary/V/virtual scatter
    rotv_kernel<<<RV_BLKS, 256>>>(b_Q, b_K, b_V, v_k, v_v);

    // 4) tensor-core flash attention
    {
        dim3 grid(S_ / 128, B_ * NQK_);
        attn_mma<<<grid, 256>>>();
    }

    // 5) GEMM2: (4096 x 768) = Zh * Wh2^T + b_O -> out fp32
    {
        dim3 grid(DM_ / 128, BS_ / 64);
        hgemm<<<grid, 256, HG_SMEM_BYTES>>>(Zh, Wh2, out, BS_, DM_, NOV_, b_O);
    }
}

// round 7
// speedup vs baseline: 6.6746x; 1.3307x over previous
#include <cuda_runtime.h>
#include <cuda_fp16.h>
#include <cstdint>

// ---------------------------------------------------------------------------
// Problem constants
// ---------------------------------------------------------------------------
#define B_   2
#define S_   2048
#define DM_  768
#define NQK_ 16
#define DQK_ 16
#define NOV_ 256
#define VKV_ 16
#define SK_  (S_ + VKV_)     // 2064 keys = 16 + 16*128 (exact)
#define BS_  (B_ * S_)       // 4096 rows

// ---------------------------------------------------------------------------
// Device scratch
// ---------------------------------------------------------------------------
__device__ __half g_Ah  [BS_ * DM_];
__device__ __half g_Wh1 [DM_ * DM_];
__device__ __half g_Wh2 [DM_ * NOV_];
__device__ float  g_rot [S_ * 16];                  // [s][0..7]=sin, [8..15]=cos
__device__ __half g_Qh  [B_ * NQK_ * S_  * DQK_];
__device__ __half g_Kh  [B_ * NQK_ * SK_ * DQK_];
__device__ __half g_Vh  [B_ * NQK_ * SK_ * DQK_];
__device__ __half g_Zh  [BS_ * NOV_];

// ---------------------------------------------------------------------------
// helpers
// ---------------------------------------------------------------------------
__device__ __forceinline__ uint32_t smem_u32(const void* p) {
    return (uint32_t)__cvta_generic_to_shared(p);
}
__device__ __forceinline__ void cp16(uint32_t s, const void* g) {
    asm volatile("cp.async.cg.shared.global [%0], [%1], 16;" :: "r"(s), "l"(g));
}
__device__ __forceinline__ float ex2f(float x) {
    float y; asm("ex2.approx.ftz.f32 %0, %1;" : "=f"(y) : "f"(x)); return y;
}
__device__ __forceinline__ uint32_t ex2h2(float lo, float hi) {
    uint32_t h, r;
    asm("cvt.rn.f16x2.f32 %0, %1, %2;" : "=r"(h) : "f"(hi), "f"(lo));
    asm("ex2.approx.f16x2 %0, %1;" : "=r"(r) : "r"(h));
    return r;
}
__device__ __forceinline__ void ldm4(uint32_t& r0, uint32_t& r1, uint32_t& r2, uint32_t& r3, uint32_t addr) {
    asm volatile("ldmatrix.sync.aligned.m8n8.x4.shared.b16 {%0,%1,%2,%3}, [%4];"
                 : "=r"(r0), "=r"(r1), "=r"(r2), "=r"(r3) : "r"(addr));
}
__device__ __forceinline__ void ldm4t(uint32_t& r0, uint32_t& r1, uint32_t& r2, uint32_t& r3, uint32_t addr) {
    asm volatile("ldmatrix.sync.aligned.m8n8.x4.trans.shared.b16 {%0,%1,%2,%3}, [%4];"
                 : "=r"(r0), "=r"(r1), "=r"(r2), "=r"(r3) : "r"(addr));
}
__device__ __forceinline__ void mma16816(float* d, const uint32_t* a, const uint32_t* b) {
    asm volatile("mma.sync.aligned.m16n8k16.row.col.f32.f16.f16.f32 "
                 "{%0,%1,%2,%3},{%4,%5,%6,%7},{%8,%9},{%0,%1,%2,%3};"
                 : "+f"(d[0]), "+f"(d[1]), "+f"(d[2]), "+f"(d[3])
                 : "r"(a[0]), "r"(a[1]), "r"(a[2]), "r"(a[3]), "r"(b[0]), "r"(b[1]));
}
__device__ __forceinline__ uint32_t packh2(float x, float y) {
    __half2 h = __floats2half2_rn(x, y);
    return *(uint32_t*)&h;
}

#define QSCALE 0.36067376022224085f   // 0.25 * log2(e)

// ---------------------------------------------------------------------------
// 1) Fused prep:
//    [0,384)      WQ/WK transpose-pack (64x16 smem tiles, coalesced both sides)
//    [384,1152)   WV pack (naturally coalesced)
//    [1152,1344)  WO transpose-pack (16x64 tiles)
//    [1344,4416)  resid -> half
//    [4416,4480)  rotary table
//    [4480,4512)  virtual K/V rows
// ---------------------------------------------------------------------------
#define PREP_TQK0 0
#define PREP_V0   384
#define PREP_W20  1152
#define PREP_CV0  1344
#define PREP_RT0  4416
#define PREP_VV0  4480
#define PREP_BLKS 4512

__global__ void prep_kernel(const float* __restrict__ WQ,
                            const float* __restrict__ WK,
                            const float* __restrict__ WV,
                            const float* __restrict__ WO,
                            const float* __restrict__ resid,
                            const float* __restrict__ vk,
                            const float* __restrict__ vv)
{
    __shared__ float sm[64 * 17];
    const int blk = blockIdx.x;
    const int t = threadIdx.x;

    if (blk < PREP_V0) {
        // WQ/WK transpose: mat (0=Q,1=K), head h, d-tile of 64
        int rem = blk, mat = rem / 192; rem %= 192;
        int h = rem / 12, d0 = (rem % 12) * 64;
        const float* W = mat ? WK : WQ;
        // read 64 d-rows x 16 e, coalesced
        {
            int row = t >> 2, part = t & 3;
            float4 v = *(const float4*)&W[((size_t)h * DM_ + d0 + row) * DQK_ + part * 4];
            sm[row * 17 + part * 4 + 0] = v.x;
            sm[row * 17 + part * 4 + 1] = v.y;
            sm[row * 17 + part * 4 + 2] = v.z;
            sm[row * 17 + part * 4 + 3] = v.w;
        }
        __syncthreads();
        // write 16 e-rows x 64 d, coalesced
        {
            int e = t >> 4, dcol = (t & 15) * 4;
            int c = mat * 256 + h * 16 + e;
            __half* dst = &g_Wh1[(size_t)c * DM_ + d0 + dcol];
            *(__half2*)&dst[0] = __floats2half2_rn(sm[(dcol + 0) * 17 + e], sm[(dcol + 1) * 17 + e]);
            *(__half2*)&dst[2] = __floats2half2_rn(sm[(dcol + 2) * 17 + e], sm[(dcol + 3) * 17 + e]);
        }
    } else if (blk < PREP_W20) {
        int idx = (blk - PREP_V0) * 256 + t;          // < 196608, both sides coalesced
        g_Wh1[512 * DM_ + idx] = __float2half(WV[idx]);
    } else if (blk < PREP_CV0) {
        // WO transpose: Wh2[m][n] <- WO[n][m]
        int rem = blk - PREP_W20;
        int n0 = (rem / 12) * 16, m0 = (rem % 12) * 64;
        {
            int row = t >> 4, part = t & 15;          // 16 n-rows x 64 m
            float4 v = *(const float4*)&WO[(size_t)(n0 + row) * DM_ + m0 + part * 4];
            sm[row * 65 + part * 4 + 0] = v.x;
            sm[row * 65 + part * 4 + 1] = v.y;
            sm[row * 65 + part * 4 + 2] = v.z;
            sm[row * 65 + part * 4 + 3] = v.w;
        }
        __syncthreads();
        {
            int mm = t >> 2, nn = (t & 3) * 4;        // 64 m-rows x 16 n
            __half* dst = &g_Wh2[(size_t)(m0 + mm) * NOV_ + n0 + nn];
            *(__half2*)&dst[0] = __floats2half2_rn(sm[(nn + 0) * 65 + mm], sm[(nn + 1) * 65 + mm]);
            *(__half2*)&dst[2] = __floats2half2_rn(sm[(nn + 2) * 65 + mm], sm[(nn + 3) * 65 + mm]);
        }
    } else if (blk < PREP_RT0) {
        int i = ((blk - PREP_CV0) * 256 + t) * 4;
        float4 v = *(const float4*)(resid + i);
        *(__half2*)&g_Ah[i]     = __floats2half2_rn(v.x, v.y);
        *(__half2*)&g_Ah[i + 2] = __floats2half2_rn(v.z, v.w);
    } else if (blk < PREP_VV0) {
        int idx = (blk - PREP_RT0) * 256 + t;
        int s = idx >> 3, i = idx & 7;
        float freq = powf(10000.f, (float)i / 8.f);
        float sn, cs;
        sincosf((float)s / freq, &sn, &cs);
        g_rot[s * 16 + i]     = sn;
        g_rot[s * 16 + 8 + i] = cs;
    } else {
        int idx = (blk - PREP_VV0) * 256 + t;         // over B*VKV*256 = 8192
        int c = idx & 255;
        int m = (idx >> 8) & 15;
        int b = idx >> 12;
        int h = c >> 4, e = c & 15;
        size_t row = ((size_t)(b * NQK_ + h) * SK_ + S_ + m) * DQK_ + e;
        g_Kh[row] = __float2half(vk[m * 256 + c]);
        g_Vh[row] = __float2half(vv[m * 256 + c]);
    }
}

// ---------------------------------------------------------------------------
// 2) fp16 tensor-core GEMM: 64x128 tile, 3-stage cp.async.
//    MODE 0: C = A*B^T + bias (fp32 out)
//    MODE 1: fused QKV epilogue: bias + rotary + scatter to g_Qh/g_Kh/g_Vh
// ---------------------------------------------------------------------------
#define BKH 32
#define LDT 40
#define HG_STAGES 3
#define HG_A_HALVES (64  * LDT)
#define HG_B_HALVES (128 * LDT)
#define HG_SMEM_BYTES (HG_STAGES * (HG_A_HALVES + HG_B_HALVES) * 2)

template<int MODE>
__global__ __launch_bounds__(256)
void hgemm(const __half* __restrict__ A, const __half* __restrict__ Bm,
           float* __restrict__ C, int M, int N, int K,
           const float* __restrict__ bias,
           const float* __restrict__ bQv,
           const float* __restrict__ bKv,
           const float* __restrict__ bVv)
{
    extern __shared__ __half smh[];
    __half* Asm = smh;
    __half* Bsm = smh + HG_STAGES * HG_A_HALVES;

    const int tid  = threadIdx.x;
    const int warp = tid >> 5, lane = tid & 31;
    const int wm = warp >> 2, wn = warp & 3;
    const int bm = blockIdx.y * 64, bn = blockIdx.x * 128;

    const int arow = tid >> 2;
    const int aoff = (tid & 3) * 8;
    const int brow = tid >> 1;
    const int boff = (tid & 1) * 16;

    const __half* Ag = A + (size_t)(bm + arow) * K + aoff;
    const __half* Bg = Bm + (size_t)(bn + brow) * K + boff;
    const uint32_t AsB = smem_u32(Asm);
    const uint32_t BsB = smem_u32(Bsm);
    const uint32_t stA = (uint32_t)(arow * LDT + aoff) * 2;
    const uint32_t stB = (uint32_t)(brow * LDT + boff) * 2;
    const uint32_t SA = HG_A_HALVES * 2;
    const uint32_t SB = HG_B_HALVES * 2;

    const int mat = lane >> 3, r = lane & 7;
    const uint32_t a_off = (uint32_t)((wm * 32 + (mat & 1) * 8 + r) * LDT + (mat >> 1) * 8) * 2;
    const uint32_t b_off = (uint32_t)((wn * 32 + (mat >> 1) * 8 + r) * LDT + (mat & 1) * 8) * 2;

    float acc[2][4][4];
#pragma unroll
    for (int i = 0; i < 2; i++)
#pragma unroll
        for (int j = 0; j < 4; j++)
#pragma unroll
            for (int tt = 0; tt < 4; tt++) acc[i][j][tt] = 0.f;

    const int KT = K / BKH;

#pragma unroll
    for (int s = 0; s < 2; s++) {
        cp16(AsB + s * SA + stA,      Ag + s * BKH);
        cp16(BsB + s * SB + stB,      Bg + s * BKH);
        cp16(BsB + s * SB + stB + 16, Bg + s * BKH + 8);
        asm volatile("cp.async.commit_group;");
    }
    asm volatile("cp.async.wait_group 1;" ::: "memory");
    __syncthreads();

    int stage = 0;
    for (int kt = 0; kt < KT; kt++) {
        const uint32_t Abuf = AsB + (uint32_t)stage * SA;
        const uint32_t Bbuf = BsB + (uint32_t)stage * SB;
#pragma unroll
        for (int ks = 0; ks < 2; ks++) {
            uint32_t a[2][4];
#pragma unroll
            for (int mt = 0; mt < 2; mt++)
                ldm4(a[mt][0], a[mt][1], a[mt][2], a[mt][3],
                     Abuf + a_off + (uint32_t)(mt * 16 * LDT + ks * 16) * 2);
            uint32_t bf[4][2];
#pragma unroll
            for (int p = 0; p < 2; p++) {
                uint32_t r0, r1, r2, r3;
                ldm4(r0, r1, r2, r3,
                     Bbuf + b_off + (uint32_t)(p * 16 * LDT + ks * 16) * 2);
                bf[2 * p][0] = r0; bf[2 * p][1] = r1;
                bf[2 * p + 1][0] = r2; bf[2 * p + 1][1] = r3;
            }
#pragma unroll
            for (int mt = 0; mt < 2; mt++)
#pragma unroll
                for (int nt = 0; nt < 4; nt++)
                    mma16816(acc[mt][nt], a[mt], bf[nt]);
        }

        if (kt + 2 < KT) {
            const int ns = (stage + 2 >= HG_STAGES) ? stage + 2 - HG_STAGES : stage + 2;
            const __half* ag = Ag + (kt + 2) * BKH;
            const __half* bg = Bg + (kt + 2) * BKH;
            cp16(AsB + (uint32_t)ns * SA + stA,      ag);
            cp16(BsB + (uint32_t)ns * SB + stB,      bg);
            cp16(BsB + (uint32_t)ns * SB + stB + 16, bg + 8);
            asm volatile("cp.async.commit_group;");
            asm volatile("cp.async.wait_group 1;" ::: "memory");
        } else {
            asm volatile("cp.async.wait_group 0;" ::: "memory");
        }
        __syncthreads();
        stage = (stage + 1 >= HG_STAGES) ? 0 : stage + 1;
    }

    if (MODE == 0) {
#pragma unroll
        for (int mt = 0; mt < 2; mt++) {
            const int r0 = bm + wm * 32 + mt * 16 + (lane >> 2);
#pragma unroll
            for (int nt = 0; nt < 4; nt++) {
                const int c0 = bn + wn * 32 + nt * 8 + (lane & 3) * 2;
                float b0 = bias[c0], b1 = bias[c0 + 1];
                float2 v01 = { acc[mt][nt][0] + b0, acc[mt][nt][1] + b1 };
                float2 v23 = { acc[mt][nt][2] + b0, acc[mt][nt][3] + b1 };
                *(float2*)(C + (size_t)r0 * N + c0)       = v01;
                *(float2*)(C + (size_t)(r0 + 8) * N + c0) = v23;
            }
        }
    } else {
        // Fused QKV epilogue: columns [0,256) Q, [256,512) K, [512,768) V.
        // Rotary partners e and e+8 live in nt pairs (2np, 2np+1) of this thread.
        const int i = (lane & 3) * 2;
#pragma unroll
        for (int mt = 0; mt < 2; mt++) {
            const int r0 = bm + wm * 32 + mt * 16 + (lane >> 2);
#pragma unroll
            for (int rr = 0; rr < 2; rr++) {
                const int row = r0 + rr * 8;
                const int s = row & (S_ - 1);
                const int b = row >> 11;
                const float* rt = &g_rot[s * 16];
#pragma unroll
                for (int np = 0; np < 2; np++) {
                    const int base = bn + wn * 32 + np * 16;   // multiple of 16
                    const float vlo0 = acc[mt][2 * np][2 * rr + 0];
                    const float vlo1 = acc[mt][2 * np][2 * rr + 1];
                    const float vhi0 = acc[mt][2 * np + 1][2 * rr + 0];
                    const float vhi1 = acc[mt][2 * np + 1][2 * rr + 1];
                    if (base < 256) {
                        const int h = base >> 4;
                        float a0 = vlo0 + bQv[h * 16 + i];
                        float a1 = vlo1 + bQv[h * 16 + i + 1];
                        float c0 = vhi0 + bQv[h * 16 + i + 8];
                        float c1 = vhi1 + bQv[h * 16 + i + 9];
                        float sn0 = rt[i], sn1 = rt[i + 1];
                        float cs0 = rt[8 + i], cs1 = rt[9 + i];
                        __half* dst = &g_Qh[((size_t)(b * NQK_ + h) * S_ + s) * DQK_];
                        *(__half2*)&dst[i]     = __floats2half2_rn((a0 * cs0 - c0 * sn0) * QSCALE,
                                                                   (a1 * cs1 - c1 * sn1) * QSCALE);
                        *(__half2*)&dst[i + 8] = __floats2half2_rn((c0 * cs0 + a0 * sn0) * QSCALE,
                                                                   (c1 * cs1 + a1 * sn1) * QSCALE);
                    } else if (base < 512) {
                        const int h = (base - 256) >> 4;
                        float a0 = vlo0 + bKv[h * 16 + i];
                        float a1 = vlo1 + bKv[h * 16 + i + 1];
                        float c0 = vhi0 + bKv[h * 16 + i + 8];
                        float c1 = vhi1 + bKv[h * 16 + i + 9];
                        float sn0 = rt[i], sn1 = rt[i + 1];
                        float cs0 = rt[8 + i], cs1 = rt[9 + i];
                        __half* dst = &g_Kh[((size_t)(b * NQK_ + h) * SK_ + s) * DQK_];
                        *(__half2*)&dst[i]     = __floats2half2_rn(a0 * cs0 - c0 * sn0,
                                                                   a1 * cs1 - c1 * sn1);
                        *(__half2*)&dst[i + 8] = __floats2half2_rn(c0 * cs0 + a0 * sn0,
                                                                   c1 * cs1 + a1 * sn1);
                    } else {
                        const int n0 = base - 512;
                        const int h = n0 >> 4;
                        __half* dst = &g_Vh[((size_t)(b * NQK_ + h) * SK_ + s) * DQK_];
                        *(__half2*)&dst[i]     = __floats2half2_rn(vlo0 + bVv[n0 + i],
                                                                   vlo1 + bVv[n0 + i + 1]);
                        *(__half2*)&dst[i + 8] = __floats2half2_rn(vhi0 + bVv[n0 + i + 8],
                                                                   vhi1 + bVv[n0 + i + 9]);
                    }
                }
            }
        }
    }
}

// ---------------------------------------------------------------------------
// 3) Tensor-core flash attention; smem rows padded to 24 halves (48B) so
//    ldmatrix 8-row accesses are bank-conflict-free.
// ---------------------------------------------------------------------------
#define PAD 24

__global__ __launch_bounds__(256, 3)
void attn_mma()
{
    const int bh   = blockIdx.y;
    const int qt   = (int)(gridDim.x - 1) - (int)blockIdx.x;   // big tiles first
    const int tid  = threadIdx.x;
    const int warp = tid >> 5, lane = tid & 31;

    __shared__ __half Qs[128 * PAD];
    __shared__ __half K0s[16 * PAD];
    __shared__ __half V0s[16 * PAD];
    __shared__ __half Ks[2][128 * PAD];
    __shared__ __half Vs[2][128 * PAD];

    const __half* Qg = g_Qh + ((size_t)bh * S_ + qt * 128) * DQK_;
    const __half* Kg = g_Kh + (size_t)bh * SK_ * DQK_;
    const __half* Vg = g_Vh + (size_t)bh * SK_ * DQK_;

    const int ld_row = tid >> 1;
    const int ld_off = (tid & 1) * 8;

    *(float4*)&Qs[ld_row * PAD + ld_off] =
        *(const float4*)&Qg[(size_t)ld_row * 16 + ld_off];

    if (tid < 32) {
        int pr = tid >> 1, po = (tid & 1) * 8;
        cp16(smem_u32(&K0s[pr * PAD + po]), Kg + (size_t)pr * 16 + po);
        cp16(smem_u32(&V0s[pr * PAD + po]), Vg + (size_t)pr * 16 + po);
    }
    asm volatile("cp.async.commit_group;");
    cp16(smem_u32(&Ks[0][ld_row * PAD + ld_off]), Kg + (size_t)(16 + ld_row) * 16 + ld_off);
    cp16(smem_u32(&Vs[0][ld_row * PAD + ld_off]), Vg + (size_t)(16 + ld_row) * 16 + ld_off);
    asm volatile("cp.async.commit_group;");

    asm volatile("cp.async.wait_group 1;" ::: "memory");
    __syncthreads();

    uint32_t qa[4];
    const int g = lane >> 3, r = lane & 7;
    {
        int row = warp * 16 + (g & 1) * 8 + r;
        int col = (g >> 1) * 8;
        ldm4(qa[0], qa[1], qa[2], qa[3], smem_u32(&Qs[row * PAD + col]));
    }
    const int krow = (g >> 1) * 8 + r;
    const int kcol = (g & 1) * 8;
    const int vrow = (g & 1) * 8 + r;
    const int vcol = (g >> 1) * 8;

    float m0, m1;
    float o[2][4] = {{0.f,0.f,0.f,0.f},{0.f,0.f,0.f,0.f}};
    float oL[4]   = {0.f,0.f,0.f,0.f};
    const uint32_t onesb[2] = { 0x3C003C00u, 0x3C003C00u };

    // ---- prologue: 16 keys, unmasked ----
    {
        float sc[2][4] = {{0.f,0.f,0.f,0.f},{0.f,0.f,0.f,0.f}};
        uint32_t b0, b1, b2, b3;
        ldm4(b0, b1, b2, b3, smem_u32(&K0s[krow * PAD + kcol]));
        {
            uint32_t bl[2] = { b0, b1 }, bh2[2] = { b2, b3 };
            mma16816(sc[0], qa, bl);
            mma16816(sc[1], qa, bh2);
        }
        float rm0 = fmaxf(fmaxf(sc[0][0], sc[0][1]), fmaxf(sc[1][0], sc[1][1]));
        float rm1 = fmaxf(fmaxf(sc[0][2], sc[0][3]), fmaxf(sc[1][2], sc[1][3]));
        rm0 = fmaxf(rm0, __shfl_xor_sync(0xffffffff, rm0, 1));
        rm0 = fmaxf(rm0, __shfl_xor_sync(0xffffffff, rm0, 2));
        rm1 = fmaxf(rm1, __shfl_xor_sync(0xffffffff, rm1, 1));
        rm1 = fmaxf(rm1, __shfl_xor_sync(0xffffffff, rm1, 2));
        m0 = rm0; m1 = rm1;

        uint32_t pa[4];
        pa[0] = ex2h2(sc[0][0] - m0, sc[0][1] - m0);
        pa[1] = ex2h2(sc[0][2] - m1, sc[0][3] - m1);
        pa[2] = ex2h2(sc[1][0] - m0, sc[1][1] - m0);
        pa[3] = ex2h2(sc[1][2] - m1, sc[1][3] - m1);

        uint32_t v0, v1, v2, v3;
        ldm4t(v0, v1, v2, v3, smem_u32(&V0s[vrow * PAD + vcol]));
        uint32_t bl[2] = { v0, v1 }, bh2[2] = { v2, v3 };
        mma16816(o[0], pa, bl);
        mma16816(o[1], pa, bh2);
        mma16816(oL,   pa, onesb);
    }

    const int wmax = warp * 16 + 15;

    for (int jt = 0; jt <= qt; jt++) {
        const int buf = jt & 1;
        if (jt < qt) {
            cp16(smem_u32(&Ks[buf ^ 1][ld_row * PAD + ld_off]),
                 Kg + (size_t)(16 + (jt + 1) * 128 + ld_row) * 16 + ld_off);
            cp16(smem_u32(&Vs[buf ^ 1][ld_row * PAD + ld_off]),
                 Vg + (size_t)(16 + (jt + 1) * 128 + ld_row) * 16 + ld_off);
            asm volatile("cp.async.commit_group;");
            asm volatile("cp.async.wait_group 1;" ::: "memory");
        } else {
            asm volatile("cp.async.wait_group 0;" ::: "memory");
        }
        __syncthreads();

        const bool diag = (jt == qt);

#pragma unroll
        for (int c = 0; c < 2; c++) {
            if (!diag || c * 64 <= wmax) {
                float sc[8][4];
#pragma unroll
                for (int nt = 0; nt < 8; nt++)
#pragma unroll
                    for (int tt = 0; tt < 4; tt++) sc[nt][tt] = 0.f;

#pragma unroll
                for (int i = 0; i < 4; i++) {
                    if (!diag || (c * 64 + i * 16) <= wmax) {
                        uint32_t b0, b1, b2, b3;
                        ldm4(b0, b1, b2, b3,
                             smem_u32(&Ks[buf][(16 * (c * 4 + i) + krow) * PAD + kcol]));
                        uint32_t bl[2] = { b0, b1 }, bh2[2] = { b2, b3 };
                        mma16816(sc[2 * i],     qa, bl);
                        mma16816(sc[2 * i + 1], qa, bh2);
                    }
                }

                if (diag) {
                    const int jb = c * 64 + (lane & 3) * 2;
                    const int t0 = warp * 16 + (lane >> 2);
                    const int t1 = t0 + 8;
#pragma unroll
                    for (int nt = 0; nt < 8; nt++) {
                        int j0 = jb + nt * 8;
                        if (j0     > t0) sc[nt][0] = -1e30f;
                        if (j0 + 1 > t0) sc[nt][1] = -1e30f;
                        if (j0     > t1) sc[nt][2] = -1e30f;
                        if (j0 + 1 > t1) sc[nt][3] = -1e30f;
                    }
                }

                float rm0 = sc[0][0], rm1 = sc[0][2];
#pragma unroll
                for (int nt = 0; nt < 8; nt++) {
                    rm0 = fmaxf(rm0, fmaxf(sc[nt][0], sc[nt][1]));
                    rm1 = fmaxf(rm1, fmaxf(sc[nt][2], sc[nt][3]));
                }
                rm0 = fmaxf(rm0, __shfl_xor_sync(0xffffffff, rm0, 1));
                rm0 = fmaxf(rm0, __shfl_xor_sync(0xffffffff, rm0, 2));
                rm1 = fmaxf(rm1, __shfl_xor_sync(0xffffffff, rm1, 1));
                rm1 = fmaxf(rm1, __shfl_xor_sync(0xffffffff, rm1, 2));

                const float mn0 = fmaxf(m0, rm0);
                const float mn1 = fmaxf(m1, rm1);
                const float c0 = ex2f(m0 - mn0);
                const float c1 = ex2f(m1 - mn1);
                m0 = mn0; m1 = mn1;
                o[0][0] *= c0; o[0][1] *= c0; o[0][2] *= c1; o[0][3] *= c1;
                o[1][0] *= c0; o[1][1] *= c0; o[1][2] *= c1; o[1][3] *= c1;
                oL[0]   *= c0; oL[1]   *= c0; oL[2]   *= c1; oL[3]   *= c1;

                uint32_t p[8][2];
#pragma unroll
                for (int nt = 0; nt < 8; nt++) {
                    p[nt][0] = ex2h2(sc[nt][0] - mn0, sc[nt][1] - mn0);
                    p[nt][1] = ex2h2(sc[nt][2] - mn1, sc[nt][3] - mn1);
                }

#pragma unroll
                for (int kt = 0; kt < 4; kt++) {
                    if (!diag || (c * 64 + kt * 16) <= wmax) {
                        uint32_t pa[4];
                        pa[0] = p[2 * kt][0];
                        pa[1] = p[2 * kt][1];
                        pa[2] = p[2 * kt + 1][0];
                        pa[3] = p[2 * kt + 1][1];
                        uint32_t v0, v1, v2, v3;
                        ldm4t(v0, v1, v2, v3,
                              smem_u32(&Vs[buf][(16 * (c * 4 + kt) + vrow) * PAD + vcol]));
                        uint32_t bl[2] = { v0, v1 }, bh2[2] = { v2, v3 };
                        mma16816(o[0], pa, bl);
                        mma16816(o[1], pa, bh2);
                        mma16816(oL,   pa, onesb);
                    }
                }
            }
        }
        __syncthreads();
    }

    const float inv0 = 1.f / oL[0];
    const float inv1 = 1.f / oL[2];

    const int qrow0 = qt * 128 + warp * 16 + (lane >> 2);
    const int b = bh >> 4, h = bh & 15;
    const int col = (lane & 3) * 2;
#pragma unroll
    for (int vt = 0; vt < 2; vt++) {
        uint32_t lo = packh2(o[vt][0] * inv0, o[vt][1] * inv0);
        uint32_t hi = packh2(o[vt][2] * inv1, o[vt][3] * inv1);
        size_t base0 = ((size_t)(b * S_ + qrow0)     ) * NOV_ + h * 16 + vt * 8 + col;
        size_t base1 = ((size_t)(b * S_ + qrow0 + 8) ) * NOV_ + h * 16 + vt * 8 + col;
        *(uint32_t*)&g_Zh[base0] = lo;
        *(uint32_t*)&g_Zh[base1] = hi;
    }
}

// ---------------------------------------------------------------------------
// Launch
// ---------------------------------------------------------------------------
extern "C" void kernel_launch(void* const* d_in, const int* in_sizes, int n_in,
                              void* d_out, int out_size)
{
    const float* resid = (const float*)d_in[0];
    const float* W_Q   = (const float*)d_in[1];
    const float* W_K   = (const float*)d_in[2];
    const float* W_V   = (const float*)d_in[3];
    const float* W_O   = (const float*)d_in[4];
    const float* b_Q   = (const float*)d_in[5];
    const float* b_K   = (const float*)d_in[6];
    const float* b_V   = (const float*)d_in[7];
    const float* b_O   = (const float*)d_in[8];
    const float* v_k   = (const float*)d_in[9];
    const float* v_v   = (const float*)d_in[10];
    float* out = (float*)d_out;

    __half *Ah, *Wh1, *Wh2, *Zh;
    cudaGetSymbolAddress((void**)&Ah,  g_Ah);
    cudaGetSymbolAddress((void**)&Wh1, g_Wh1);
    cudaGetSymbolAddress((void**)&Wh2, g_Wh2);
    cudaGetSymbolAddress((void**)&Zh,  g_Zh);

    cudaFuncSetAttribute(hgemm<0>, cudaFuncAttributeMaxDynamicSharedMemorySize, HG_SMEM_BYTES);
    cudaFuncSetAttribute(hgemm<1>, cudaFuncAttributeMaxDynamicSharedMemorySize, HG_SMEM_BYTES);

    // 1) fused prep (weights, resid, rotary table, virtual KV)
    prep_kernel<<<PREP_BLKS, 256>>>(W_Q, W_K, W_V, W_O, resid, v_k, v_v);

    // 2) GEMM1 + fused bias/rotary/scatter epilogue -> g_Qh/g_Kh/g_Vh
    {
        dim3 grid(DM_ / 128, BS_ / 64);
        hgemm<1><<<grid, 256, HG_SMEM_BYTES>>>(Ah, Wh1, nullptr, BS_, DM_, DM_,
                                               nullptr, b_Q, b_K, b_V);
    }

    // 3) tensor-core flash attention
    {
        dim3 grid(S_ / 128, B_ * NQK_);
        attn_mma<<<grid, 256>>>();
    }

    // 4) GEMM2: (4096 x 768) = Zh * Wh2^T + b_O -> out fp32
    {
        dim3 grid(DM_ / 128, BS_ / 64);
        hgemm<0><<<grid, 256, HG_SMEM_BYTES>>>(Zh, Wh2, out, BS_, DM_, NOV_,
                                               b_O, nullptr, nullptr, nullptr);
    }
}

// round 8
// speedup vs baseline: 6.9931x; 1.0477x over previous
#include <cuda_runtime.h>
#include <cuda_fp16.h>
#include <cstdint>

// ---------------------------------------------------------------------------
// Problem constants
// ---------------------------------------------------------------------------
#define B_   2
#define S_   2048
#define DM_  768
#define NQK_ 16
#define DQK_ 16
#define NOV_ 256
#define VKV_ 16
#define SK_  (S_ + VKV_)     // 2064 keys = 16 + 16*128 (exact)
#define BS_  (B_ * S_)       // 4096 rows

// ---------------------------------------------------------------------------
// Device scratch
// ---------------------------------------------------------------------------
__device__ __half g_Ah  [BS_ * DM_];
__device__ __half g_Wh1 [DM_ * DM_];
__device__ __half g_Wh2 [DM_ * NOV_];
__device__ float  g_rot [S_ * 16];                  // [s][0..7]=sin, [8..15]=cos
__device__ __half g_Qh  [B_ * NQK_ * S_  * DQK_];
__device__ __half g_Kh  [B_ * NQK_ * SK_ * DQK_];
__device__ __half g_Vh  [B_ * NQK_ * SK_ * DQK_];
__device__ __half g_Zh  [BS_ * NOV_];

// ---------------------------------------------------------------------------
// helpers
// ---------------------------------------------------------------------------
__device__ __forceinline__ uint32_t smem_u32(const void* p) {
    return (uint32_t)__cvta_generic_to_shared(p);
}
__device__ __forceinline__ void cp16(uint32_t s, const void* g) {
    asm volatile("cp.async.cg.shared.global [%0], [%1], 16;" :: "r"(s), "l"(g));
}
__device__ __forceinline__ float ex2f(float x) {
    float y; asm("ex2.approx.ftz.f32 %0, %1;" : "=f"(y) : "f"(x)); return y;
}
__device__ __forceinline__ uint32_t ex2h2(float lo, float hi) {
    uint32_t h, r;
    asm("cvt.rn.f16x2.f32 %0, %1, %2;" : "=r"(h) : "f"(hi), "f"(lo));
    asm("ex2.approx.f16x2 %0, %1;" : "=r"(r) : "r"(h));
    return r;
}
__device__ __forceinline__ void ldm4(uint32_t& r0, uint32_t& r1, uint32_t& r2, uint32_t& r3, uint32_t addr) {
    asm volatile("ldmatrix.sync.aligned.m8n8.x4.shared.b16 {%0,%1,%2,%3}, [%4];"
                 : "=r"(r0), "=r"(r1), "=r"(r2), "=r"(r3) : "r"(addr));
}
__device__ __forceinline__ void ldm4t(uint32_t& r0, uint32_t& r1, uint32_t& r2, uint32_t& r3, uint32_t addr) {
    asm volatile("ldmatrix.sync.aligned.m8n8.x4.trans.shared.b16 {%0,%1,%2,%3}, [%4];"
                 : "=r"(r0), "=r"(r1), "=r"(r2), "=r"(r3) : "r"(addr));
}
__device__ __forceinline__ void mma16816(float* d, const uint32_t* a, const uint32_t* b) {
    asm volatile("mma.sync.aligned.m16n8k16.row.col.f32.f16.f16.f32 "
                 "{%0,%1,%2,%3},{%4,%5,%6,%7},{%8,%9},{%0,%1,%2,%3};"
                 : "+f"(d[0]), "+f"(d[1]), "+f"(d[2]), "+f"(d[3])
                 : "r"(a[0]), "r"(a[1]), "r"(a[2]), "r"(a[3]), "r"(b[0]), "r"(b[1]));
}
__device__ __forceinline__ uint32_t packh2(float x, float y) {
    __half2 h = __floats2half2_rn(x, y);
    return *(uint32_t*)&h;
}

#define QSCALE 0.36067376022224085f   // 0.25 * log2(e)

// ---------------------------------------------------------------------------
// 1) Fused prep (unchanged from R7)
// ---------------------------------------------------------------------------
#define PREP_TQK0 0
#define PREP_V0   384
#define PREP_W20  1152
#define PREP_CV0  1344
#define PREP_RT0  4416
#define PREP_VV0  4480
#define PREP_BLKS 4512

__global__ void prep_kernel(const float* __restrict__ WQ,
                            const float* __restrict__ WK,
                            const float* __restrict__ WV,
                            const float* __restrict__ WO,
                            const float* __restrict__ resid,
                            const float* __restrict__ vk,
                            const float* __restrict__ vv)
{
    __shared__ float sm[64 * 17];
    const int blk = blockIdx.x;
    const int t = threadIdx.x;

    if (blk < PREP_V0) {
        int rem = blk, mat = rem / 192; rem %= 192;
        int h = rem / 12, d0 = (rem % 12) * 64;
        const float* W = mat ? WK : WQ;
        {
            int row = t >> 2, part = t & 3;
            float4 v = *(const float4*)&W[((size_t)h * DM_ + d0 + row) * DQK_ + part * 4];
            sm[row * 17 + part * 4 + 0] = v.x;
            sm[row * 17 + part * 4 + 1] = v.y;
            sm[row * 17 + part * 4 + 2] = v.z;
            sm[row * 17 + part * 4 + 3] = v.w;
        }
        __syncthreads();
        {
            int e = t >> 4, dcol = (t & 15) * 4;
            int c = mat * 256 + h * 16 + e;
            __half* dst = &g_Wh1[(size_t)c * DM_ + d0 + dcol];
            *(__half2*)&dst[0] = __floats2half2_rn(sm[(dcol + 0) * 17 + e], sm[(dcol + 1) * 17 + e]);
            *(__half2*)&dst[2] = __floats2half2_rn(sm[(dcol + 2) * 17 + e], sm[(dcol + 3) * 17 + e]);
        }
    } else if (blk < PREP_W20) {
        int idx = (blk - PREP_V0) * 256 + t;
        g_Wh1[512 * DM_ + idx] = __float2half(WV[idx]);
    } else if (blk < PREP_CV0) {
        int rem = blk - PREP_W20;
        int n0 = (rem / 12) * 16, m0 = (rem % 12) * 64;
        {
            int row = t >> 4, part = t & 15;
            float4 v = *(const float4*)&WO[(size_t)(n0 + row) * DM_ + m0 + part * 4];
            sm[row * 65 + part * 4 + 0] = v.x;
            sm[row * 65 + part * 4 + 1] = v.y;
            sm[row * 65 + part * 4 + 2] = v.z;
            sm[row * 65 + part * 4 + 3] = v.w;
        }
        __syncthreads();
        {
            int mm = t >> 2, nn = (t & 3) * 4;
            __half* dst = &g_Wh2[(size_t)(m0 + mm) * NOV_ + n0 + nn];
            *(__half2*)&dst[0] = __floats2half2_rn(sm[(nn + 0) * 65 + mm], sm[(nn + 1) * 65 + mm]);
            *(__half2*)&dst[2] = __floats2half2_rn(sm[(nn + 2) * 65 + mm], sm[(nn + 3) * 65 + mm]);
        }
    } else if (blk < PREP_RT0) {
        int i = ((blk - PREP_CV0) * 256 + t) * 4;
        float4 v = *(const float4*)(resid + i);
        *(__half2*)&g_Ah[i]     = __floats2half2_rn(v.x, v.y);
        *(__half2*)&g_Ah[i + 2] = __floats2half2_rn(v.z, v.w);
    } else if (blk < PREP_VV0) {
        int idx = (blk - PREP_RT0) * 256 + t;
        int s = idx >> 3, i = idx & 7;
        float freq = powf(10000.f, (float)i / 8.f);
        float sn, cs;
        sincosf((float)s / freq, &sn, &cs);
        g_rot[s * 16 + i]     = sn;
        g_rot[s * 16 + 8 + i] = cs;
    } else {
        int idx = (blk - PREP_VV0) * 256 + t;
        int c = idx & 255;
        int m = (idx >> 8) & 15;
        int b = idx >> 12;
        int h = c >> 4, e = c & 15;
        size_t row = ((size_t)(b * NQK_ + h) * SK_ + S_ + m) * DQK_ + e;
        g_Kh[row] = __float2half(vk[m * 256 + c]);
        g_Vh[row] = __float2half(vv[m * 256 + c]);
    }
}

// ---------------------------------------------------------------------------
// 2) fp16 tensor-core GEMM: 64x128 tile, 4-stage cp.async pipeline.
//    MODE 0: C = A*B^T + bias; MODE 1: fused QKV bias/rotary/scatter epilogue
// ---------------------------------------------------------------------------
#define BKH 32
#define LDT 40
#define HG_STAGES 4
#define HG_A_HALVES (64  * LDT)
#define HG_B_HALVES (128 * LDT)
#define HG_SMEM_BYTES (HG_STAGES * (HG_A_HALVES + HG_B_HALVES) * 2)   // 61440

template<int MODE>
__global__ __launch_bounds__(256)
void hgemm(const __half* __restrict__ A, const __half* __restrict__ Bm,
           float* __restrict__ C, int M, int N, int K,
           const float* __restrict__ bias,
           const float* __restrict__ bQv,
           const float* __restrict__ bKv,
           const float* __restrict__ bVv)
{
    extern __shared__ __half smh[];
    __half* Asm = smh;
    __half* Bsm = smh + HG_STAGES * HG_A_HALVES;

    const int tid  = threadIdx.x;
    const int warp = tid >> 5, lane = tid & 31;
    const int wm = warp >> 2, wn = warp & 3;
    const int bm = blockIdx.y * 64, bn = blockIdx.x * 128;

    const int arow = tid >> 2;
    const int aoff = (tid & 3) * 8;
    const int brow = tid >> 1;
    const int boff = (tid & 1) * 16;

    const __half* Ag = A + (size_t)(bm + arow) * K + aoff;
    const __half* Bg = Bm + (size_t)(bn + brow) * K + boff;
    const uint32_t AsB = smem_u32(Asm);
    const uint32_t BsB = smem_u32(Bsm);
    const uint32_t stA = (uint32_t)(arow * LDT + aoff) * 2;
    const uint32_t stB = (uint32_t)(brow * LDT + boff) * 2;
    const uint32_t SA = HG_A_HALVES * 2;
    const uint32_t SB = HG_B_HALVES * 2;

    const int mat = lane >> 3, r = lane & 7;
    const uint32_t a_off = (uint32_t)((wm * 32 + (mat & 1) * 8 + r) * LDT + (mat >> 1) * 8) * 2;
    const uint32_t b_off = (uint32_t)((wn * 32 + (mat >> 1) * 8 + r) * LDT + (mat & 1) * 8) * 2;

    float acc[2][4][4];
#pragma unroll
    for (int i = 0; i < 2; i++)
#pragma unroll
        for (int j = 0; j < 4; j++)
#pragma unroll
            for (int tt = 0; tt < 4; tt++) acc[i][j][tt] = 0.f;

    const int KT = K / BKH;

#pragma unroll
    for (int s = 0; s < 3; s++) {
        cp16(AsB + s * SA + stA,      Ag + s * BKH);
        cp16(BsB + s * SB + stB,      Bg + s * BKH);
        cp16(BsB + s * SB + stB + 16, Bg + s * BKH + 8);
        asm volatile("cp.async.commit_group;");
    }
    asm volatile("cp.async.wait_group 2;" ::: "memory");
    __syncthreads();

    int stage = 0;
    for (int kt = 0; kt < KT; kt++) {
        const uint32_t Abuf = AsB + (uint32_t)stage * SA;
        const uint32_t Bbuf = BsB + (uint32_t)stage * SB;
#pragma unroll
        for (int ks = 0; ks < 2; ks++) {
            uint32_t a[2][4];
#pragma unroll
            for (int mt = 0; mt < 2; mt++)
                ldm4(a[mt][0], a[mt][1], a[mt][2], a[mt][3],
                     Abuf + a_off + (uint32_t)(mt * 16 * LDT + ks * 16) * 2);
            uint32_t bf[4][2];
#pragma unroll
            for (int p = 0; p < 2; p++) {
                uint32_t r0, r1, r2, r3;
                ldm4(r0, r1, r2, r3,
                     Bbuf + b_off + (uint32_t)(p * 16 * LDT + ks * 16) * 2);
                bf[2 * p][0] = r0; bf[2 * p][1] = r1;
                bf[2 * p + 1][0] = r2; bf[2 * p + 1][1] = r3;
            }
#pragma unroll
            for (int mt = 0; mt < 2; mt++)
#pragma unroll
                for (int nt = 0; nt < 4; nt++)
                    mma16816(acc[mt][nt], a[mt], bf[nt]);
        }

        if (kt + 3 < KT) {
            const int ns = (stage + 3 >= HG_STAGES) ? stage + 3 - HG_STAGES : stage + 3;
            const __half* ag = Ag + (kt + 3) * BKH;
            const __half* bg = Bg + (kt + 3) * BKH;
            cp16(AsB + (uint32_t)ns * SA + stA,      ag);
            cp16(BsB + (uint32_t)ns * SB + stB,      bg);
            cp16(BsB + (uint32_t)ns * SB + stB + 16, bg + 8);
            asm volatile("cp.async.commit_group;");
            asm volatile("cp.async.wait_group 2;" ::: "memory");
        } else {
            asm volatile("cp.async.wait_group 0;" ::: "memory");
        }
        __syncthreads();
        stage = (stage + 1 >= HG_STAGES) ? 0 : stage + 1;
    }

    if (MODE == 0) {
#pragma unroll
        for (int mt = 0; mt < 2; mt++) {
            const int r0 = bm + wm * 32 + mt * 16 + (lane >> 2);
#pragma unroll
            for (int nt = 0; nt < 4; nt++) {
                const int c0 = bn + wn * 32 + nt * 8 + (lane & 3) * 2;
                float b0 = bias[c0], b1 = bias[c0 + 1];
                float2 v01 = { acc[mt][nt][0] + b0, acc[mt][nt][1] + b1 };
                float2 v23 = { acc[mt][nt][2] + b0, acc[mt][nt][3] + b1 };
                *(float2*)(C + (size_t)r0 * N + c0)       = v01;
                *(float2*)(C + (size_t)(r0 + 8) * N + c0) = v23;
            }
        }
    } else {
        const int i = (lane & 3) * 2;
#pragma unroll
        for (int mt = 0; mt < 2; mt++) {
            const int r0 = bm + wm * 32 + mt * 16 + (lane >> 2);
#pragma unroll
            for (int rr = 0; rr < 2; rr++) {
                const int row = r0 + rr * 8;
                const int s = row & (S_ - 1);
                const int b = row >> 11;
                const float* rt = &g_rot[s * 16];
#pragma unroll
                for (int np = 0; np < 2; np++) {
                    const int base = bn + wn * 32 + np * 16;
                    const float vlo0 = acc[mt][2 * np][2 * rr + 0];
                    const float vlo1 = acc[mt][2 * np][2 * rr + 1];
                    const float vhi0 = acc[mt][2 * np + 1][2 * rr + 0];
                    const float vhi1 = acc[mt][2 * np + 1][2 * rr + 1];
                    if (base < 256) {
                        const int h = base >> 4;
                        float a0 = vlo0 + bQv[h * 16 + i];
                        float a1 = vlo1 + bQv[h * 16 + i + 1];
                        float c0 = vhi0 + bQv[h * 16 + i + 8];
                        float c1 = vhi1 + bQv[h * 16 + i + 9];
                        float sn0 = rt[i], sn1 = rt[i + 1];
                        float cs0 = rt[8 + i], cs1 = rt[9 + i];
                        __half* dst = &g_Qh[((size_t)(b * NQK_ + h) * S_ + s) * DQK_];
                        *(__half2*)&dst[i]     = __floats2half2_rn((a0 * cs0 - c0 * sn0) * QSCALE,
                                                                   (a1 * cs1 - c1 * sn1) * QSCALE);
                        *(__half2*)&dst[i + 8] = __floats2half2_rn((c0 * cs0 + a0 * sn0) * QSCALE,
                                                                   (c1 * cs1 + a1 * sn1) * QSCALE);
                    } else if (base < 512) {
                        const int h = (base - 256) >> 4;
                        float a0 = vlo0 + bKv[h * 16 + i];
                        float a1 = vlo1 + bKv[h * 16 + i + 1];
                        float c0 = vhi0 + bKv[h * 16 + i + 8];
                        float c1 = vhi1 + bKv[h * 16 + i + 9];
                        float sn0 = rt[i], sn1 = rt[i + 1];
                        float cs0 = rt[8 + i], cs1 = rt[9 + i];
                        __half* dst = &g_Kh[((size_t)(b * NQK_ + h) * SK_ + s) * DQK_];
                        *(__half2*)&dst[i]     = __floats2half2_rn(a0 * cs0 - c0 * sn0,
                                                                   a1 * cs1 - c1 * sn1);
                        *(__half2*)&dst[i + 8] = __floats2half2_rn(c0 * cs0 + a0 * sn0,
                                                                   c1 * cs1 + a1 * sn1);
                    } else {
                        const int n0 = base - 512;
                        const int h = n0 >> 4;
                        __half* dst = &g_Vh[((size_t)(b * NQK_ + h) * SK_ + s) * DQK_];
                        *(__half2*)&dst[i]     = __floats2half2_rn(vlo0 + bVv[n0 + i],
                                                                   vlo1 + bVv[n0 + i + 1]);
                        *(__half2*)&dst[i + 8] = __floats2half2_rn(vhi0 + bVv[n0 + i + 8],
                                                                   vhi1 + bVv[n0 + i + 9]);
                    }
                }
            }
        }
    }
}

// ---------------------------------------------------------------------------
// 3) Tensor-core flash attention: 64-query CTAs, 4 warps (128 threads).
//    Shifted tiling: prologue keys [0,16); tile j covers [16+128j, 16+128j+16*8).
//    Only the LAST tile (j==jmax) is partial; off = 64*qt - 128*jmax in {0,64}.
// ---------------------------------------------------------------------------
#define PAD 24

__global__ __launch_bounds__(128, 6)
void attn_mma()
{
    const int bh   = blockIdx.y;
    const int qt   = (int)(gridDim.x - 1) - (int)blockIdx.x;   // big tiles first
    const int tid  = threadIdx.x;
    const int warp = tid >> 5, lane = tid & 31;
    const int q0   = qt * 64;

    __shared__ __half Qs[64 * PAD];
    __shared__ __half K0s[16 * PAD];
    __shared__ __half V0s[16 * PAD];
    __shared__ __half Ks[2][128 * PAD];
    __shared__ __half Vs[2][128 * PAD];

    const __half* Qg = g_Qh + ((size_t)bh * S_ + q0) * DQK_;
    const __half* Kg = g_Kh + (size_t)bh * SK_ * DQK_;
    const __half* Vg = g_Vh + (size_t)bh * SK_ * DQK_;

    const int ld_row = tid >> 1;          // 0..63
    const int ld_off = (tid & 1) * 8;

    // Q tile (64 rows) -> smem
    *(float4*)&Qs[ld_row * PAD + ld_off] =
        *(const float4*)&Qg[(size_t)ld_row * 16 + ld_off];

    // group0: prologue K0/V0 (keys 0..15)
    if (tid < 32) {
        int pr = tid >> 1, po = (tid & 1) * 8;
        cp16(smem_u32(&K0s[pr * PAD + po]), Kg + (size_t)pr * 16 + po);
        cp16(smem_u32(&V0s[pr * PAD + po]), Vg + (size_t)pr * 16 + po);
    }
    asm volatile("cp.async.commit_group;");
    // group1: tile 0 (keys 16..143); each thread loads 2 rows for K and V
    cp16(smem_u32(&Ks[0][ld_row * PAD + ld_off]),        Kg + (size_t)(16 + ld_row) * 16 + ld_off);
    cp16(smem_u32(&Ks[0][(ld_row + 64) * PAD + ld_off]), Kg + (size_t)(80 + ld_row) * 16 + ld_off);
    cp16(smem_u32(&Vs[0][ld_row * PAD + ld_off]),        Vg + (size_t)(16 + ld_row) * 16 + ld_off);
    cp16(smem_u32(&Vs[0][(ld_row + 64) * PAD + ld_off]), Vg + (size_t)(80 + ld_row) * 16 + ld_off);
    asm volatile("cp.async.commit_group;");

    asm volatile("cp.async.wait_group 1;" ::: "memory");
    __syncthreads();

    uint32_t qa[4];
    const int g = lane >> 3, r = lane & 7;
    {
        int row = warp * 16 + (g & 1) * 8 + r;       // < 64
        int col = (g >> 1) * 8;
        ldm4(qa[0], qa[1], qa[2], qa[3], smem_u32(&Qs[row * PAD + col]));
    }
    const int krow = (g >> 1) * 8 + r;
    const int kcol = (g & 1) * 8;
    const int vrow = (g & 1) * 8 + r;
    const int vcol = (g >> 1) * 8;

    float m0, m1;
    float o[2][4] = {{0.f,0.f,0.f,0.f},{0.f,0.f,0.f,0.f}};
    float oL[4]   = {0.f,0.f,0.f,0.f};
    const uint32_t onesb[2] = { 0x3C003C00u, 0x3C003C00u };

    // ---- prologue: 16 keys, unmasked ----
    {
        float sc[2][4] = {{0.f,0.f,0.f,0.f},{0.f,0.f,0.f,0.f}};
        uint32_t b0, b1, b2, b3;
        ldm4(b0, b1, b2, b3, smem_u32(&K0s[krow * PAD + kcol]));
        {
            uint32_t bl[2] = { b0, b1 }, bh2[2] = { b2, b3 };
            mma16816(sc[0], qa, bl);
            mma16816(sc[1], qa, bh2);
        }
        float rm0 = fmaxf(fmaxf(sc[0][0], sc[0][1]), fmaxf(sc[1][0], sc[1][1]));
        float rm1 = fmaxf(fmaxf(sc[0][2], sc[0][3]), fmaxf(sc[1][2], sc[1][3]));
        rm0 = fmaxf(rm0, __shfl_xor_sync(0xffffffff, rm0, 1));
        rm0 = fmaxf(rm0, __shfl_xor_sync(0xffffffff, rm0, 2));
        rm1 = fmaxf(rm1, __shfl_xor_sync(0xffffffff, rm1, 1));
        rm1 = fmaxf(rm1, __shfl_xor_sync(0xffffffff, rm1, 2));
        m0 = rm0; m1 = rm1;

        uint32_t pa[4];
        pa[0] = ex2h2(sc[0][0] - m0, sc[0][1] - m0);
        pa[1] = ex2h2(sc[0][2] - m1, sc[0][3] - m1);
        pa[2] = ex2h2(sc[1][0] - m0, sc[1][1] - m0);
        pa[3] = ex2h2(sc[1][2] - m1, sc[1][3] - m1);

        uint32_t v0, v1, v2, v3;
        ldm4t(v0, v1, v2, v3, smem_u32(&V0s[vrow * PAD + vcol]));
        uint32_t bl[2] = { v0, v1 }, bh2[2] = { v2, v3 };
        mma16816(o[0], pa, bl);
        mma16816(o[1], pa, bh2);
        mma16816(oL,   pa, onesb);
    }

    const int jmax = (q0 + 63) >> 7;       // last (and only partial) tile index

    for (int jt = 0; jt <= jmax; jt++) {
        const int buf = jt & 1;
        if (jt < jmax) {
            const size_t kb = (size_t)(16 + (jt + 1) * 128);
            cp16(smem_u32(&Ks[buf ^ 1][ld_row * PAD + ld_off]),        Kg + (kb + ld_row) * 16 + ld_off);
            cp16(smem_u32(&Ks[buf ^ 1][(ld_row + 64) * PAD + ld_off]), Kg + (kb + ld_row + 64) * 16 + ld_off);
            cp16(smem_u32(&Vs[buf ^ 1][ld_row * PAD + ld_off]),        Vg + (kb + ld_row) * 16 + ld_off);
            cp16(smem_u32(&Vs[buf ^ 1][(ld_row + 64) * PAD + ld_off]), Vg + (kb + ld_row + 64) * 16 + ld_off);
            asm volatile("cp.async.commit_group;");
            asm volatile("cp.async.wait_group 1;" ::: "memory");
        } else {
            asm volatile("cp.async.wait_group 0;" ::: "memory");
        }
        __syncthreads();

        const bool diag = (jt == jmax);
        const int off   = q0 - 128 * jt;               // >= 112 means fully live
        const int wb    = off + warp * 16 + 15;        // max live key col for this warp

#pragma unroll
        for (int c = 0; c < 2; c++) {
            if (!diag || c * 64 <= wb) {
                float sc[8][4];
#pragma unroll
                for (int nt = 0; nt < 8; nt++)
#pragma unroll
                    for (int tt = 0; tt < 4; tt++) sc[nt][tt] = 0.f;

#pragma unroll
                for (int i = 0; i < 4; i++) {
                    if (!diag || (c * 64 + i * 16) <= wb) {
                        uint32_t b0, b1, b2, b3;
                        ldm4(b0, b1, b2, b3,
                             smem_u32(&Ks[buf][(16 * (c * 4 + i) + krow) * PAD + kcol]));
                        uint32_t bl[2] = { b0, b1 }, bh2[2] = { b2, b3 };
                        mma16816(sc[2 * i],     qa, bl);
                        mma16816(sc[2 * i + 1], qa, bh2);
                    }
                }

                if (diag) {
                    const int jb = c * 64 + (lane & 3) * 2;
                    const int t0 = off + warp * 16 + (lane >> 2);
                    const int t1 = t0 + 8;
#pragma unroll
                    for (int nt = 0; nt < 8; nt++) {
                        int j0 = jb + nt * 8;
                        if (j0     > t0) sc[nt][0] = -1e30f;
                        if (j0 + 1 > t0) sc[nt][1] = -1e30f;
                        if (j0     > t1) sc[nt][2] = -1e30f;
                        if (j0 + 1 > t1) sc[nt][3] = -1e30f;
                    }
                }

                float rm0 = sc[0][0], rm1 = sc[0][2];
#pragma unroll
                for (int nt = 0; nt < 8; nt++) {
                    rm0 = fmaxf(rm0, fmaxf(sc[nt][0], sc[nt][1]));
                    rm1 = fmaxf(rm1, fmaxf(sc[nt][2], sc[nt][3]));
                }
                rm0 = fmaxf(rm0, __shfl_xor_sync(0xffffffff, rm0, 1));
                rm0 = fmaxf(rm0, __shfl_xor_sync(0xffffffff, rm0, 2));
                rm1 = fmaxf(rm1, __shfl_xor_sync(0xffffffff, rm1, 1));
                rm1 = fmaxf(rm1, __shfl_xor_sync(0xffffffff, rm1, 2));

                const float mn0 = fmaxf(m0, rm0);
                const float mn1 = fmaxf(m1, rm1);
                const float c0 = ex2f(m0 - mn0);
                const float c1 = ex2f(m1 - mn1);
                m0 = mn0; m1 = mn1;
                o[0][0] *= c0; o[0][1] *= c0; o[0][2] *= c1; o[0][3] *= c1;
                o[1][0] *= c0; o[1][1] *= c0; o[1][2] *= c1; o[1][3] *= c1;
                oL[0]   *= c0; oL[1]   *= c0; oL[2]   *= c1; oL[3]   *= c1;

                uint32_t p[8][2];
#pragma unroll
                for (int nt = 0; nt < 8; nt++) {
                    p[nt][0] = ex2h2(sc[nt][0] - mn0, sc[nt][1] - mn0);
                    p[nt][1] = ex2h2(sc[nt][2] - mn1, sc[nt][3] - mn1);
                }

#pragma unroll
                for (int kt = 0; kt < 4; kt++) {
                    if (!diag || (c * 64 + kt * 16) <= wb) {
                        uint32_t pa[4];
                        pa[0] = p[2 * kt][0];
                        pa[1] = p[2 * kt][1];
                        pa[2] = p[2 * kt + 1][0];
                        pa[3] = p[2 * kt + 1][1];
                        uint32_t v0, v1, v2, v3;
                        ldm4t(v0, v1, v2, v3,
                              smem_u32(&Vs[buf][(16 * (c * 4 + kt) + vrow) * PAD + vcol]));
                        uint32_t bl[2] = { v0, v1 }, bh2[2] = { v2, v3 };
                        mma16816(o[0], pa, bl);
                        mma16816(o[1], pa, bh2);
                        mma16816(oL,   pa, onesb);
                    }
                }
            }
        }
        __syncthreads();
    }

    const float inv0 = 1.f / oL[0];
    const float inv1 = 1.f / oL[2];

    const int qrow0 = q0 + warp * 16 + (lane >> 2);
    const int b = bh >> 4, h = bh & 15;
    const int col = (lane & 3) * 2;
#pragma unroll
    for (int vt = 0; vt < 2; vt++) {
        uint32_t lo = packh2(o[vt][0] * inv0, o[vt][1] * inv0);
        uint32_t hi = packh2(o[vt][2] * inv1, o[vt][3] * inv1);
        size_t base0 = ((size_t)(b * S_ + qrow0)     ) * NOV_ + h * 16 + vt * 8 + col;
        size_t base1 = ((size_t)(b * S_ + qrow0 + 8) ) * NOV_ + h * 16 + vt * 8 + col;
        *(uint32_t*)&g_Zh[base0] = lo;
        *(uint32_t*)&g_Zh[base1] = hi;
    }
}

// ---------------------------------------------------------------------------
// Launch
// ---------------------------------------------------------------------------
extern "C" void kernel_launch(void* const* d_in, const int* in_sizes, int n_in,
                              void* d_out, int out_size)
{
    const float* resid = (const float*)d_in[0];
    const float* W_Q   = (const float*)d_in[1];
    const float* W_K   = (const float*)d_in[2];
    const float* W_V   = (const float*)d_in[3];
    const float* W_O   = (const float*)d_in[4];
    const float* b_Q   = (const float*)d_in[5];
    const float* b_K   = (const float*)d_in[6];
    const float* b_V   = (const float*)d_in[7];
    const float* b_O   = (const float*)d_in[8];
    const float* v_k   = (const float*)d_in[9];
    const float* v_v   = (const float*)d_in[10];
    float* out = (float*)d_out;

    __half *Ah, *Wh1, *Wh2, *Zh;
    cudaGetSymbolAddress((void**)&Ah,  g_Ah);
    cudaGetSymbolAddress((void**)&Wh1, g_Wh1);
    cudaGetSymbolAddress((void**)&Wh2, g_Wh2);
    cudaGetSymbolAddress((void**)&Zh,  g_Zh);

    cudaFuncSetAttribute(hgemm<0>, cudaFuncAttributeMaxDynamicSharedMemorySize, HG_SMEM_BYTES);
    cudaFuncSetAttribute(hgemm<1>, cudaFuncAttributeMaxDynamicSharedMemorySize, HG_SMEM_BYTES);

    // 1) fused prep
    prep_kernel<<<PREP_BLKS, 256>>>(W_Q, W_K, W_V, W_O, resid, v_k, v_v);

    // 2) GEMM1 + fused bias/rotary/scatter epilogue -> g_Qh/g_Kh/g_Vh
    {
        dim3 grid(DM_ / 128, BS_ / 64);
        hgemm<1><<<grid, 256, HG_SMEM_BYTES>>>(Ah, Wh1, nullptr, BS_, DM_, DM_,
                                               nullptr, b_Q, b_K, b_V);
    }

    // 3) tensor-core flash attention (64-query CTAs)
    {
        dim3 grid(S_ / 64, B_ * NQK_);
        attn_mma<<<grid, 128>>>();
    }

    // 4) GEMM2: (4096 x 768) = Zh * Wh2^T + b_O -> out fp32
    {
        dim3 grid(DM_ / 128, BS_ / 64);
        hgemm<0><<<grid, 256, HG_SMEM_BYTES>>>(Zh, Wh2, out, BS_, DM_, NOV_,
                                               b_O, nullptr, nullptr, nullptr);
    }
}

// round 9
// speedup vs baseline: 7.1716x; 1.0255x over previous
#include <cuda_runtime.h>
#include <cuda_fp16.h>
#include <cstdint>

// ---------------------------------------------------------------------------
// Problem constants
// ---------------------------------------------------------------------------
#define B_   2
#define S_   2048
#define DM_  768
#define NQK_ 16
#define DQK_ 16
#define NOV_ 256
#define VKV_ 16
#define SK_  (S_ + VKV_)     // 2064 keys = 16 + 16*128 (exact)
#define BS_  (B_ * S_)       // 4096 rows

// ---------------------------------------------------------------------------
// Device scratch
// ---------------------------------------------------------------------------
__device__ __half g_Ah  [BS_ * DM_];
__device__ __half g_Wh1 [DM_ * DM_];
__device__ __half g_Wh2 [DM_ * NOV_];
__device__ float  g_rot [S_ * 16];                  // [s][0..7]=sin, [8..15]=cos
__device__ __half g_Qh  [B_ * NQK_ * S_  * DQK_];
__device__ __half g_Kh  [B_ * NQK_ * SK_ * DQK_];
__device__ __half g_Vh  [B_ * NQK_ * SK_ * DQK_];
__device__ __half g_Zh  [BS_ * NOV_];

// ---------------------------------------------------------------------------
// helpers
// ---------------------------------------------------------------------------
__device__ __forceinline__ uint32_t smem_u32(const void* p) {
    return (uint32_t)__cvta_generic_to_shared(p);
}
__device__ __forceinline__ void cp16(uint32_t s, const void* g) {
    asm volatile("cp.async.cg.shared.global [%0], [%1], 16;" :: "r"(s), "l"(g));
}
__device__ __forceinline__ float ex2f(float x) {
    float y; asm("ex2.approx.ftz.f32 %0, %1;" : "=f"(y) : "f"(x)); return y;
}
__device__ __forceinline__ uint32_t ex2h2(float lo, float hi) {
    uint32_t h, r;
    asm("cvt.rn.f16x2.f32 %0, %1, %2;" : "=r"(h) : "f"(hi), "f"(lo));
    asm("ex2.approx.f16x2 %0, %1;" : "=r"(r) : "r"(h));
    return r;
}
__device__ __forceinline__ void ldm4(uint32_t& r0, uint32_t& r1, uint32_t& r2, uint32_t& r3, uint32_t addr) {
    asm volatile("ldmatrix.sync.aligned.m8n8.x4.shared.b16 {%0,%1,%2,%3}, [%4];"
                 : "=r"(r0), "=r"(r1), "=r"(r2), "=r"(r3) : "r"(addr));
}
__device__ __forceinline__ void ldm4t(uint32_t& r0, uint32_t& r1, uint32_t& r2, uint32_t& r3, uint32_t addr) {
    asm volatile("ldmatrix.sync.aligned.m8n8.x4.trans.shared.b16 {%0,%1,%2,%3}, [%4];"
                 : "=r"(r0), "=r"(r1), "=r"(r2), "=r"(r3) : "r"(addr));
}
__device__ __forceinline__ void mma16816(float* d, const uint32_t* a, const uint32_t* b) {
    asm volatile("mma.sync.aligned.m16n8k16.row.col.f32.f16.f16.f32 "
                 "{%0,%1,%2,%3},{%4,%5,%6,%7},{%8,%9},{%0,%1,%2,%3};"
                 : "+f"(d[0]), "+f"(d[1]), "+f"(d[2]), "+f"(d[3])
                 : "r"(a[0]), "r"(a[1]), "r"(a[2]), "r"(a[3]), "r"(b[0]), "r"(b[1]));
}
__device__ __forceinline__ uint32_t packh2(float x, float y) {
    __half2 h = __floats2half2_rn(x, y);
    return *(uint32_t*)&h;
}

#define QSCALE 0.36067376022224085f   // 0.25 * log2(e)

// ---------------------------------------------------------------------------
// 1) Fused prep (unchanged)
// ---------------------------------------------------------------------------
#define PREP_TQK0 0
#define PREP_V0   384
#define PREP_W20  1152
#define PREP_CV0  1344
#define PREP_RT0  4416
#define PREP_VV0  4480
#define PREP_BLKS 4512

__global__ void prep_kernel(const float* __restrict__ WQ,
                            const float* __restrict__ WK,
                            const float* __restrict__ WV,
                            const float* __restrict__ WO,
                            const float* __restrict__ resid,
                            const float* __restrict__ vk,
                            const float* __restrict__ vv)
{
    __shared__ float sm[64 * 17];
    const int blk = blockIdx.x;
    const int t = threadIdx.x;

    if (blk < PREP_V0) {
        int rem = blk, mat = rem / 192; rem %= 192;
        int h = rem / 12, d0 = (rem % 12) * 64;
        const float* W = mat ? WK : WQ;
        {
            int row = t >> 2, part = t & 3;
            float4 v = *(const float4*)&W[((size_t)h * DM_ + d0 + row) * DQK_ + part * 4];
            sm[row * 17 + part * 4 + 0] = v.x;
            sm[row * 17 + part * 4 + 1] = v.y;
            sm[row * 17 + part * 4 + 2] = v.z;
            sm[row * 17 + part * 4 + 3] = v.w;
        }
        __syncthreads();
        {
            int e = t >> 4, dcol = (t & 15) * 4;
            int c = mat * 256 + h * 16 + e;
            __half* dst = &g_Wh1[(size_t)c * DM_ + d0 + dcol];
            *(__half2*)&dst[0] = __floats2half2_rn(sm[(dcol + 0) * 17 + e], sm[(dcol + 1) * 17 + e]);
            *(__half2*)&dst[2] = __floats2half2_rn(sm[(dcol + 2) * 17 + e], sm[(dcol + 3) * 17 + e]);
        }
    } else if (blk < PREP_W20) {
        int idx = (blk - PREP_V0) * 256 + t;
        g_Wh1[512 * DM_ + idx] = __float2half(WV[idx]);
    } else if (blk < PREP_CV0) {
        int rem = blk - PREP_W20;
        int n0 = (rem / 12) * 16, m0 = (rem % 12) * 64;
        {
            int row = t >> 4, part = t & 15;
            float4 v = *(const float4*)&WO[(size_t)(n0 + row) * DM_ + m0 + part * 4];
            sm[row * 65 + part * 4 + 0] = v.x;
            sm[row * 65 + part * 4 + 1] = v.y;
            sm[row * 65 + part * 4 + 2] = v.z;
            sm[row * 65 + part * 4 + 3] = v.w;
        }
        __syncthreads();
        {
            int mm = t >> 2, nn = (t & 3) * 4;
            __half* dst = &g_Wh2[(size_t)(m0 + mm) * NOV_ + n0 + nn];
            *(__half2*)&dst[0] = __floats2half2_rn(sm[(nn + 0) * 65 + mm], sm[(nn + 1) * 65 + mm]);
            *(__half2*)&dst[2] = __floats2half2_rn(sm[(nn + 2) * 65 + mm], sm[(nn + 3) * 65 + mm]);
        }
    } else if (blk < PREP_RT0) {
        int i = ((blk - PREP_CV0) * 256 + t) * 4;
        float4 v = *(const float4*)(resid + i);
        *(__half2*)&g_Ah[i]     = __floats2half2_rn(v.x, v.y);
        *(__half2*)&g_Ah[i + 2] = __floats2half2_rn(v.z, v.w);
    } else if (blk < PREP_VV0) {
        int idx = (blk - PREP_RT0) * 256 + t;
        int s = idx >> 3, i = idx & 7;
        float freq = powf(10000.f, (float)i / 8.f);
        float sn, cs;
        sincosf((float)s / freq, &sn, &cs);
        g_rot[s * 16 + i]     = sn;
        g_rot[s * 16 + 8 + i] = cs;
    } else {
        int idx = (blk - PREP_VV0) * 256 + t;
        int c = idx & 255;
        int m = (idx >> 8) & 15;
        int b = idx >> 12;
        int h = c >> 4, e = c & 15;
        size_t row = ((size_t)(b * NQK_ + h) * SK_ + S_ + m) * DQK_ + e;
        g_Kh[row] = __float2half(vk[m * 256 + c]);
        g_Vh[row] = __float2half(vv[m * 256 + c]);
    }
}

// ---------------------------------------------------------------------------
// 2) fp16 tensor-core GEMM (unchanged from R8)
// ---------------------------------------------------------------------------
#define BKH 32
#define LDT 40
#define HG_STAGES 4
#define HG_A_HALVES (64  * LDT)
#define HG_B_HALVES (128 * LDT)
#define HG_SMEM_BYTES (HG_STAGES * (HG_A_HALVES + HG_B_HALVES) * 2)

template<int MODE>
__global__ __launch_bounds__(256)
void hgemm(const __half* __restrict__ A, const __half* __restrict__ Bm,
           float* __restrict__ C, int M, int N, int K,
           const float* __restrict__ bias,
           const float* __restrict__ bQv,
           const float* __restrict__ bKv,
           const float* __restrict__ bVv)
{
    extern __shared__ __half smh[];
    __half* Asm = smh;
    __half* Bsm = smh + HG_STAGES * HG_A_HALVES;

    const int tid  = threadIdx.x;
    const int warp = tid >> 5, lane = tid & 31;
    const int wm = warp >> 2, wn = warp & 3;
    const int bm = blockIdx.y * 64, bn = blockIdx.x * 128;

    const int arow = tid >> 2;
    const int aoff = (tid & 3) * 8;
    const int brow = tid >> 1;
    const int boff = (tid & 1) * 16;

    const __half* Ag = A + (size_t)(bm + arow) * K + aoff;
    const __half* Bg = Bm + (size_t)(bn + brow) * K + boff;
    const uint32_t AsB = smem_u32(Asm);
    const uint32_t BsB = smem_u32(Bsm);
    const uint32_t stA = (uint32_t)(arow * LDT + aoff) * 2;
    const uint32_t stB = (uint32_t)(brow * LDT + boff) * 2;
    const uint32_t SA = HG_A_HALVES * 2;
    const uint32_t SB = HG_B_HALVES * 2;

    const int mat = lane >> 3, r = lane & 7;
    const uint32_t a_off = (uint32_t)((wm * 32 + (mat & 1) * 8 + r) * LDT + (mat >> 1) * 8) * 2;
    const uint32_t b_off = (uint32_t)((wn * 32 + (mat >> 1) * 8 + r) * LDT + (mat & 1) * 8) * 2;

    float acc[2][4][4];
#pragma unroll
    for (int i = 0; i < 2; i++)
#pragma unroll
        for (int j = 0; j < 4; j++)
#pragma unroll
            for (int tt = 0; tt < 4; tt++) acc[i][j][tt] = 0.f;

    const int KT = K / BKH;

#pragma unroll
    for (int s = 0; s < 3; s++) {
        cp16(AsB + s * SA + stA,      Ag + s * BKH);
        cp16(BsB + s * SB + stB,      Bg + s * BKH);
        cp16(BsB + s * SB + stB + 16, Bg + s * BKH + 8);
        asm volatile("cp.async.commit_group;");
    }
    asm volatile("cp.async.wait_group 2;" ::: "memory");
    __syncthreads();

    int stage = 0;
    for (int kt = 0; kt < KT; kt++) {
        const uint32_t Abuf = AsB + (uint32_t)stage * SA;
        const uint32_t Bbuf = BsB + (uint32_t)stage * SB;
#pragma unroll
        for (int ks = 0; ks < 2; ks++) {
            uint32_t a[2][4];
#pragma unroll
            for (int mt = 0; mt < 2; mt++)
                ldm4(a[mt][0], a[mt][1], a[mt][2], a[mt][3],
                     Abuf + a_off + (uint32_t)(mt * 16 * LDT + ks * 16) * 2);
            uint32_t bf[4][2];
#pragma unroll
            for (int p = 0; p < 2; p++) {
                uint32_t r0, r1, r2, r3;
                ldm4(r0, r1, r2, r3,
                     Bbuf + b_off + (uint32_t)(p * 16 * LDT + ks * 16) * 2);
                bf[2 * p][0] = r0; bf[2 * p][1] = r1;
                bf[2 * p + 1][0] = r2; bf[2 * p + 1][1] = r3;
            }
#pragma unroll
            for (int mt = 0; mt < 2; mt++)
#pragma unroll
                for (int nt = 0; nt < 4; nt++)
                    mma16816(acc[mt][nt], a[mt], bf[nt]);
        }

        if (kt + 3 < KT) {
            const int ns = (stage + 3 >= HG_STAGES) ? stage + 3 - HG_STAGES : stage + 3;
            const __half* ag = Ag + (kt + 3) * BKH;
            const __half* bg = Bg + (kt + 3) * BKH;
            cp16(AsB + (uint32_t)ns * SA + stA,      ag);
            cp16(BsB + (uint32_t)ns * SB + stB,      bg);
            cp16(BsB + (uint32_t)ns * SB + stB + 16, bg + 8);
            asm volatile("cp.async.commit_group;");
            asm volatile("cp.async.wait_group 2;" ::: "memory");
        } else {
            asm volatile("cp.async.wait_group 0;" ::: "memory");
        }
        __syncthreads();
        stage = (stage + 1 >= HG_STAGES) ? 0 : stage + 1;
    }

    if (MODE == 0) {
#pragma unroll
        for (int mt = 0; mt < 2; mt++) {
            const int r0 = bm + wm * 32 + mt * 16 + (lane >> 2);
#pragma unroll
            for (int nt = 0; nt < 4; nt++) {
                const int c0 = bn + wn * 32 + nt * 8 + (lane & 3) * 2;
                float b0 = bias[c0], b1 = bias[c0 + 1];
                float2 v01 = { acc[mt][nt][0] + b0, acc[mt][nt][1] + b1 };
                float2 v23 = { acc[mt][nt][2] + b0, acc[mt][nt][3] + b1 };
                *(float2*)(C + (size_t)r0 * N + c0)       = v01;
                *(float2*)(C + (size_t)(r0 + 8) * N + c0) = v23;
            }
        }
    } else {
        const int i = (lane & 3) * 2;
#pragma unroll
        for (int mt = 0; mt < 2; mt++) {
            const int r0 = bm + wm * 32 + mt * 16 + (lane >> 2);
#pragma unroll
            for (int rr = 0; rr < 2; rr++) {
                const int row = r0 + rr * 8;
                const int s = row & (S_ - 1);
                const int b = row >> 11;
                const float* rt = &g_rot[s * 16];
#pragma unroll
                for (int np = 0; np < 2; np++) {
                    const int base = bn + wn * 32 + np * 16;
                    const float vlo0 = acc[mt][2 * np][2 * rr + 0];
                    const float vlo1 = acc[mt][2 * np][2 * rr + 1];
                    const float vhi0 = acc[mt][2 * np + 1][2 * rr + 0];
                    const float vhi1 = acc[mt][2 * np + 1][2 * rr + 1];
                    if (base < 256) {
                        const int h = base >> 4;
                        float a0 = vlo0 + bQv[h * 16 + i];
                        float a1 = vlo1 + bQv[h * 16 + i + 1];
                        float c0 = vhi0 + bQv[h * 16 + i + 8];
                        float c1 = vhi1 + bQv[h * 16 + i + 9];
                        float sn0 = rt[i], sn1 = rt[i + 1];
                        float cs0 = rt[8 + i], cs1 = rt[9 + i];
                        __half* dst = &g_Qh[((size_t)(b * NQK_ + h) * S_ + s) * DQK_];
                        *(__half2*)&dst[i]     = __floats2half2_rn((a0 * cs0 - c0 * sn0) * QSCALE,
                                                                   (a1 * cs1 - c1 * sn1) * QSCALE);
                        *(__half2*)&dst[i + 8] = __floats2half2_rn((c0 * cs0 + a0 * sn0) * QSCALE,
                                                                   (c1 * cs1 + a1 * sn1) * QSCALE);
                    } else if (base < 512) {
                        const int h = (base - 256) >> 4;
                        float a0 = vlo0 + bKv[h * 16 + i];
                        float a1 = vlo1 + bKv[h * 16 + i + 1];
                        float c0 = vhi0 + bKv[h * 16 + i + 8];
                        float c1 = vhi1 + bKv[h * 16 + i + 9];
                        float sn0 = rt[i], sn1 = rt[i + 1];
                        float cs0 = rt[8 + i], cs1 = rt[9 + i];
                        __half* dst = &g_Kh[((size_t)(b * NQK_ + h) * SK_ + s) * DQK_];
                        *(__half2*)&dst[i]     = __floats2half2_rn(a0 * cs0 - c0 * sn0,
                                                                   a1 * cs1 - c1 * sn1);
                        *(__half2*)&dst[i + 8] = __floats2half2_rn(c0 * cs0 + a0 * sn0,
                                                                   c1 * cs1 + a1 * sn1);
                    } else {
                        const int n0 = base - 512;
                        const int h = n0 >> 4;
                        __half* dst = &g_Vh[((size_t)(b * NQK_ + h) * SK_ + s) * DQK_];
                        *(__half2*)&dst[i]     = __floats2half2_rn(vlo0 + bVv[n0 + i],
                                                                   vlo1 + bVv[n0 + i + 1]);
                        *(__half2*)&dst[i + 8] = __floats2half2_rn(vhi0 + bVv[n0 + i + 8],
                                                                   vhi1 + bVv[n0 + i + 9]);
                    }
                }
            }
        }
    }
}

// ---------------------------------------------------------------------------
// 3) Tensor-core flash attention, antithetic-paired query tiles.
//    CTA p of head bh handles qt = 31-p then qt = p: exactly 17 key-tiles
//    per CTA (perfect balance). Grid (16, 32) = 512 CTAs, single wave.
// ---------------------------------------------------------------------------
#define PAD 24

__global__ __launch_bounds__(128, 6)
void attn_mma()
{
    const int bh   = blockIdx.y;
    const int pp   = blockIdx.x;          // 0..15
    const int tid  = threadIdx.x;
    const int warp = tid >> 5, lane = tid & 31;

    __shared__ __half Qs[64 * PAD];
    __shared__ __half K0s[16 * PAD];
    __shared__ __half V0s[16 * PAD];
    __shared__ __half Ks[2][128 * PAD];
    __shared__ __half Vs[2][128 * PAD];

    const __half* Kg = g_Kh + (size_t)bh * SK_ * DQK_;
    const __half* Vg = g_Vh + (size_t)bh * SK_ * DQK_;

    const int ld_row = tid >> 1;          // 0..63
    const int ld_off = (tid & 1) * 8;

    // shared prologue K0/V0 (keys 0..15) — loaded ONCE, reused by both qt
    if (tid < 32) {
        int pr = tid >> 1, po = (tid & 1) * 8;
        cp16(smem_u32(&K0s[pr * PAD + po]), Kg + (size_t)pr * 16 + po);
        cp16(smem_u32(&V0s[pr * PAD + po]), Vg + (size_t)pr * 16 + po);
    }
    asm volatile("cp.async.commit_group;");

    const int g = lane >> 3, r = lane & 7;
    const int qfrow = warp * 16 + (g & 1) * 8 + r;
    const int qfcol = (g >> 1) * 8;
    const int krow = (g >> 1) * 8 + r;
    const int kcol = (g & 1) * 8;
    const int vrow = (g & 1) * 8 + r;
    const int vcol = (g >> 1) * 8;
    const uint32_t onesb[2] = { 0x3C003C00u, 0x3C003C00u };

#pragma unroll 1
    for (int sel = 0; sel < 2; sel++) {
        const int qt = sel ? pp : (31 - pp);
        const int q0 = qt * 64;
        const __half* Qg = g_Qh + ((size_t)bh * S_ + q0) * DQK_;

        // barrier: all warps past previous pass's smem reads before we
        // overwrite Qs / reissue cp.async into Ks/Vs buffers
        __syncthreads();

        *(float4*)&Qs[ld_row * PAD + ld_off] =
            *(const float4*)&Qg[(size_t)ld_row * 16 + ld_off];

        // issue tile 0 (keys 16..143)
        cp16(smem_u32(&Ks[0][ld_row * PAD + ld_off]),        Kg + (size_t)(16 + ld_row) * 16 + ld_off);
        cp16(smem_u32(&Ks[0][(ld_row + 64) * PAD + ld_off]), Kg + (size_t)(80 + ld_row) * 16 + ld_off);
        cp16(smem_u32(&Vs[0][ld_row * PAD + ld_off]),        Vg + (size_t)(16 + ld_row) * 16 + ld_off);
        cp16(smem_u32(&Vs[0][(ld_row + 64) * PAD + ld_off]), Vg + (size_t)(80 + ld_row) * 16 + ld_off);
        asm volatile("cp.async.commit_group;");

        // sel=0: drains the K0/V0 group (leaves tile0 in flight); sel=1: no-op
        asm volatile("cp.async.wait_group 1;" ::: "memory");
        __syncthreads();

        uint32_t qa[4];
        ldm4(qa[0], qa[1], qa[2], qa[3], smem_u32(&Qs[qfrow * PAD + qfcol]));

        float m0, m1;
        float o[2][4] = {{0.f,0.f,0.f,0.f},{0.f,0.f,0.f,0.f}};
        float oL[4]   = {0.f,0.f,0.f,0.f};

        // ---- prologue: 16 keys, unmasked ----
        {
            float sc[2][4] = {{0.f,0.f,0.f,0.f},{0.f,0.f,0.f,0.f}};
            uint32_t b0, b1, b2, b3;
            ldm4(b0, b1, b2, b3, smem_u32(&K0s[krow * PAD + kcol]));
            {
                uint32_t bl[2] = { b0, b1 }, bh2[2] = { b2, b3 };
                mma16816(sc[0], qa, bl);
                mma16816(sc[1], qa, bh2);
            }
            float rm0 = fmaxf(fmaxf(sc[0][0], sc[0][1]), fmaxf(sc[1][0], sc[1][1]));
            float rm1 = fmaxf(fmaxf(sc[0][2], sc[0][3]), fmaxf(sc[1][2], sc[1][3]));
            rm0 = fmaxf(rm0, __shfl_xor_sync(0xffffffff, rm0, 1));
            rm0 = fmaxf(rm0, __shfl_xor_sync(0xffffffff, rm0, 2));
            rm1 = fmaxf(rm1, __shfl_xor_sync(0xffffffff, rm1, 1));
            rm1 = fmaxf(rm1, __shfl_xor_sync(0xffffffff, rm1, 2));
            m0 = rm0; m1 = rm1;

            uint32_t pa[4];
            pa[0] = ex2h2(sc[0][0] - m0, sc[0][1] - m0);
            pa[1] = ex2h2(sc[0][2] - m1, sc[0][3] - m1);
            pa[2] = ex2h2(sc[1][0] - m0, sc[1][1] - m0);
            pa[3] = ex2h2(sc[1][2] - m1, sc[1][3] - m1);

            uint32_t v0, v1, v2, v3;
            ldm4t(v0, v1, v2, v3, smem_u32(&V0s[vrow * PAD + vcol]));
            uint32_t bl[2] = { v0, v1 }, bh2[2] = { v2, v3 };
            mma16816(o[0], pa, bl);
            mma16816(o[1], pa, bh2);
            mma16816(oL,   pa, onesb);
        }

        const int jmax = (q0 + 63) >> 7;

        for (int jt = 0; jt <= jmax; jt++) {
            const int buf = jt & 1;
            if (jt < jmax) {
                const size_t kb = (size_t)(16 + (jt + 1) * 128);
                cp16(smem_u32(&Ks[buf ^ 1][ld_row * PAD + ld_off]),        Kg + (kb + ld_row) * 16 + ld_off);
                cp16(smem_u32(&Ks[buf ^ 1][(ld_row + 64) * PAD + ld_off]), Kg + (kb + ld_row + 64) * 16 + ld_off);
                cp16(smem_u32(&Vs[buf ^ 1][ld_row * PAD + ld_off]),        Vg + (kb + ld_row) * 16 + ld_off);
                cp16(smem_u32(&Vs[buf ^ 1][(ld_row + 64) * PAD + ld_off]), Vg + (kb + ld_row + 64) * 16 + ld_off);
                asm volatile("cp.async.commit_group;");
                asm volatile("cp.async.wait_group 1;" ::: "memory");
            } else {
                asm volatile("cp.async.wait_group 0;" ::: "memory");
            }
            __syncthreads();

            const bool diag = (jt == jmax);
            const int off   = q0 - 128 * jt;
            const int wb    = off + warp * 16 + 15;

#pragma unroll
            for (int c = 0; c < 2; c++) {
                if (!diag || c * 64 <= wb) {
                    float sc[8][4];
#pragma unroll
                    for (int nt = 0; nt < 8; nt++)
#pragma unroll
                        for (int tt = 0; tt < 4; tt++) sc[nt][tt] = 0.f;

#pragma unroll
                    for (int i = 0; i < 4; i++) {
                        if (!diag || (c * 64 + i * 16) <= wb) {
                            uint32_t b0, b1, b2, b3;
                            ldm4(b0, b1, b2, b3,
                                 smem_u32(&Ks[buf][(16 * (c * 4 + i) + krow) * PAD + kcol]));
                            uint32_t bl[2] = { b0, b1 }, bh2[2] = { b2, b3 };
                            mma16816(sc[2 * i],     qa, bl);
                            mma16816(sc[2 * i + 1], qa, bh2);
                        }
                    }

                    if (diag) {
                        const int jb = c * 64 + (lane & 3) * 2;
                        const int t0 = off + warp * 16 + (lane >> 2);
                        const int t1 = t0 + 8;
#pragma unroll
                        for (int nt = 0; nt < 8; nt++) {
                            int j0 = jb + nt * 8;
                            if (j0     > t0) sc[nt][0] = -1e30f;
                            if (j0 + 1 > t0) sc[nt][1] = -1e30f;
                            if (j0     > t1) sc[nt][2] = -1e30f;
                            if (j0 + 1 > t1) sc[nt][3] = -1e30f;
                        }
                    }

                    float rm0 = sc[0][0], rm1 = sc[0][2];
#pragma unroll
                    for (int nt = 0; nt < 8; nt++) {
                        rm0 = fmaxf(rm0, fmaxf(sc[nt][0], sc[nt][1]));
                        rm1 = fmaxf(rm1, fmaxf(sc[nt][2], sc[nt][3]));
                    }
                    rm0 = fmaxf(rm0, __shfl_xor_sync(0xffffffff, rm0, 1));
                    rm0 = fmaxf(rm0, __shfl_xor_sync(0xffffffff, rm0, 2));
                    rm1 = fmaxf(rm1, __shfl_xor_sync(0xffffffff, rm1, 1));
                    rm1 = fmaxf(rm1, __shfl_xor_sync(0xffffffff, rm1, 2));

                    const float mn0 = fmaxf(m0, rm0);
                    const float mn1 = fmaxf(m1, rm1);
                    const float c0 = ex2f(m0 - mn0);
                    const float c1 = ex2f(m1 - mn1);
                    m0 = mn0; m1 = mn1;
                    o[0][0] *= c0; o[0][1] *= c0; o[0][2] *= c1; o[0][3] *= c1;
                    o[1][0] *= c0; o[1][1] *= c0; o[1][2] *= c1; o[1][3] *= c1;
                    oL[0]   *= c0; oL[1]   *= c0; oL[2]   *= c1; oL[3]   *= c1;

                    uint32_t p[8][2];
#pragma unroll
                    for (int nt = 0; nt < 8; nt++) {
                        p[nt][0] = ex2h2(sc[nt][0] - mn0, sc[nt][1] - mn0);
                        p[nt][1] = ex2h2(sc[nt][2] - mn1, sc[nt][3] - mn1);
                    }

#pragma unroll
                    for (int kt = 0; kt < 4; kt++) {
                        if (!diag || (c * 64 + kt * 16) <= wb) {
                            uint32_t pa[4];
                            pa[0] = p[2 * kt][0];
                            pa[1] = p[2 * kt][1];
                            pa[2] = p[2 * kt + 1][0];
                            pa[3] = p[2 * kt + 1][1];
                            uint32_t v0, v1, v2, v3;
                            ldm4t(v0, v1, v2, v3,
                                  smem_u32(&Vs[buf][(16 * (c * 4 + kt) + vrow) * PAD + vcol]));
                            uint32_t bl[2] = { v0, v1 }, bh2[2] = { v2, v3 };
                            mma16816(o[0], pa, bl);
                            mma16816(o[1], pa, bh2);
                            mma16816(oL,   pa, onesb);
                        }
                    }
                }
            }
            __syncthreads();
        }

        // ---- epilogue for this query tile ----
        const float inv0 = 1.f / oL[0];
        const float inv1 = 1.f / oL[2];

        const int qrow0 = q0 + warp * 16 + (lane >> 2);
        const int b = bh >> 4, h = bh & 15;
        const int col = (lane & 3) * 2;
#pragma unroll
        for (int vt = 0; vt < 2; vt++) {
            uint32_t lo = packh2(o[vt][0] * inv0, o[vt][1] * inv0);
            uint32_t hi = packh2(o[vt][2] * inv1, o[vt][3] * inv1);
            size_t base0 = ((size_t)(b * S_ + qrow0)     ) * NOV_ + h * 16 + vt * 8 + col;
            size_t base1 = ((size_t)(b * S_ + qrow0 + 8) ) * NOV_ + h * 16 + vt * 8 + col;
            *(uint32_t*)&g_Zh[base0] = lo;
            *(uint32_t*)&g_Zh[base1] = hi;
        }
    }
}

// ---------------------------------------------------------------------------
// Launch
// ---------------------------------------------------------------------------
extern "C" void kernel_launch(void* const* d_in, const int* in_sizes, int n_in,
                              void* d_out, int out_size)
{
    const float* resid = (const float*)d_in[0];
    const float* W_Q   = (const float*)d_in[1];
    const float* W_K   = (const float*)d_in[2];
    const float* W_V   = (const float*)d_in[3];
    const float* W_O   = (const float*)d_in[4];
    const float* b_Q   = (const float*)d_in[5];
    const float* b_K   = (const float*)d_in[6];
    const float* b_V   = (const float*)d_in[7];
    const float* b_O   = (const float*)d_in[8];
    const float* v_k   = (const float*)d_in[9];
    const float* v_v   = (const float*)d_in[10];
    float* out = (float*)d_out;

    __half *Ah, *Wh1, *Wh2, *Zh;
    cudaGetSymbolAddress((void**)&Ah,  g_Ah);
    cudaGetSymbolAddress((void**)&Wh1, g_Wh1);
    cudaGetSymbolAddress((void**)&Wh2, g_Wh2);
    cudaGetSymbolAddress((void**)&Zh,  g_Zh);

    cudaFuncSetAttribute(hgemm<0>, cudaFuncAttributeMaxDynamicSharedMemorySize, HG_SMEM_BYTES);
    cudaFuncSetAttribute(hgemm<1>, cudaFuncAttributeMaxDynamicSharedMemorySize, HG_SMEM_BYTES);

    // 1) fused prep
    prep_kernel<<<PREP_BLKS, 256>>>(W_Q, W_K, W_V, W_O, resid, v_k, v_v);

    // 2) GEMM1 + fused bias/rotary/scatter epilogue -> g_Qh/g_Kh/g_Vh
    {
        dim3 grid(DM_ / 128, BS_ / 64);
        hgemm<1><<<grid, 256, HG_SMEM_BYTES>>>(Ah, Wh1, nullptr, BS_, DM_, DM_,
                                               nullptr, b_Q, b_K, b_V);
    }

    // 3) tensor-core flash attention (antithetic-paired query tiles)
    {
        dim3 grid(16, B_ * NQK_);
        attn_mma<<<grid, 128>>>();
    }

    // 4) GEMM2: (4096 x 768) = Zh * Wh2^T + b_O -> out fp32
    {
        dim3 grid(DM_ / 128, BS_ / 64);
        hgemm<0><<<grid, 256, HG_SMEM_BYTES>>>(Zh, Wh2, out, BS_, DM_, NOV_,
                                               b_O, nullptr, nullptr, nullptr);
    }
}